// round 3
// baseline (speedup 1.0000x reference)
#include <cuda_runtime.h>
#include <math.h>

#define GN 100000
#define GD 256
#define GH 256
#define GB 128
#define GE 128
#define NSTEPS 5
#define GJ (4*GH)   // 1024 gate width

// ---------------- scratch (device globals; no allocations) ----------------
__device__ float g_t1[(size_t)GN*GH];     // elu(x@W1+b1)
__device__ float g_hfeat[(size_t)GN*GH];  // node features
__device__ float g_e[GN];
__device__ float g_ex[GN];
__device__ float g_h[3*GB*GH];
__device__ float g_c[3*GB*GH];
__device__ float g_qstar[GB*2*GH];
__device__ float g_gates[GB*GJ];
__device__ unsigned g_menc[GB];
__device__ float g_m[GB];
__device__ float g_denom[GB];
__device__ float g_r[GB*GH];

// monotone float<->uint encoding for atomicMax over signed floats
__device__ __forceinline__ unsigned fenc(float f){
    unsigned u = __float_as_uint(f);
    return (u & 0x80000000u) ? ~u : (u | 0x80000000u);
}
__device__ __forceinline__ float fdec(unsigned u){
    unsigned b = (u & 0x80000000u) ? (u ^ 0x80000000u) : ~u;
    return __uint_as_float(b);
}

// ---------------- FNN GEMM: C(MxN=256) = A(Mx256) @ W(256x256) + bias ----------------
// BM=128 BN=128 BK=16, 8x8 per thread, 256 threads.
__global__ void __launch_bounds__(256) gemm_nn256(
    const float* __restrict__ A, const float* __restrict__ W,
    const float* __restrict__ bias, float* __restrict__ C, int M, int do_elu)
{
    __shared__ float As[16][132];
    __shared__ float Ws[16][128];
    const int tid  = threadIdx.x;
    const int row0 = blockIdx.y * 128;
    const int col0 = blockIdx.x * 128;
    const int ar = tid >> 2;          // 0..63
    const int ak = (tid & 3) << 2;    // 0,4,8,12
    const int wr = tid >> 5;          // 0..7
    const int wc = (tid & 31) << 2;   // 0..124
    const int tx = tid & 15;
    const int ty = tid >> 4;

    float acc[8][8];
#pragma unroll
    for (int i=0;i<8;i++)
#pragma unroll
        for (int j=0;j<8;j++) acc[i][j]=0.f;

    for (int k0 = 0; k0 < 256; k0 += 16) {
#pragma unroll
        for (int i = 0; i < 2; i++) {
            int r  = ar + i*64;
            int gr = row0 + r;
            float4 v = make_float4(0.f,0.f,0.f,0.f);
            if (gr < M) v = *reinterpret_cast<const float4*>(&A[(size_t)gr*256 + k0 + ak]);
            As[ak+0][r]=v.x; As[ak+1][r]=v.y; As[ak+2][r]=v.z; As[ak+3][r]=v.w;
        }
#pragma unroll
        for (int i = 0; i < 2; i++) {
            int r = wr + i*8;
            *reinterpret_cast<float4*>(&Ws[r][wc]) =
                *reinterpret_cast<const float4*>(&W[(size_t)(k0+r)*256 + col0 + wc]);
        }
        __syncthreads();
#pragma unroll
        for (int kk = 0; kk < 16; kk++) {
            float ra[8], rb[8];
            *reinterpret_cast<float4*>(&ra[0]) = *reinterpret_cast<const float4*>(&As[kk][ty*8]);
            *reinterpret_cast<float4*>(&ra[4]) = *reinterpret_cast<const float4*>(&As[kk][ty*8+4]);
            *reinterpret_cast<float4*>(&rb[0]) = *reinterpret_cast<const float4*>(&Ws[kk][tx*8]);
            *reinterpret_cast<float4*>(&rb[4]) = *reinterpret_cast<const float4*>(&Ws[kk][tx*8+4]);
#pragma unroll
            for (int i=0;i<8;i++)
#pragma unroll
                for (int j=0;j<8;j++) acc[i][j] = fmaf(ra[i], rb[j], acc[i][j]);
        }
        __syncthreads();
    }
#pragma unroll
    for (int i=0;i<8;i++){
        int gr = row0 + ty*8 + i;
        if (gr >= M) continue;
#pragma unroll
        for (int j=0;j<8;j+=4){
            int gc = col0 + tx*8 + j;
            float4 v;
            v.x = acc[i][j+0] + bias[gc+0];
            v.y = acc[i][j+1] + bias[gc+1];
            v.z = acc[i][j+2] + bias[gc+2];
            v.w = acc[i][j+3] + bias[gc+3];
            if (do_elu){
                v.x = v.x > 0.f ? v.x : expm1f(v.x);
                v.y = v.y > 0.f ? v.y : expm1f(v.y);
                v.z = v.z > 0.f ? v.z : expm1f(v.z);
                v.w = v.w > 0.f ? v.w : expm1f(v.w);
            }
            *reinterpret_cast<float4*>(&C[(size_t)gr*256 + gc]) = v;
        }
    }
}

// ---------------- LSTM gates: gates[b,j] = xin@Wih^T + h@Whh^T + bih + bhh ----------------
// grid (GJ/64, GB/8); block handles 8 b x 64 j; thread: 1 j, 2 b's.
__global__ void __launch_bounds__(256) lstm_gates(
    const float* __restrict__ xin, int Kx,
    const float* __restrict__ h,
    const float* __restrict__ Wih, const float* __restrict__ Whh,
    const float* __restrict__ bih, const float* __restrict__ bhh,
    float* __restrict__ gates)
{
    __shared__ float sx[8*512];
    __shared__ float sh[8*256];
    const int tid = threadIdx.x;
    const int jt  = blockIdx.x * 64;
    const int bt  = blockIdx.y * 8;
    {   // 8 rows of xin / h are contiguous in memory
        const float4* src = reinterpret_cast<const float4*>(xin + (size_t)bt*Kx);
        float4* dst = reinterpret_cast<float4*>(sx);
        int tot = (8*Kx) >> 2;
        for (int i = tid; i < tot; i += 256) dst[i] = src[i];
        const float4* srch = reinterpret_cast<const float4*>(h + (size_t)bt*GH);
        float4* dsth = reinterpret_cast<float4*>(sh);
        for (int i = tid; i < (8*GH)>>2; i += 256) dsth[i] = srch[i];
    }
    __syncthreads();
    const int j  = jt + (tid & 63);
    const int bg = (tid >> 6) * 2;  // local b0 (0,2,4,6)
    float a0 = 0.f, a1 = 0.f;
    const float* wr1 = Wih + (size_t)j*Kx;
    const float* x0  = sx + bg*Kx;
    const float* x1  = sx + (bg+1)*Kx;
    for (int k = 0; k < Kx; k += 4){
        float4 w  = *reinterpret_cast<const float4*>(wr1 + k);
        float4 xa = *reinterpret_cast<const float4*>(x0 + k);
        float4 xb = *reinterpret_cast<const float4*>(x1 + k);
        a0 = fmaf(w.x,xa.x,fmaf(w.y,xa.y,fmaf(w.z,xa.z,fmaf(w.w,xa.w,a0))));
        a1 = fmaf(w.x,xb.x,fmaf(w.y,xb.y,fmaf(w.z,xb.z,fmaf(w.w,xb.w,a1))));
    }
    const float* wr2 = Whh + (size_t)j*GH;
    const float* h0  = sh + bg*GH;
    const float* h1  = sh + (bg+1)*GH;
    for (int k = 0; k < GH; k += 4){
        float4 w  = *reinterpret_cast<const float4*>(wr2 + k);
        float4 xa = *reinterpret_cast<const float4*>(h0 + k);
        float4 xb = *reinterpret_cast<const float4*>(h1 + k);
        a0 = fmaf(w.x,xa.x,fmaf(w.y,xa.y,fmaf(w.z,xa.z,fmaf(w.w,xa.w,a0))));
        a1 = fmaf(w.x,xb.x,fmaf(w.y,xb.y,fmaf(w.z,xb.z,fmaf(w.w,xb.w,a1))));
    }
    const float bb = bih[j] + bhh[j];
    gates[(size_t)(bt+bg  )*GJ + j] = a0 + bb;
    gates[(size_t)(bt+bg+1)*GJ + j] = a1 + bb;
}

__global__ void lstm_cell(const float* __restrict__ gates,
                          float* __restrict__ h, float* __restrict__ c)
{
    int idx = blockIdx.x * blockDim.x + threadIdx.x;  // GB*GH
    int b = idx >> 8, k = idx & 255;
    const float* g = gates + (size_t)b*GJ;
    float gi = g[k], gf = g[GH+k], gg = g[2*GH+k], go = g[3*GH+k];
    float si = 1.f/(1.f+expf(-gi));
    float sf = 1.f/(1.f+expf(-gf));
    float so = 1.f/(1.f+expf(-go));
    float cn = sf*c[idx] + si*tanhf(gg);
    c[idx] = cn;
    h[idx] = so * tanhf(cn);
}

// ---------------- init kernels ----------------
__global__ void init_state(){
    int idx = blockIdx.x*blockDim.x + threadIdx.x;
    if (idx < 3*GB*GH){ g_h[idx]=0.f; g_c[idx]=0.f; }
    if (idx < GB*2*GH) g_qstar[idx]=0.f;
}
__global__ void init_step(){
    int idx = blockIdx.x*blockDim.x + threadIdx.x;
    if (idx < GB){ g_menc[idx] = 0x007FFFFFu; /* fenc(-inf) */ g_denom[idx] = 0.f; }
    if (idx < GB*GH) g_r[idx] = 0.f;
}

// ---------------- attention ----------------
// one warp per node: e[n] = dot(hfeat[n], q[bi[n]]), atomicMax segment max
__global__ void __launch_bounds__(256) attn_e(const float* __restrict__ q,
                                              const int* __restrict__ bi)
{
    int gw   = (blockIdx.x * 256 + threadIdx.x) >> 5;
    int lane = threadIdx.x & 31;
    if (gw >= GN) return;
    int b = bi[gw];
    const float4* hr = reinterpret_cast<const float4*>(g_hfeat + (size_t)gw*GH);
    const float4* qr = reinterpret_cast<const float4*>(q + (size_t)b*GH);
    float s = 0.f;
#pragma unroll
    for (int i=0;i<2;i++){
        float4 a = hr[lane + 32*i];
        float4 w = qr[lane + 32*i];
        s += a.x*w.x + a.y*w.y + a.z*w.z + a.w*w.w;
    }
#pragma unroll
    for (int off=16; off>0; off>>=1) s += __shfl_xor_sync(0xffffffffu, s, off);
    if (lane == 0){
        g_e[gw] = s;
        atomicMax(&g_menc[b], fenc(s));
    }
}

__global__ void m_fin(){
    int b = threadIdx.x;
    if (b < GB){
        float m = fdec(g_menc[b]);
        g_m[b] = isfinite(m) ? m : 0.f;
    }
}

__global__ void attn_ex(const int* __restrict__ bi){
    int n = blockIdx.x*blockDim.x + threadIdx.x;
    if (n >= GN) return;
    int b = bi[n];
    float v = expf(g_e[n] - g_m[b]);
    g_ex[n] = v;
    atomicAdd(&g_denom[b], v);
}

// r[b,h] = sum_{n in seg(b)} (ex[n]/denom[b]) * hfeat[n,h]
// grid (GB, 8 chunks), 256 threads = one h column each; bi is sorted -> binary search.
__global__ void __launch_bounds__(256) attn_r(const int* __restrict__ bi)
{
    int b = blockIdx.x;
    int chunk = blockIdx.y;
    int lo = 0, hi = GN;
    while (lo < hi){ int mid=(lo+hi)>>1; if (bi[mid] <  b) lo=mid+1; else hi=mid; }
    int start = lo; hi = GN;
    while (lo < hi){ int mid=(lo+hi)>>1; if (bi[mid] <= b) lo=mid+1; else hi=mid; }
    int end = lo;
    int len = end - start;
    if (len <= 0) return;
    int per = (len + 7) >> 3;
    int s = start + chunk*per;
    int t = min(end, s + per);
    if (s >= t) return;
    int hcol = threadIdx.x;
    float inv = 1.f/(g_denom[b] + 1e-16f);
    float acc = 0.f;
    int n = s;
    for (; n + 4 <= t; n += 4){
        float e0=g_ex[n], e1=g_ex[n+1], e2=g_ex[n+2], e3=g_ex[n+3];
        float f0=g_hfeat[(size_t)(n  )*GH + hcol];
        float f1=g_hfeat[(size_t)(n+1)*GH + hcol];
        float f2=g_hfeat[(size_t)(n+2)*GH + hcol];
        float f3=g_hfeat[(size_t)(n+3)*GH + hcol];
        acc = fmaf(e0,f0,fmaf(e1,f1,fmaf(e2,f2,fmaf(e3,f3,acc))));
    }
    for (; n < t; n++) acc = fmaf(g_ex[n], g_hfeat[(size_t)n*GH + hcol], acc);
    atomicAdd(&g_r[b*GH + hcol], acc * inv);
}

__global__ void build_qstar(const float* __restrict__ h2){
    int idx = blockIdx.x*blockDim.x + threadIdx.x;  // GB*512
    if (idx >= GB*2*GH) return;
    int b = idx >> 9, k = idx & 511;
    g_qstar[idx] = (k < GH) ? h2[b*GH + k] : g_r[b*GH + (k - GH)];
}

// out[b,e] = q_star[b,:] @ out_W[:,e] + out_b[e]
__global__ void out_gemm(const float* __restrict__ W, const float* __restrict__ bias,
                         float* __restrict__ out)
{
    int b = blockIdx.x, e = threadIdx.x;
    const float* qs = g_qstar + (size_t)b*(2*GH);
    float acc = bias[e];
    for (int k = 0; k < 2*GH; k++) acc = fmaf(qs[k], W[(size_t)k*GE + e], acc);
    out[(size_t)b*GE + e] = acc;
}

// ---------------- launch ----------------
extern "C" void kernel_launch(void* const* d_in, const int* in_sizes, int n_in,
                              void* d_out, int out_size)
{
    const float* x    = (const float*)d_in[0];
    const int*   bi   = (const int*)  d_in[1];
    const float* W1   = (const float*)d_in[2];
    const float* b1   = (const float*)d_in[3];
    const float* W2   = (const float*)d_in[4];
    const float* b2   = (const float*)d_in[5];
    const float* Wih[3] = {(const float*)d_in[6],  (const float*)d_in[10], (const float*)d_in[14]};
    const float* Whh[3] = {(const float*)d_in[7],  (const float*)d_in[11], (const float*)d_in[15]};
    const float* bih[3] = {(const float*)d_in[8],  (const float*)d_in[12], (const float*)d_in[16]};
    const float* bhh[3] = {(const float*)d_in[9],  (const float*)d_in[13], (const float*)d_in[17]};
    const float* outW = (const float*)d_in[18];
    const float* outb = (const float*)d_in[19];

    float *t1, *hfeat, *gates, *h, *c, *qstar;
    cudaGetSymbolAddress((void**)&t1,    g_t1);
    cudaGetSymbolAddress((void**)&hfeat, g_hfeat);
    cudaGetSymbolAddress((void**)&gates, g_gates);
    cudaGetSymbolAddress((void**)&h,     g_h);
    cudaGetSymbolAddress((void**)&c,     g_c);
    cudaGetSymbolAddress((void**)&qstar, g_qstar);

    dim3 gg(2, (GN + 127) / 128);
    gemm_nn256<<<gg, 256>>>(x,  W1, b1, t1,    GN, 1);
    gemm_nn256<<<gg, 256>>>(t1, W2, b2, hfeat, GN, 0);
    init_state<<<(3*GB*GH + 255)/256, 256>>>();

    for (int step = 0; step < NSTEPS; step++){
        const float* lin = qstar; int Kx = 2*GH;
        for (int l = 0; l < 3; l++){
            lstm_gates<<<dim3(GJ/64, GB/8), 256>>>(lin, Kx, h + l*GB*GH,
                                                   Wih[l], Whh[l], bih[l], bhh[l], gates);
            lstm_cell<<<GB, GH>>>(gates, h + l*GB*GH, c + l*GB*GH);
            lin = h + l*GB*GH; Kx = GH;
        }
        init_step<<<(GB*GH + 255)/256, 256>>>();
        attn_e<<<(GN*32 + 255)/256, 256>>>(h + 2*GB*GH, bi);
        m_fin<<<1, GB>>>();
        attn_ex<<<(GN + 255)/256, 256>>>(bi);
        attn_r<<<dim3(GB, 8), GH>>>(bi);
        build_qstar<<<(GB*2*GH + 255)/256, 256>>>(h + 2*GB*GH);
    }
    out_gemm<<<GB, GE>>>(outW, outb, (float*)d_out);
}

// round 4
// speedup vs baseline: 2.0745x; 2.0745x over previous
#include <cuda_runtime.h>
#include <math.h>
#include <stdint.h>

#define GN 100000
#define GD 256
#define GH 256
#define GB 128
#define GE 128
#define NSTEPS 5
#define GJ (4*GH)     // 1024 gate width
#define NCHMAX 12     // max K chunks (layer0: (512+256)/64 = 12)

// ---------------- scratch (device globals; no allocations) ----------------
__device__ float g_t1[(size_t)GN*GH];     // elu(x@W1+b1)
__device__ float g_hfeat[(size_t)GN*GH];  // node features
__device__ float g_e[GN];
__device__ float g_ex[GN];
__device__ float g_h[3*GB*GH];
__device__ float g_c[3*GB*GH];
__device__ float g_qstar[GB*2*GH];
__device__ float g_gpart[(size_t)NCHMAX*GB*GJ];  // LSTM gate partial sums
__device__ unsigned g_menc[GB];
__device__ float g_m[GB];
__device__ float g_denom[GB];
__device__ float g_r[GB*GH];

// monotone float<->uint encoding for atomicMax over signed floats
__device__ __forceinline__ unsigned fenc(float f){
    unsigned u = __float_as_uint(f);
    return (u & 0x80000000u) ? ~u : (u | 0x80000000u);
}
__device__ __forceinline__ float fdec(unsigned u){
    unsigned b = (u & 0x80000000u) ? (u ^ 0x80000000u) : ~u;
    return __uint_as_float(b);
}

// ---------------- tf32 helpers ----------------
__device__ __forceinline__ void tf32_split(float v, float& hi, float& lo){
    uint32_t u;
    asm("cvt.rna.tf32.f32 %0, %1;" : "=r"(u) : "f"(v));
    hi = __uint_as_float(u);
    float r = v - hi;
    uint32_t u2;
    asm("cvt.rna.tf32.f32 %0, %1;" : "=r"(u2) : "f"(r));
    lo = __uint_as_float(u2);
}

__device__ __forceinline__ void mma_tf32(float c[4], const float a[4], const float b[2]){
    const uint32_t* A = reinterpret_cast<const uint32_t*>(a);
    const uint32_t* B = reinterpret_cast<const uint32_t*>(b);
    asm volatile("mma.sync.aligned.m16n8k8.row.col.f32.tf32.tf32.f32 "
        "{%0,%1,%2,%3}, {%4,%5,%6,%7}, {%8,%9}, {%0,%1,%2,%3};"
        : "+f"(c[0]), "+f"(c[1]), "+f"(c[2]), "+f"(c[3])
        : "r"(A[0]), "r"(A[1]), "r"(A[2]), "r"(A[3]), "r"(B[0]), "r"(B[1]));
}

// ---------------- FNN GEMM (3xTF32 tensor cores) ----------------
// C(Mx256) = A(Mx256) @ W(256x256) + bias [+ ELU]
// BM=128 BN=128 BK=16; 256 threads = 8 warps, warp grid 2m x 4n, warp tile 64x32.
__global__ void __launch_bounds__(256) gemm_tf32(
    const float* __restrict__ A, const float* __restrict__ W,
    const float* __restrict__ bias, float* __restrict__ C, int M, int do_elu)
{
    __shared__ float Ah[16][132], Al[16][132];
    __shared__ float Wh[16][132], Wl[16][132];
    const int tid  = threadIdx.x;
    const int lane = tid & 31;
    const int warp = tid >> 5;
    const int wm   = warp >> 2;    // 0..1
    const int wn   = warp & 3;     // 0..3
    const int row0 = blockIdx.y * 128;
    const int col0 = blockIdx.x * 128;
    const int lg   = lane >> 2;    // group id 0..7
    const int lt   = lane & 3;     // thread-in-group 0..3

    float acc[4][4][4];
#pragma unroll
    for (int i=0;i<4;i++)
#pragma unroll
        for (int j=0;j<4;j++)
#pragma unroll
            for (int f=0;f<4;f++) acc[i][j][f] = 0.f;

    for (int k0 = 0; k0 < 256; k0 += 16) {
        // stage A tile 128x16 (2 float4 per thread), split hi/lo
#pragma unroll
        for (int it = 0; it < 2; it++) {
            int idx = tid + it*256;        // 0..511 float4 slots
            int r   = idx >> 2;            // 0..127
            int kc  = (idx & 3) << 2;      // 0,4,8,12
            int gr  = row0 + r;
            float4 v = make_float4(0.f,0.f,0.f,0.f);
            if (gr < M) v = *reinterpret_cast<const float4*>(&A[(size_t)gr*256 + k0 + kc]);
            float h0,l0; tf32_split(v.x,h0,l0); Ah[kc+0][r]=h0; Al[kc+0][r]=l0;
            float h1,l1; tf32_split(v.y,h1,l1); Ah[kc+1][r]=h1; Al[kc+1][r]=l1;
            float h2,l2; tf32_split(v.z,h2,l2); Ah[kc+2][r]=h2; Al[kc+2][r]=l2;
            float h3,l3; tf32_split(v.w,h3,l3); Ah[kc+3][r]=h3; Al[kc+3][r]=l3;
        }
        // stage W tile 16x128 (2 float4 per thread), split hi/lo
#pragma unroll
        for (int it = 0; it < 2; it++) {
            int idx = tid + it*256;
            int kr  = idx >> 5;            // 0..15
            int nc  = (idx & 31) << 2;     // 0..124
            float4 v = *reinterpret_cast<const float4*>(&W[(size_t)(k0+kr)*256 + col0 + nc]);
            float h0,l0; tf32_split(v.x,h0,l0); Wh[kr][nc+0]=h0; Wl[kr][nc+0]=l0;
            float h1,l1; tf32_split(v.y,h1,l1); Wh[kr][nc+1]=h1; Wl[kr][nc+1]=l1;
            float h2,l2; tf32_split(v.z,h2,l2); Wh[kr][nc+2]=h2; Wl[kr][nc+2]=l2;
            float h3,l3; tf32_split(v.w,h3,l3); Wh[kr][nc+3]=h3; Wl[kr][nc+3]=l3;
        }
        __syncthreads();

#pragma unroll
        for (int s = 0; s < 16; s += 8) {
            float ah[4][4], al[4][4], bh[4][2], bl[4][2];
#pragma unroll
            for (int mi = 0; mi < 4; mi++) {
                int r0 = wm*64 + mi*16 + lg;
                int cc = s + lt;
                ah[mi][0] = Ah[cc  ][r0];   ah[mi][1] = Ah[cc  ][r0+8];
                ah[mi][2] = Ah[cc+4][r0];   ah[mi][3] = Ah[cc+4][r0+8];
                al[mi][0] = Al[cc  ][r0];   al[mi][1] = Al[cc  ][r0+8];
                al[mi][2] = Al[cc+4][r0];   al[mi][3] = Al[cc+4][r0+8];
            }
#pragma unroll
            for (int nj = 0; nj < 4; nj++) {
                int n0 = wn*32 + nj*8 + lg;
                bh[nj][0] = Wh[s+lt  ][n0]; bh[nj][1] = Wh[s+4+lt][n0];
                bl[nj][0] = Wl[s+lt  ][n0]; bl[nj][1] = Wl[s+4+lt][n0];
            }
#pragma unroll
            for (int mi = 0; mi < 4; mi++)
#pragma unroll
                for (int nj = 0; nj < 4; nj++) {
                    mma_tf32(acc[mi][nj], al[mi], bh[nj]);   // small terms first
                    mma_tf32(acc[mi][nj], ah[mi], bl[nj]);
                    mma_tf32(acc[mi][nj], ah[mi], bh[nj]);
                }
        }
        __syncthreads();
    }

    // epilogue
#pragma unroll
    for (int mi = 0; mi < 4; mi++) {
#pragma unroll
        for (int nj = 0; nj < 4; nj++) {
            int r  = row0 + wm*64 + mi*16 + lg;
            int cb = col0 + wn*32 + nj*8 + 2*lt;
            float b0 = bias[cb], b1 = bias[cb+1];
#pragma unroll
            for (int half = 0; half < 2; half++) {
                int rr = r + half*8;
                if (rr >= M) continue;
                float v0 = acc[mi][nj][2*half+0] + b0;
                float v1 = acc[mi][nj][2*half+1] + b1;
                if (do_elu) {
                    v0 = v0 > 0.f ? v0 : expm1f(v0);
                    v1 = v1 > 0.f ? v1 : expm1f(v1);
                }
                *reinterpret_cast<float2*>(&C[(size_t)rr*256 + cb]) = make_float2(v0, v1);
            }
        }
    }
}

// ---------------- LSTM gates: K-split partial GEMM ----------------
// gpart[kc][b][j] = partial of xin@Wih^T + h@Whh^T over K chunk kc (64 wide)
// grid (GJ/64=16, nch); block 256. BM=128 (full batch), BN=64, per-thread 8x4.
__global__ void __launch_bounds__(256) lstm_gates2(
    const float* __restrict__ xin, int Kx,
    const float* __restrict__ h,
    const float* __restrict__ Wih, const float* __restrict__ Whh,
    float* __restrict__ gpart)
{
    __shared__ float As[16][132];
    __shared__ float Bs[16][68];
    const int tid = threadIdx.x;
    const int j0  = blockIdx.x * 64;
    const int kc  = blockIdx.y;
    const int kg0 = kc * 64;
    const float* Asrc; const float* Wsrc; int ld, koff;
    if (kg0 < Kx) { Asrc = xin; Wsrc = Wih; ld = Kx; koff = kg0; }
    else          { Asrc = h;   Wsrc = Whh; ld = GH; koff = kg0 - Kx; }

    const int tx = tid & 15;   // 4 n each
    const int ty = tid >> 4;   // 8 m each
    float acc[8][4];
#pragma unroll
    for (int i=0;i<8;i++)
#pragma unroll
        for (int j=0;j<4;j++) acc[i][j]=0.f;

    for (int ks = 0; ks < 64; ks += 16) {
        // stage A: 128 rows x 16 k; 2 float4 per thread
#pragma unroll
        for (int it = 0; it < 2; it++) {
            int idx = tid + it*256;
            int r   = idx >> 2;
            int kcc = (idx & 3) << 2;
            float4 v = *reinterpret_cast<const float4*>(&Asrc[(size_t)r*ld + koff + ks + kcc]);
            As[kcc+0][r]=v.x; As[kcc+1][r]=v.y; As[kcc+2][r]=v.z; As[kcc+3][r]=v.w;
        }
        // stage W: 64 j rows x 16 k; 1 float4 per thread
        {
            int jr  = tid >> 2;
            int kcc = (tid & 3) << 2;
            float4 v = *reinterpret_cast<const float4*>(&Wsrc[(size_t)(j0+jr)*ld + koff + ks + kcc]);
            Bs[kcc+0][jr]=v.x; Bs[kcc+1][jr]=v.y; Bs[kcc+2][jr]=v.z; Bs[kcc+3][jr]=v.w;
        }
        __syncthreads();
#pragma unroll
        for (int kk = 0; kk < 16; kk++) {
            float ra[8], rb[4];
#pragma unroll
            for (int i=0;i<8;i++) ra[i] = As[kk][ty*8+i];
#pragma unroll
            for (int j=0;j<4;j++) rb[j] = Bs[kk][tx*4+j];
#pragma unroll
            for (int i=0;i<8;i++)
#pragma unroll
                for (int j=0;j<4;j++) acc[i][j] = fmaf(ra[i], rb[j], acc[i][j]);
        }
        __syncthreads();
    }
#pragma unroll
    for (int i=0;i<8;i++) {
        int b = ty*8 + i;
        float4 v = make_float4(acc[i][0], acc[i][1], acc[i][2], acc[i][3]);
        *reinterpret_cast<float4*>(&gpart[((size_t)kc*GB + b)*GJ + j0 + tx*4]) = v;
    }
}

// reduce partials + biases + activation
__global__ void lstm_cell2(const float* __restrict__ gpart, int nch,
                           const float* __restrict__ bih, const float* __restrict__ bhh,
                           float* __restrict__ h, float* __restrict__ c)
{
    int idx = blockIdx.x * blockDim.x + threadIdx.x;  // GB*GH
    int b = idx >> 8, k = idx & 255;
    float gi = bih[k      ] + bhh[k      ];
    float gf = bih[GH  +k ] + bhh[GH  +k ];
    float gg = bih[2*GH+k ] + bhh[2*GH+k ];
    float go = bih[3*GH+k ] + bhh[3*GH+k ];
    for (int kc = 0; kc < nch; kc++) {
        const float* gp = gpart + ((size_t)kc*GB + b)*GJ;
        gi += gp[k];
        gf += gp[GH  + k];
        gg += gp[2*GH + k];
        go += gp[3*GH + k];
    }
    float si = 1.f/(1.f+expf(-gi));
    float sf = 1.f/(1.f+expf(-gf));
    float so = 1.f/(1.f+expf(-go));
    float cn = sf*c[idx] + si*tanhf(gg);
    c[idx] = cn;
    h[idx] = so * tanhf(cn);
}

// ---------------- init kernels ----------------
__global__ void init_state(){
    int idx = blockIdx.x*blockDim.x + threadIdx.x;
    if (idx < 3*GB*GH){ g_h[idx]=0.f; g_c[idx]=0.f; }
    if (idx < GB*2*GH) g_qstar[idx]=0.f;
}
__global__ void init_step(){
    int idx = blockIdx.x*blockDim.x + threadIdx.x;
    if (idx < GB){ g_menc[idx] = 0x007FFFFFu; /* fenc(-inf) */ g_denom[idx] = 0.f; }
    if (idx < GB*GH) g_r[idx] = 0.f;
}

// ---------------- attention ----------------
// one warp per node: e[n] = dot(hfeat[n], q[bi[n]]), atomicMax segment max
__global__ void __launch_bounds__(256) attn_e(const float* __restrict__ q,
                                              const int* __restrict__ bi)
{
    int gw   = (blockIdx.x * 256 + threadIdx.x) >> 5;
    int lane = threadIdx.x & 31;
    if (gw >= GN) return;
    int b = bi[gw];
    const float4* hr = reinterpret_cast<const float4*>(g_hfeat + (size_t)gw*GH);
    const float4* qr = reinterpret_cast<const float4*>(q + (size_t)b*GH);
    float s = 0.f;
#pragma unroll
    for (int i=0;i<2;i++){
        float4 a = hr[lane + 32*i];
        float4 w = qr[lane + 32*i];
        s += a.x*w.x + a.y*w.y + a.z*w.z + a.w*w.w;
    }
#pragma unroll
    for (int off=16; off>0; off>>=1) s += __shfl_xor_sync(0xffffffffu, s, off);
    if (lane == 0){
        g_e[gw] = s;
        atomicMax(&g_menc[b], fenc(s));
    }
}

__global__ void m_fin(){
    int b = threadIdx.x;
    if (b < GB){
        float m = fdec(g_menc[b]);
        g_m[b] = isfinite(m) ? m : 0.f;
    }
}

__global__ void attn_ex(const int* __restrict__ bi){
    int n = blockIdx.x*blockDim.x + threadIdx.x;
    if (n >= GN) return;
    int b = bi[n];
    float v = expf(g_e[n] - g_m[b]);
    g_ex[n] = v;
    atomicAdd(&g_denom[b], v);
}

// unnormalized r[b,h] = sum_{n in seg(b)} ex[n] * hfeat[n,h]
__global__ void __launch_bounds__(256) attn_r(const int* __restrict__ bi)
{
    int b = blockIdx.x;
    int chunk = blockIdx.y;
    int lo = 0, hi = GN;
    while (lo < hi){ int mid=(lo+hi)>>1; if (bi[mid] <  b) lo=mid+1; else hi=mid; }
    int start = lo; hi = GN;
    while (lo < hi){ int mid=(lo+hi)>>1; if (bi[mid] <= b) lo=mid+1; else hi=mid; }
    int end = lo;
    int len = end - start;
    if (len <= 0) return;
    int per = (len + 7) >> 3;
    int s = start + chunk*per;
    int t = min(end, s + per);
    if (s >= t) return;
    int hcol = threadIdx.x;
    float acc = 0.f;
    int n = s;
    for (; n + 4 <= t; n += 4){
        float e0=g_ex[n], e1=g_ex[n+1], e2=g_ex[n+2], e3=g_ex[n+3];
        float f0=g_hfeat[(size_t)(n  )*GH + hcol];
        float f1=g_hfeat[(size_t)(n+1)*GH + hcol];
        float f2=g_hfeat[(size_t)(n+2)*GH + hcol];
        float f3=g_hfeat[(size_t)(n+3)*GH + hcol];
        acc = fmaf(e0,f0,fmaf(e1,f1,fmaf(e2,f2,fmaf(e3,f3,acc))));
    }
    for (; n < t; n++) acc = fmaf(g_ex[n], g_hfeat[(size_t)n*GH + hcol], acc);
    atomicAdd(&g_r[b*GH + hcol], acc);
}

__global__ void build_qstar(const float* __restrict__ h2){
    int idx = blockIdx.x*blockDim.x + threadIdx.x;  // GB*512
    if (idx >= GB*2*GH) return;
    int b = idx >> 9, k = idx & 511;
    if (k < GH) g_qstar[idx] = h2[b*GH + k];
    else        g_qstar[idx] = g_r[b*GH + (k - GH)] / (g_denom[b] + 1e-16f);
}

// out[b,e] = q_star[b,:] @ out_W[:,e] + out_b[e]
__global__ void out_gemm(const float* __restrict__ W, const float* __restrict__ bias,
                         float* __restrict__ out)
{
    int b = blockIdx.x, e = threadIdx.x;
    const float* qs = g_qstar + (size_t)b*(2*GH);
    float acc = bias[e];
    for (int k = 0; k < 2*GH; k++) acc = fmaf(qs[k], W[(size_t)k*GE + e], acc);
    out[(size_t)b*GE + e] = acc;
}

// ---------------- launch ----------------
extern "C" void kernel_launch(void* const* d_in, const int* in_sizes, int n_in,
                              void* d_out, int out_size)
{
    const float* x    = (const float*)d_in[0];
    const int*   bi   = (const int*)  d_in[1];
    const float* W1   = (const float*)d_in[2];
    const float* b1   = (const float*)d_in[3];
    const float* W2   = (const float*)d_in[4];
    const float* b2   = (const float*)d_in[5];
    const float* Wih[3] = {(const float*)d_in[6],  (const float*)d_in[10], (const float*)d_in[14]};
    const float* Whh[3] = {(const float*)d_in[7],  (const float*)d_in[11], (const float*)d_in[15]};
    const float* bih[3] = {(const float*)d_in[8],  (const float*)d_in[12], (const float*)d_in[16]};
    const float* bhh[3] = {(const float*)d_in[9],  (const float*)d_in[13], (const float*)d_in[17]};
    const float* outW = (const float*)d_in[18];
    const float* outb = (const float*)d_in[19];

    float *t1, *hfeat, *gpart, *h, *c, *qstar;
    cudaGetSymbolAddress((void**)&t1,    g_t1);
    cudaGetSymbolAddress((void**)&hfeat, g_hfeat);
    cudaGetSymbolAddress((void**)&gpart, g_gpart);
    cudaGetSymbolAddress((void**)&h,     g_h);
    cudaGetSymbolAddress((void**)&c,     g_c);
    cudaGetSymbolAddress((void**)&qstar, g_qstar);

    dim3 gg(2, (GN + 127) / 128);
    gemm_tf32<<<gg, 256>>>(x,  W1, b1, t1,    GN, 1);
    gemm_tf32<<<gg, 256>>>(t1, W2, b2, hfeat, GN, 0);
    init_state<<<(3*GB*GH + 255)/256, 256>>>();

    for (int step = 0; step < NSTEPS; step++){
        const float* lin = qstar; int Kx = 2*GH;
        for (int l = 0; l < 3; l++){
            int nch = (Kx + GH) / 64;   // 12 for layer 0, 8 for layers 1,2
            lstm_gates2<<<dim3(GJ/64, nch), 256>>>(lin, Kx, h + l*GB*GH,
                                                   Wih[l], Whh[l], gpart);
            lstm_cell2<<<GB, GH>>>(gpart, nch, bih[l], bhh[l], h + l*GB*GH, c + l*GB*GH);
            lin = h + l*GB*GH; Kx = GH;
        }
        init_step<<<(GB*GH + 255)/256, 256>>>();
        attn_e<<<(GN*32 + 255)/256, 256>>>(h + 2*GB*GH, bi);
        m_fin<<<1, GB>>>();
        attn_ex<<<(GN + 255)/256, 256>>>(bi);
        attn_r<<<dim3(GB, 8), GH>>>(bi);
        build_qstar<<<(GB*2*GH + 255)/256, 256>>>(h + 2*GB*GH);
    }
    out_gemm<<<GB, GE>>>(outW, outb, (float*)d_out);
}

// round 8
// speedup vs baseline: 2.3923x; 1.1532x over previous
#include <cuda_runtime.h>
#include <cuda_bf16.h>
#include <math.h>
#include <stdint.h>

#define GN 100000
#define GD 256
#define GH 256
#define GB 128
#define GE 128
#define NSTEPS 5
#define GJ (4*GH)     // 1024 gate width
#define NCHMAX 12     // max K chunks (layer0: (512+256)/64 = 12)

// ---------------- scratch (device globals; no allocations) ----------------
__device__ float g_t1[(size_t)GN*GH];     // elu(x@W1+b1)
__device__ float g_hfeat[(size_t)GN*GH];  // node features
__device__ float g_e[GN];
__device__ float g_ex[GN];
__device__ float g_h[3*GB*GH];
__device__ float g_c[3*GB*GH];
__device__ float g_qstar[GB*2*GH];
__device__ float g_gpart[(size_t)NCHMAX*GB*GJ];  // LSTM gate partial sums
__device__ unsigned g_menc[GB];
__device__ float g_m[GB];
__device__ float g_denom[GB];
__device__ float g_r[GB*GH];
// W^T hi/lo splits for the two FNN weights ([N=256][K=256], K-major)
__device__ __nv_bfloat16 g_wt1h[GD*GH], g_wt1l[GD*GH];
__device__ __nv_bfloat16 g_wt2h[GH*GH], g_wt2l[GH*GH];

// monotone float<->uint encoding for atomicMax over signed floats
__device__ __forceinline__ unsigned fenc(float f){
    unsigned u = __float_as_uint(f);
    return (u & 0x80000000u) ? ~u : (u | 0x80000000u);
}
__device__ __forceinline__ float fdec(unsigned u){
    unsigned b = (u & 0x80000000u) ? (u ^ 0x80000000u) : ~u;
    return __uint_as_float(b);
}

// ---------------- mma/ldmatrix helpers (family-wide instructions only) ----------------
__device__ __forceinline__ uint32_t smem_u32(const void* p){
    uint32_t a;
    asm("{ .reg .u64 t; cvta.to.shared.u64 t, %1; cvt.u32.u64 %0, t; }" : "=r"(a) : "l"(p));
    return a;
}
__device__ __forceinline__ void ldsm4(uint32_t r[4], uint32_t addr){
    asm volatile("ldmatrix.sync.aligned.m8n8.x4.shared.b16 {%0,%1,%2,%3}, [%4];"
        : "=r"(r[0]), "=r"(r[1]), "=r"(r[2]), "=r"(r[3]) : "r"(addr));
}
__device__ __forceinline__ void mma16816(float d[4], const uint32_t a[4], uint32_t b0, uint32_t b1){
    asm volatile("mma.sync.aligned.m16n8k16.row.col.f32.bf16.bf16.f32 "
        "{%0,%1,%2,%3},{%4,%5,%6,%7},{%8,%9},{%0,%1,%2,%3};"
        : "+f"(d[0]), "+f"(d[1]), "+f"(d[2]), "+f"(d[3])
        : "r"(a[0]), "r"(a[1]), "r"(a[2]), "r"(a[3]), "r"(b0), "r"(b1));
}

__device__ __forceinline__ void split8(float4 a, float4 b, uint4& hi, uint4& lo){
    float v[8] = {a.x,a.y,a.z,a.w,b.x,b.y,b.z,b.w};
    unsigned short hs[8], ls[8];
#pragma unroll
    for (int i=0;i<8;i++){
        __nv_bfloat16 h = __float2bfloat16_rn(v[i]);
        hs[i] = __bfloat16_as_ushort(h);
        float r = v[i] - __bfloat162float(h);
        ls[i] = __bfloat16_as_ushort(__float2bfloat16_rn(r));
    }
    hi.x = hs[0] | ((uint32_t)hs[1]<<16); hi.y = hs[2] | ((uint32_t)hs[3]<<16);
    hi.z = hs[4] | ((uint32_t)hs[5]<<16); hi.w = hs[6] | ((uint32_t)hs[7]<<16);
    lo.x = ls[0] | ((uint32_t)ls[1]<<16); lo.y = ls[2] | ((uint32_t)ls[3]<<16);
    lo.z = ls[4] | ((uint32_t)ls[5]<<16); lo.w = ls[6] | ((uint32_t)ls[7]<<16);
}

// ---------------- W^T hi/lo prep (transpose through shared) ----------------
__global__ void wt_prep(const float* __restrict__ W,
                        __nv_bfloat16* __restrict__ Th, __nv_bfloat16* __restrict__ Tl)
{
    __shared__ float tile[32][33];
    int n0 = blockIdx.x*32, k0 = blockIdx.y*32;
    int tx = threadIdx.x, ty = threadIdx.y;   // block (32,8)
#pragma unroll
    for (int i=0;i<32;i+=8)
        tile[ty+i][tx] = W[(size_t)(k0+ty+i)*256 + n0+tx];
    __syncthreads();
#pragma unroll
    for (int i=0;i<32;i+=8){
        int n = n0 + ty + i, k = k0 + tx;
        float v = tile[tx][ty+i];
        __nv_bfloat16 h = __float2bfloat16_rn(v);
        Th[(size_t)n*256 + k] = h;
        Tl[(size_t)n*256 + k] = __float2bfloat16_rn(v - __bfloat162float(h));
    }
}

// ---------------- FNN GEMM: bf16 split on mma.sync.m16n8k16 ----------------
// C(Mx256) = A(Mx256)@W + bias [+ELU].  B = W^T hi/lo bf16 ([n][k] k-major).
// BM=128, BN=128, BK=32; 8 warps as 4m x 2n; warp tile 32m x 64n.
// smem/buffer: Ah 8K | Al 8K | Bh 8K | Bl 8K = 32K; double buffered (dynamic 64K).
#define GB_BUF 32768
__device__ __forceinline__ uint32_t sw_off(int r, int kc){
    return (uint32_t)(r*64 + ((kc ^ ((r>>1)&3))*16));
}

__global__ void __launch_bounds__(256, 1) gemm_bf16(
    const float* __restrict__ A,
    const __nv_bfloat16* __restrict__ Bh, const __nv_bfloat16* __restrict__ Bl,
    const float* __restrict__ bias, float* __restrict__ C, int M, int do_elu)
{
    extern __shared__ char smem[];
    const int tid = threadIdx.x, lane = tid & 31, wid = tid >> 5;
    const int row0 = blockIdx.y * 128;
    const int col0 = blockIdx.x * 128;
    const int mw = (wid >> 1) * 32;   // warp m offset
    const int nw = (wid & 1) * 64;    // warp n offset
    const uint32_t sbase = smem_u32(smem);

    float acc[2][8][4];
#pragma unroll
    for (int i=0;i<2;i++)
#pragma unroll
        for (int j=0;j<8;j++)
#pragma unroll
            for (int f=0;f<4;f++) acc[i][j][f]=0.f;

    // staging registers
    float4 ra[4];
    uint4  rbh[2], rbl[2];
    const int sr = tid >> 1;          // staging row 0..127
    const int skh = (tid & 1) * 16;   // k sub-offset (elements)

    auto ld_regs = [&](int it){
        int k0 = it*32;
        bool ok = (row0 + sr) < M;
        const float* ap = A + (size_t)(row0+sr)*256 + k0 + skh;
#pragma unroll
        for (int i=0;i<4;i++)
            ra[i] = ok ? *reinterpret_cast<const float4*>(ap + i*4)
                       : make_float4(0.f,0.f,0.f,0.f);
        const __nv_bfloat16* bhp = Bh + (size_t)(col0+sr)*256 + k0 + skh;
        const __nv_bfloat16* blp = Bl + (size_t)(col0+sr)*256 + k0 + skh;
        rbh[0] = *reinterpret_cast<const uint4*>(bhp);
        rbh[1] = *reinterpret_cast<const uint4*>(bhp+8);
        rbl[0] = *reinterpret_cast<const uint4*>(blp);
        rbl[1] = *reinterpret_cast<const uint4*>(blp+8);
    };
    auto st_smem = [&](int buf){
        char* base = smem + buf*GB_BUF;
        int c0 = (tid & 1) * 2;       // chunk pair 0/1 or 2/3
        uint4 h0,l0,h1,l1;
        split8(ra[0], ra[1], h0, l0);
        split8(ra[2], ra[3], h1, l1);
        *reinterpret_cast<uint4*>(base +         sw_off(sr, c0  )) = h0;
        *reinterpret_cast<uint4*>(base +         sw_off(sr, c0+1)) = h1;
        *reinterpret_cast<uint4*>(base +  8192 + sw_off(sr, c0  )) = l0;
        *reinterpret_cast<uint4*>(base +  8192 + sw_off(sr, c0+1)) = l1;
        *reinterpret_cast<uint4*>(base + 16384 + sw_off(sr, c0  )) = rbh[0];
        *reinterpret_cast<uint4*>(base + 16384 + sw_off(sr, c0+1)) = rbh[1];
        *reinterpret_cast<uint4*>(base + 24576 + sw_off(sr, c0  )) = rbl[0];
        *reinterpret_cast<uint4*>(base + 24576 + sw_off(sr, c0+1)) = rbl[1];
    };
    auto compute = [&](int buf){
        uint32_t aB = sbase + buf*GB_BUF;
        const int lr = (lane & 7) + ((lane >> 3) & 1) * 8;   // ldmatrix row within 16
        const int lk = lane >> 4;                            // ldmatrix k-chunk select
#pragma unroll
        for (int s = 0; s < 2; s++){
            uint32_t ah[2][4], al[2][4];
#pragma unroll
            for (int f = 0; f < 2; f++){
                int r  = mw + f*16 + lr;
                int kc = s*2 + lk;
                uint32_t ad = aB + sw_off(r, kc);
                ldsm4(ah[f], ad);
                ldsm4(al[f], ad + 8192);
            }
            uint32_t bh[4][4], bl[4][4];
#pragma unroll
            for (int g = 0; g < 4; g++){
                int n  = nw + g*16 + lr;
                int kc = s*2 + lk;
                uint32_t ad = aB + 16384 + sw_off(n, kc);
                ldsm4(bh[g], ad);
                ldsm4(bl[g], ad + 8192);
            }
#pragma unroll
            for (int mi = 0; mi < 2; mi++)
#pragma unroll
                for (int g = 0; g < 4; g++)
#pragma unroll
                    for (int t = 0; t < 2; t++){
                        float* d = acc[mi][g*2+t];
                        mma16816(d, al[mi], bh[g][t], bh[g][2+t]);
                        mma16816(d, ah[mi], bl[g][t], bl[g][2+t]);
                        mma16816(d, ah[mi], bh[g][t], bh[g][2+t]);
                    }
        }
    };

    ld_regs(0);
    st_smem(0);
    __syncthreads();
#pragma unroll 1
    for (int it = 0; it < 8; it++){
        if (it + 1 < 8) ld_regs(it + 1);
        compute(it & 1);
        __syncthreads();
        if (it + 1 < 8){
            st_smem((it + 1) & 1);
            __syncthreads();
        }
    }

    // epilogue
#pragma unroll
    for (int mi = 0; mi < 2; mi++){
#pragma unroll
        for (int j = 0; j < 8; j++){
            int r  = row0 + mw + mi*16 + (lane >> 2);
            int cb = col0 + nw + (j>>1)*16 + (j&1)*8 + (lane & 3)*2;
            float b0 = bias[cb], b1 = bias[cb+1];
            float v0 = acc[mi][j][0] + b0, v1 = acc[mi][j][1] + b1;
            float v2 = acc[mi][j][2] + b0, v3 = acc[mi][j][3] + b1;
            if (do_elu){
                v0 = v0 > 0.f ? v0 : expm1f(v0);
                v1 = v1 > 0.f ? v1 : expm1f(v1);
                v2 = v2 > 0.f ? v2 : expm1f(v2);
                v3 = v3 > 0.f ? v3 : expm1f(v3);
            }
            if (r < M)     *reinterpret_cast<float2*>(&C[(size_t)r*256 + cb])     = make_float2(v0, v1);
            if (r + 8 < M) *reinterpret_cast<float2*>(&C[(size_t)(r+8)*256 + cb]) = make_float2(v2, v3);
        }
    }
}

// ---------------- LSTM gates: K-split partial GEMM (vectorized LDS) ----------------
__global__ void __launch_bounds__(256) lstm_gates2(
    const float* __restrict__ xin, int Kx,
    const float* __restrict__ h,
    const float* __restrict__ Wih, const float* __restrict__ Whh,
    float* __restrict__ gpart)
{
    __shared__ __align__(16) float As[16][132];
    __shared__ __align__(16) float Bs[16][68];
    const int tid = threadIdx.x;
    const int j0  = blockIdx.x * 64;
    const int kc  = blockIdx.y;
    const int kg0 = kc * 64;
    const float* Asrc; const float* Wsrc; int ld, koff;
    if (kg0 < Kx) { Asrc = xin; Wsrc = Wih; ld = Kx; koff = kg0; }
    else          { Asrc = h;   Wsrc = Whh; ld = GH; koff = kg0 - Kx; }

    const int tx = tid & 15;   // 4 n each
    const int ty = tid >> 4;   // 8 m each
    float acc[8][4];
#pragma unroll
    for (int i=0;i<8;i++)
#pragma unroll
        for (int j=0;j<4;j++) acc[i][j]=0.f;

    for (int ks = 0; ks < 64; ks += 16) {
#pragma unroll
        for (int it = 0; it < 2; it++) {
            int idx = tid + it*256;
            int r   = idx >> 2;
            int kcc = (idx & 3) << 2;
            float4 v = *reinterpret_cast<const float4*>(&Asrc[(size_t)r*ld + koff + ks + kcc]);
            As[kcc+0][r]=v.x; As[kcc+1][r]=v.y; As[kcc+2][r]=v.z; As[kcc+3][r]=v.w;
        }
        {
            int jr  = tid >> 2;
            int kcc = (tid & 3) << 2;
            float4 v = *reinterpret_cast<const float4*>(&Wsrc[(size_t)(j0+jr)*ld + koff + ks + kcc]);
            Bs[kcc+0][jr]=v.x; Bs[kcc+1][jr]=v.y; Bs[kcc+2][jr]=v.z; Bs[kcc+3][jr]=v.w;
        }
        __syncthreads();
#pragma unroll
        for (int kk = 0; kk < 16; kk++) {
            float4 a0 = *reinterpret_cast<const float4*>(&As[kk][ty*8]);
            float4 a1 = *reinterpret_cast<const float4*>(&As[kk][ty*8+4]);
            float4 b  = *reinterpret_cast<const float4*>(&Bs[kk][tx*4]);
            float ra[8] = {a0.x,a0.y,a0.z,a0.w,a1.x,a1.y,a1.z,a1.w};
            float rb[4] = {b.x,b.y,b.z,b.w};
#pragma unroll
            for (int i=0;i<8;i++)
#pragma unroll
                for (int j=0;j<4;j++) acc[i][j] = fmaf(ra[i], rb[j], acc[i][j]);
        }
        __syncthreads();
    }
#pragma unroll
    for (int i=0;i<8;i++) {
        int b = ty*8 + i;
        float4 v = make_float4(acc[i][0], acc[i][1], acc[i][2], acc[i][3]);
        *reinterpret_cast<float4*>(&gpart[((size_t)kc*GB + b)*GJ + j0 + tx*4]) = v;
    }
}

// reduce partials + biases + activation
__global__ void lstm_cell2(const float* __restrict__ gpart, int nch,
                           const float* __restrict__ bih, const float* __restrict__ bhh,
                           float* __restrict__ h, float* __restrict__ c)
{
    int idx = blockIdx.x * blockDim.x + threadIdx.x;  // GB*GH
    int b = idx >> 8, k = idx & 255;
    float gi = bih[k      ] + bhh[k      ];
    float gf = bih[GH  +k ] + bhh[GH  +k ];
    float gg = bih[2*GH+k ] + bhh[2*GH+k ];
    float go = bih[3*GH+k ] + bhh[3*GH+k ];
    for (int kc = 0; kc < nch; kc++) {
        const float* gp = gpart + ((size_t)kc*GB + b)*GJ;
        gi += gp[k];
        gf += gp[GH  + k];
        gg += gp[2*GH + k];
        go += gp[3*GH + k];
    }
    float si = 1.f/(1.f+expf(-gi));
    float sf = 1.f/(1.f+expf(-gf));
    float so = 1.f/(1.f+expf(-go));
    float cn = sf*c[idx] + si*tanhf(gg);
    c[idx] = cn;
    h[idx] = so * tanhf(cn);
}

// ---------------- init kernels ----------------
__global__ void init_state(){
    int idx = blockIdx.x*blockDim.x + threadIdx.x;
    if (idx < 3*GB*GH){ g_h[idx]=0.f; g_c[idx]=0.f; }
    if (idx < GB*2*GH) g_qstar[idx]=0.f;
}
__global__ void init_step(){
    int idx = blockIdx.x*blockDim.x + threadIdx.x;
    if (idx < GB){ g_menc[idx] = 0x007FFFFFu; g_denom[idx] = 0.f; }
    if (idx < GB*GH) g_r[idx] = 0.f;
}

// ---------------- attention ----------------
__global__ void __launch_bounds__(256) attn_e(const float* __restrict__ q,
                                              const int* __restrict__ bi)
{
    int gw   = (blockIdx.x * 256 + threadIdx.x) >> 5;
    int lane = threadIdx.x & 31;
    if (gw >= GN) return;
    int b = bi[gw];
    const float4* hr = reinterpret_cast<const float4*>(g_hfeat + (size_t)gw*GH);
    const float4* qr = reinterpret_cast<const float4*>(q + (size_t)b*GH);
    float s = 0.f;
#pragma unroll
    for (int i=0;i<2;i++){
        float4 a = hr[lane + 32*i];
        float4 w = qr[lane + 32*i];
        s += a.x*w.x + a.y*w.y + a.z*w.z + a.w*w.w;
    }
#pragma unroll
    for (int off=16; off>0; off>>=1) s += __shfl_xor_sync(0xffffffffu, s, off);
    if (lane == 0){
        g_e[gw] = s;
        atomicMax(&g_menc[b], fenc(s));
    }
}

__global__ void m_fin(){
    int b = threadIdx.x;
    if (b < GB){
        float m = fdec(g_menc[b]);
        g_m[b] = isfinite(m) ? m : 0.f;
    }
}

__global__ void attn_ex(const int* __restrict__ bi){
    int n = blockIdx.x*blockDim.x + threadIdx.x;
    if (n >= GN) return;
    int b = bi[n];
    float v = expf(g_e[n] - g_m[b]);
    g_ex[n] = v;
    atomicAdd(&g_denom[b], v);
}

__global__ void __launch_bounds__(256) attn_r(const int* __restrict__ bi)
{
    int b = blockIdx.x;
    int chunk = blockIdx.y;
    int lo = 0, hi = GN;
    while (lo < hi){ int mid=(lo+hi)>>1; if (bi[mid] <  b) lo=mid+1; else hi=mid; }
    int start = lo; hi = GN;
    while (lo < hi){ int mid=(lo+hi)>>1; if (bi[mid] <= b) lo=mid+1; else hi=mid; }
    int end = lo;
    int len = end - start;
    if (len <= 0) return;
    int per = (len + 7) >> 3;
    int s = start + chunk*per;
    int t = min(end, s + per);
    if (s >= t) return;
    int hcol = threadIdx.x;
    float acc = 0.f;
    int n = s;
    for (; n + 4 <= t; n += 4){
        float e0=g_ex[n], e1=g_ex[n+1], e2=g_ex[n+2], e3=g_ex[n+3];
        float f0=g_hfeat[(size_t)(n  )*GH + hcol];
        float f1=g_hfeat[(size_t)(n+1)*GH + hcol];
        float f2=g_hfeat[(size_t)(n+2)*GH + hcol];
        float f3=g_hfeat[(size_t)(n+3)*GH + hcol];
        acc = fmaf(e0,f0,fmaf(e1,f1,fmaf(e2,f2,fmaf(e3,f3,acc))));
    }
    for (; n < t; n++) acc = fmaf(g_ex[n], g_hfeat[(size_t)n*GH + hcol], acc);
    atomicAdd(&g_r[b*GH + hcol], acc);
}

__global__ void build_qstar(const float* __restrict__ h2){
    int idx = blockIdx.x*blockDim.x + threadIdx.x;
    if (idx >= GB*2*GH) return;
    int b = idx >> 9, k = idx & 511;
    if (k < GH) g_qstar[idx] = h2[b*GH + k];
    else        g_qstar[idx] = g_r[b*GH + (k - GH)] / (g_denom[b] + 1e-16f);
}

__global__ void out_gemm(const float* __restrict__ W, const float* __restrict__ bias,
                         float* __restrict__ out)
{
    int b = blockIdx.x, e = threadIdx.x;
    const float* qs = g_qstar + (size_t)b*(2*GH);
    float acc = bias[e];
    for (int k = 0; k < 2*GH; k++) acc = fmaf(qs[k], W[(size_t)k*GE + e], acc);
    out[(size_t)b*GE + e] = acc;
}

// ---------------- launch ----------------
extern "C" void kernel_launch(void* const* d_in, const int* in_sizes, int n_in,
                              void* d_out, int out_size)
{
    const float* x    = (const float*)d_in[0];
    const int*   bi   = (const int*)  d_in[1];
    const float* W1   = (const float*)d_in[2];
    const float* b1   = (const float*)d_in[3];
    const float* W2   = (const float*)d_in[4];
    const float* b2   = (const float*)d_in[5];
    const float* Wih[3] = {(const float*)d_in[6],  (const float*)d_in[10], (const float*)d_in[14]};
    const float* Whh[3] = {(const float*)d_in[7],  (const float*)d_in[11], (const float*)d_in[15]};
    const float* bih[3] = {(const float*)d_in[8],  (const float*)d_in[12], (const float*)d_in[16]};
    const float* bhh[3] = {(const float*)d_in[9],  (const float*)d_in[13], (const float*)d_in[17]};
    const float* outW = (const float*)d_in[18];
    const float* outb = (const float*)d_in[19];

    float *t1, *hfeat, *gpart, *h, *c, *qstar;
    __nv_bfloat16 *wt1h, *wt1l, *wt2h, *wt2l;
    cudaGetSymbolAddress((void**)&t1,    g_t1);
    cudaGetSymbolAddress((void**)&hfeat, g_hfeat);
    cudaGetSymbolAddress((void**)&gpart, g_gpart);
    cudaGetSymbolAddress((void**)&h,     g_h);
    cudaGetSymbolAddress((void**)&c,     g_c);
    cudaGetSymbolAddress((void**)&qstar, g_qstar);
    cudaGetSymbolAddress((void**)&wt1h,  g_wt1h);
    cudaGetSymbolAddress((void**)&wt1l,  g_wt1l);
    cudaGetSymbolAddress((void**)&wt2h,  g_wt2h);
    cudaGetSymbolAddress((void**)&wt2l,  g_wt2l);

    cudaFuncSetAttribute(gemm_bf16, cudaFuncAttributeMaxDynamicSharedMemorySize, 2*GB_BUF);

    wt_prep<<<dim3(8,8), dim3(32,8)>>>(W1, wt1h, wt1l);
    wt_prep<<<dim3(8,8), dim3(32,8)>>>(W2, wt2h, wt2l);

    dim3 gg(2, (GN + 127) / 128);
    gemm_bf16<<<gg, 256, 2*GB_BUF>>>(x,  wt1h, wt1l, b1, t1,    GN, 1);
    gemm_bf16<<<gg, 256, 2*GB_BUF>>>(t1, wt2h, wt2l, b2, hfeat, GN, 0);
    init_state<<<(3*GB*GH + 255)/256, 256>>>();

    for (int step = 0; step < NSTEPS; step++){
        const float* lin = qstar; int Kx = 2*GH;
        for (int l = 0; l < 3; l++){
            int nch = (Kx + GH) / 64;
            lstm_gates2<<<dim3(GJ/64, nch), 256>>>(lin, Kx, h + l*GB*GH,
                                                   Wih[l], Whh[l], gpart);
            lstm_cell2<<<GB, GH>>>(gpart, nch, bih[l], bhh[l], h + l*GB*GH, c + l*GB*GH);
            lin = h + l*GB*GH; Kx = GH;
        }
        init_step<<<(GB*GH + 255)/256, 256>>>();
        attn_e<<<(GN*32 + 255)/256, 256>>>(h + 2*GB*GH, bi);
        m_fin<<<1, GB>>>();
        attn_ex<<<(GN + 255)/256, 256>>>(bi);
        attn_r<<<dim3(GB, 8), GH>>>(bi);
        build_qstar<<<(GB*2*GH + 255)/256, 256>>>(h + 2*GB*GH);
    }
    out_gemm<<<GB, GE>>>(outW, outb, (float*)d_out);
}

// round 9
// speedup vs baseline: 2.4452x; 1.0221x over previous
#include <cuda_runtime.h>
#include <cuda_bf16.h>
#include <math.h>
#include <stdint.h>

#define GN 100000
#define GD 256
#define GH 256
#define GB 128
#define GE 128
#define NSTEPS 5
#define GJ (4*GH)     // 1024 gate width

// ---------------- scratch (device globals; no allocations) ----------------
__device__ __nv_bfloat16 g_t1h[(size_t)GN*GH], g_t1l[(size_t)GN*GH];  // split ELU output
__device__ float g_hfeat[(size_t)GN*GH];  // node features (fp32)
__device__ float g_h[3*GB*GH];
__device__ float g_c[3*GB*GH];
__device__ float g_qstar[GB*2*GH];
__device__ float g_gates[GB*GJ];
// FNN weight transposed hi/lo splits ([n][k] k-major)
__device__ __nv_bfloat16 g_wt1h[GD*GH], g_wt1l[GD*GH];
__device__ __nv_bfloat16 g_wt2h[GH*GH], g_wt2l[GH*GH];
// LSTM weight hi/lo splits (already [j][k]); Wih packed l0@0(1024x512), l1@524288, l2@786432
__device__ __nv_bfloat16 g_wihh[1024*1024], g_wihl[1024*1024];
__device__ __nv_bfloat16 g_whhh[3*1024*256], g_whhl[3*1024*256];
// attention chunk partials
__device__ float g_am[GB*8], g_as[GB*8], g_ar[(size_t)GB*8*256];

// ---------------- mma/ldmatrix/cp.async helpers (family-wide only) ----------------
__device__ __forceinline__ uint32_t smem_u32(const void* p){
    uint32_t a;
    asm("{ .reg .u64 t; cvta.to.shared.u64 t, %1; cvt.u32.u64 %0, t; }" : "=r"(a) : "l"(p));
    return a;
}
__device__ __forceinline__ void ldsm4(uint32_t r[4], uint32_t addr){
    asm volatile("ldmatrix.sync.aligned.m8n8.x4.shared.b16 {%0,%1,%2,%3}, [%4];"
        : "=r"(r[0]), "=r"(r[1]), "=r"(r[2]), "=r"(r[3]) : "r"(addr));
}
__device__ __forceinline__ void mma16816(float d[4], const uint32_t a[4], uint32_t b0, uint32_t b1){
    asm volatile("mma.sync.aligned.m16n8k16.row.col.f32.bf16.bf16.f32 "
        "{%0,%1,%2,%3},{%4,%5,%6,%7},{%8,%9},{%0,%1,%2,%3};"
        : "+f"(d[0]), "+f"(d[1]), "+f"(d[2]), "+f"(d[3])
        : "r"(a[0]), "r"(a[1]), "r"(a[2]), "r"(a[3]), "r"(b0), "r"(b1));
}
__device__ __forceinline__ void cpa16(uint32_t dst, const void* src){
    asm volatile("cp.async.cg.shared.global [%0], [%1], 16;" :: "r"(dst), "l"(src));
}
__device__ __forceinline__ void cpa_commit(){ asm volatile("cp.async.commit_group;"); }
__device__ __forceinline__ void cpa_wait0(){ asm volatile("cp.async.wait_group 0;" ::: "memory"); }

__device__ __forceinline__ uint32_t sw_off(int r, int kc){
    return (uint32_t)(r*64 + ((kc ^ ((r>>1)&3))*16));
}
__device__ __forceinline__ void split8(float4 a, float4 b, uint4& hi, uint4& lo){
    float v[8] = {a.x,a.y,a.z,a.w,b.x,b.y,b.z,b.w};
    unsigned short hs[8], ls[8];
#pragma unroll
    for (int i=0;i<8;i++){
        __nv_bfloat16 h = __float2bfloat16_rn(v[i]);
        hs[i] = __bfloat16_as_ushort(h);
        float r = v[i] - __bfloat162float(h);
        ls[i] = __bfloat16_as_ushort(__float2bfloat16_rn(r));
    }
    hi.x = hs[0] | ((uint32_t)hs[1]<<16); hi.y = hs[2] | ((uint32_t)hs[3]<<16);
    hi.z = hs[4] | ((uint32_t)hs[5]<<16); hi.w = hs[6] | ((uint32_t)hs[7]<<16);
    lo.x = ls[0] | ((uint32_t)ls[1]<<16); lo.y = ls[2] | ((uint32_t)ls[3]<<16);
    lo.z = ls[4] | ((uint32_t)ls[5]<<16); lo.w = ls[6] | ((uint32_t)ls[7]<<16);
}

// ---------------- weight prep ----------------
// transpose fp32 [k][n] -> bf16 hi/lo [n][k]
__global__ void wt_prep(const float* __restrict__ W,
                        __nv_bfloat16* __restrict__ Th, __nv_bfloat16* __restrict__ Tl)
{
    __shared__ float tile[32][33];
    int n0 = blockIdx.x*32, k0 = blockIdx.y*32;
    int tx = threadIdx.x, ty = threadIdx.y;   // block (32,8)
#pragma unroll
    for (int i=0;i<32;i+=8)
        tile[ty+i][tx] = W[(size_t)(k0+ty+i)*256 + n0+tx];
    __syncthreads();
#pragma unroll
    for (int i=0;i<32;i+=8){
        int n = n0 + ty + i, k = k0 + tx;
        float v = tile[tx][ty+i];
        __nv_bfloat16 h = __float2bfloat16_rn(v);
        Th[(size_t)n*256 + k] = h;
        Tl[(size_t)n*256 + k] = __float2bfloat16_rn(v - __bfloat162float(h));
    }
}
// elementwise hi/lo split (no transpose)
__global__ void wsplit(const float* __restrict__ src,
                       __nv_bfloat16* __restrict__ hi, __nv_bfloat16* __restrict__ lo, int n)
{
    int i = blockIdx.x*blockDim.x + threadIdx.x;
    if (i >= n) return;
    float v = src[i];
    __nv_bfloat16 h = __float2bfloat16_rn(v);
    hi[i] = h;
    lo[i] = __float2bfloat16_rn(v - __bfloat162float(h));
}

// ---------------- big FNN GEMM: BM=128, BN=256, BK=32 ----------------
// buffer: Ah[0,8K) Al[8K,16K) Bh[16K,32K) Bl[32K,48K); double buffered (96K dynamic)
#define FBUF 49152
template<bool ASPLIT, bool OSPLIT, bool ELU>
__global__ void __launch_bounds__(256, 1) gemm_big(
    const float* __restrict__ Af,
    const __nv_bfloat16* __restrict__ Ah_g, const __nv_bfloat16* __restrict__ Al_g,
    const __nv_bfloat16* __restrict__ Bh, const __nv_bfloat16* __restrict__ Bl,
    const float* __restrict__ bias,
    float* __restrict__ Cf, __nv_bfloat16* __restrict__ Ch, __nv_bfloat16* __restrict__ Cl,
    int M)
{
    extern __shared__ char smem[];
    const int tid = threadIdx.x, lane = tid & 31, wid = tid >> 5;
    const int row0 = blockIdx.x * 128;
    const int wm = (wid & 1) * 64;     // warp m offset (2 groups)
    const int wn = (wid >> 1) * 64;    // warp n offset (4 groups)
    const uint32_t sbase = smem_u32(smem);

    float acc[4][8][4];
#pragma unroll
    for (int i=0;i<4;i++)
#pragma unroll
        for (int j=0;j<8;j++)
#pragma unroll
            for (int f=0;f<4;f++) acc[i][j][f]=0.f;

    // staging (conv-A path)
    float4 ra[4];
    const int sr  = tid >> 1;
    const int skh = (tid & 1) * 16;

    auto cpB = [&](int it, int buf){
        uint32_t base = sbase + buf*FBUF;
        int k0 = it*32;
#pragma unroll
        for (int t = 0; t < 4; t++){
            int idx = tid + t*256;          // 0..1023
            int r = idx >> 2, kc = idx & 3;
            uint32_t d = base + 16384 + sw_off(r, kc);
            cpa16(d,        Bh + (size_t)r*256 + k0 + kc*8);
            cpa16(d + 16384, Bl + (size_t)r*256 + k0 + kc*8);
        }
    };
    auto cpA = [&](int it, int buf){
        uint32_t base = sbase + buf*FBUF;
        int k0 = it*32;
#pragma unroll
        for (int t = 0; t < 2; t++){
            int idx = tid + t*256;          // 0..511
            int r = idx >> 2, kc = idx & 3;
            uint32_t d = base + sw_off(r, kc);
            cpa16(d,       Ah_g + (size_t)(row0+r)*256 + k0 + kc*8);
            cpa16(d + 8192, Al_g + (size_t)(row0+r)*256 + k0 + kc*8);
        }
    };
    auto ldA = [&](int it){
        int k0 = it*32;
        bool ok = (row0 + sr) < M;
        const float* ap = Af + (size_t)(row0+sr)*256 + k0 + skh;
#pragma unroll
        for (int i=0;i<4;i++)
            ra[i] = ok ? *reinterpret_cast<const float4*>(ap + i*4)
                       : make_float4(0.f,0.f,0.f,0.f);
    };
    auto stA = [&](int buf){
        char* base = smem + buf*FBUF;
        int c0 = (tid & 1) * 2;
        uint4 h0,l0,h1,l1;
        split8(ra[0], ra[1], h0, l0);
        split8(ra[2], ra[3], h1, l1);
        *reinterpret_cast<uint4*>(base +        sw_off(sr, c0  )) = h0;
        *reinterpret_cast<uint4*>(base +        sw_off(sr, c0+1)) = h1;
        *reinterpret_cast<uint4*>(base + 8192 + sw_off(sr, c0  )) = l0;
        *reinterpret_cast<uint4*>(base + 8192 + sw_off(sr, c0+1)) = l1;
    };
    auto compute = [&](int buf){
        uint32_t aB = sbase + buf*FBUF;
        const int lr = (lane & 7) + ((lane >> 3) & 1) * 8;
        const int lk = lane >> 4;
#pragma unroll
        for (int s = 0; s < 2; s++){
            int kc = s*2 + lk;
            uint32_t ah[4][4], al[4][4];
#pragma unroll
            for (int f = 0; f < 4; f++){
                uint32_t ad = aB + sw_off(wm + f*16 + lr, kc);
                ldsm4(ah[f], ad);
                ldsm4(al[f], ad + 8192);
            }
            uint32_t bh[4][4], bl[4][4];
#pragma unroll
            for (int g = 0; g < 4; g++){
                uint32_t ad = aB + 16384 + sw_off(wn + g*16 + lr, kc);
                ldsm4(bh[g], ad);
                ldsm4(bl[g], ad + 16384);
            }
#pragma unroll
            for (int f = 0; f < 4; f++)
#pragma unroll
                for (int g = 0; g < 4; g++)
#pragma unroll
                    for (int t = 0; t < 2; t++){
                        float* d = acc[f][g*2+t];
                        mma16816(d, al[f], bh[g][t], bh[g][2+t]);
                        mma16816(d, ah[f], bl[g][t], bl[g][2+t]);
                        mma16816(d, ah[f], bh[g][t], bh[g][2+t]);
                    }
        }
    };

    // prologue
    if (ASPLIT){ cpA(0,0); } else { ldA(0); }
    cpB(0,0); cpa_commit();
    if (!ASPLIT) stA(0);
    cpa_wait0(); __syncthreads();

#pragma unroll 1
    for (int it = 0; it < 8; it++){
        int buf = it & 1, nbuf = buf ^ 1;
        if (it + 1 < 8){
            if (ASPLIT){ cpA(it+1, nbuf); } else { ldA(it+1); }
            cpB(it+1, nbuf); cpa_commit();
        }
        compute(buf);
        __syncthreads();
        if (it + 1 < 8){
            if (!ASPLIT) stA(nbuf);
            cpa_wait0(); __syncthreads();
        }
    }

    // epilogue
#pragma unroll
    for (int f = 0; f < 4; f++){
        int r = row0 + wm + f*16 + (lane >> 2);
#pragma unroll
        for (int j = 0; j < 8; j++){
            int cb = wn + (j>>1)*16 + (j&1)*8 + (lane & 3)*2;
            float b0 = bias[cb], b1 = bias[cb+1];
            float v0 = acc[f][j][0] + b0, v1 = acc[f][j][1] + b1;
            float v2 = acc[f][j][2] + b0, v3 = acc[f][j][3] + b1;
            if (ELU){
                v0 = v0 > 0.f ? v0 : expm1f(v0);
                v1 = v1 > 0.f ? v1 : expm1f(v1);
                v2 = v2 > 0.f ? v2 : expm1f(v2);
                v3 = v3 > 0.f ? v3 : expm1f(v3);
            }
            if (OSPLIT){
                if (r < M){
                    __nv_bfloat16 h0=__float2bfloat16_rn(v0), h1=__float2bfloat16_rn(v1);
                    Ch[(size_t)r*256+cb]   = h0;  Ch[(size_t)r*256+cb+1] = h1;
                    Cl[(size_t)r*256+cb]   = __float2bfloat16_rn(v0-__bfloat162float(h0));
                    Cl[(size_t)r*256+cb+1] = __float2bfloat16_rn(v1-__bfloat162float(h1));
                }
                if (r + 8 < M){
                    __nv_bfloat16 h2=__float2bfloat16_rn(v2), h3=__float2bfloat16_rn(v3);
                    Ch[(size_t)(r+8)*256+cb]   = h2;  Ch[(size_t)(r+8)*256+cb+1] = h3;
                    Cl[(size_t)(r+8)*256+cb]   = __float2bfloat16_rn(v2-__bfloat162float(h2));
                    Cl[(size_t)(r+8)*256+cb+1] = __float2bfloat16_rn(v3-__bfloat162float(h3));
                }
            } else {
                if (r < M)     *reinterpret_cast<float2*>(&Cf[(size_t)r*256 + cb])     = make_float2(v0, v1);
                if (r + 8 < M) *reinterpret_cast<float2*>(&Cf[(size_t)(r+8)*256 + cb]) = make_float2(v2, v3);
            }
        }
    }
}

// ---------------- LSTM gates on tensor cores ----------------
// gates[128, 1024] = [xin | h] @ [Wih | Whh]^T, fully reduced. grid = 8 (BN=128).
// buffer: Ah 8K | Al 8K | Bh 8K | Bl 8K = 32K; double (64K dynamic).
#define LBUF 32768
__global__ void __launch_bounds__(256, 1) lstm_gates_tc(
    const float* __restrict__ A0, int K0,            // xin, row stride K0
    const float* __restrict__ A1,                     // h, row stride 256
    const __nv_bfloat16* __restrict__ B0h, const __nv_bfloat16* __restrict__ B0l, // Wih split [j][K0]
    const __nv_bfloat16* __restrict__ B1h, const __nv_bfloat16* __restrict__ B1l, // Whh split [j][256]
    float* __restrict__ gates)
{
    extern __shared__ char smem[];
    const int tid = threadIdx.x, lane = tid & 31, wid = tid >> 5;
    const int j0 = blockIdx.x * 128;
    const int mw = (wid >> 1) * 32;    // 4 m groups
    const int nw = (wid & 1) * 64;     // 2 n groups
    const uint32_t sbase = smem_u32(smem);
    const int nch0 = K0 >> 5;
    const int nch  = nch0 + 8;

    float acc[2][8][4];
#pragma unroll
    for (int i=0;i<2;i++)
#pragma unroll
        for (int j=0;j<8;j++)
#pragma unroll
            for (int f=0;f<4;f++) acc[i][j][f]=0.f;

    float4 ra[4];
    const int sr  = tid >> 1;
    const int skh = (tid & 1) * 16;

    auto ldA = [&](int c){
        const float* ap;
        if (c < nch0) ap = A0 + (size_t)sr*K0 + c*32 + skh;
        else          ap = A1 + (size_t)sr*256 + (c-nch0)*32 + skh;
#pragma unroll
        for (int i=0;i<4;i++) ra[i] = *reinterpret_cast<const float4*>(ap + i*4);
    };
    auto stA = [&](int buf){
        char* base = smem + buf*LBUF;
        int c0 = (tid & 1) * 2;
        uint4 h0,l0,h1,l1;
        split8(ra[0], ra[1], h0, l0);
        split8(ra[2], ra[3], h1, l1);
        *reinterpret_cast<uint4*>(base +        sw_off(sr, c0  )) = h0;
        *reinterpret_cast<uint4*>(base +        sw_off(sr, c0+1)) = h1;
        *reinterpret_cast<uint4*>(base + 8192 + sw_off(sr, c0  )) = l0;
        *reinterpret_cast<uint4*>(base + 8192 + sw_off(sr, c0+1)) = l1;
    };
    auto cpB = [&](int c, int buf){
        uint32_t base = sbase + buf*LBUF;
        const __nv_bfloat16 *bh, *bl; int ld, k0;
        if (c < nch0){ bh=B0h; bl=B0l; ld=K0; k0=c*32; }
        else         { bh=B1h; bl=B1l; ld=256; k0=(c-nch0)*32; }
#pragma unroll
        for (int t = 0; t < 2; t++){
            int idx = tid + t*256;          // 0..511
            int r = idx >> 2, kc = idx & 3;
            uint32_t d = base + 16384 + sw_off(r, kc);
            cpa16(d,       bh + (size_t)(j0+r)*ld + k0 + kc*8);
            cpa16(d + 8192, bl + (size_t)(j0+r)*ld + k0 + kc*8);
        }
    };
    auto compute = [&](int buf){
        uint32_t aB = sbase + buf*LBUF;
        const int lr = (lane & 7) + ((lane >> 3) & 1) * 8;
        const int lk = lane >> 4;
#pragma unroll
        for (int s = 0; s < 2; s++){
            int kc = s*2 + lk;
            uint32_t ah[2][4], al[2][4];
#pragma unroll
            for (int f = 0; f < 2; f++){
                uint32_t ad = aB + sw_off(mw + f*16 + lr, kc);
                ldsm4(ah[f], ad);
                ldsm4(al[f], ad + 8192);
            }
            uint32_t bh[4][4], bl[4][4];
#pragma unroll
            for (int g = 0; g < 4; g++){
                uint32_t ad = aB + 16384 + sw_off(nw + g*16 + lr, kc);
                ldsm4(bh[g], ad);
                ldsm4(bl[g], ad + 8192);
            }
#pragma unroll
            for (int f = 0; f < 2; f++)
#pragma unroll
                for (int g = 0; g < 4; g++)
#pragma unroll
                    for (int t = 0; t < 2; t++){
                        float* d = acc[f][g*2+t];
                        mma16816(d, al[f], bh[g][t], bh[g][2+t]);
                        mma16816(d, ah[f], bl[g][t], bl[g][2+t]);
                        mma16816(d, ah[f], bh[g][t], bh[g][2+t]);
                    }
        }
    };

    ldA(0); cpB(0, 0); cpa_commit(); stA(0);
    cpa_wait0(); __syncthreads();
#pragma unroll 1
    for (int it = 0; it < nch; it++){
        int buf = it & 1, nbuf = buf ^ 1;
        if (it + 1 < nch){ ldA(it+1); cpB(it+1, nbuf); cpa_commit(); }
        compute(buf);
        __syncthreads();
        if (it + 1 < nch){ stA(nbuf); cpa_wait0(); __syncthreads(); }
    }

#pragma unroll
    for (int f = 0; f < 2; f++){
        int b = mw + f*16 + (lane >> 2);
#pragma unroll
        for (int j = 0; j < 8; j++){
            int cb = j0 + nw + (j>>1)*16 + (j&1)*8 + (lane & 3)*2;
            *reinterpret_cast<float2*>(&gates[(size_t)b*GJ + cb])
                = make_float2(acc[f][j][0], acc[f][j][1]);
            *reinterpret_cast<float2*>(&gates[(size_t)(b+8)*GJ + cb])
                = make_float2(acc[f][j][2], acc[f][j][3]);
        }
    }
}

// cell: gates fully reduced -> activations
__global__ void lstm_cell3(const float* __restrict__ gates,
                           const float* __restrict__ bih, const float* __restrict__ bhh,
                           float* __restrict__ h, float* __restrict__ c)
{
    int idx = blockIdx.x * blockDim.x + threadIdx.x;  // GB*GH
    int b = idx >> 8, k = idx & 255;
    const float* g = gates + (size_t)b*GJ;
    float gi = g[k]        + bih[k]        + bhh[k];
    float gf = g[GH  + k]  + bih[GH  + k]  + bhh[GH  + k];
    float gg = g[2*GH + k] + bih[2*GH + k] + bhh[2*GH + k];
    float go = g[3*GH + k] + bih[3*GH + k] + bhh[3*GH + k];
    float si = 1.f/(1.f+expf(-gi));
    float sf = 1.f/(1.f+expf(-gf));
    float so = 1.f/(1.f+expf(-go));
    float cn = sf*c[idx] + si*tanhf(gg);
    c[idx] = cn;
    h[idx] = so * tanhf(cn);
}

__global__ void init_state(){
    int idx = blockIdx.x*blockDim.x + threadIdx.x;
    if (idx < 3*GB*GH){ g_h[idx]=0.f; g_c[idx]=0.f; }
    if (idx < GB*2*GH) g_qstar[idx]=0.f;
}

// ---------------- fused single-pass attention ----------------
// grid (GB, 8): chunk of segment b; running-max softmax accumulation in one hfeat pass.
__global__ void __launch_bounds__(256) attn_fused(const float* __restrict__ q,
                                                  const int* __restrict__ bi)
{
    const int b = blockIdx.x, ch = blockIdx.y;
    const int tid = threadIdx.x, lane = tid & 31, wid = tid >> 5;
    __shared__ float sq[256];
    __shared__ float se[32], spe[32];
    __shared__ float s_m, s_s, s_scale;

    int lo = 0, hi = GN;
    while (lo < hi){ int mid=(lo+hi)>>1; if (bi[mid] <  b) lo=mid+1; else hi=mid; }
    int start = lo; hi = GN;
    while (lo < hi){ int mid=(lo+hi)>>1; if (bi[mid] <= b) lo=mid+1; else hi=mid; }
    int end = lo;
    int len = end - start;
    int per = (len + 7) >> 3;
    int s = start + ch*per;
    int t = min(end, s + per);

    sq[tid] = q[(size_t)b*256 + tid];
    if (tid == 0){ s_m = -INFINITY; s_s = 0.f; s_scale = 1.f; }
    float racc = 0.f;
    __syncthreads();

    for (int n0 = s; n0 < t; n0 += 32){
        int nrows = min(32, t - n0);
        // phase A: dot products, warp wid -> rows wid*4..+3
#pragma unroll
        for (int i = 0; i < 4; i++){
            int rr = wid*4 + i;
            float sd = 0.f;
            if (rr < nrows){
                const float4* hp = reinterpret_cast<const float4*>(g_hfeat + (size_t)(n0+rr)*256);
                const float4* qp = reinterpret_cast<const float4*>(sq);
                float4 a = hp[lane*2],   w = qp[lane*2];
                sd += a.x*w.x + a.y*w.y + a.z*w.z + a.w*w.w;
                a = hp[lane*2+1]; w = qp[lane*2+1];
                sd += a.x*w.x + a.y*w.y + a.z*w.z + a.w*w.w;
            }
#pragma unroll
            for (int off=16; off>0; off>>=1) sd += __shfl_xor_sync(0xffffffffu, sd, off);
            if (lane == 0) se[rr] = (rr < nrows) ? sd : -INFINITY;
        }
        __syncthreads();
        // phase B (warp 0): running max update, exp
        if (wid == 0){
            float e = se[lane];
            float mt = e;
#pragma unroll
            for (int off=16; off>0; off>>=1) mt = fmaxf(mt, __shfl_xor_sync(0xffffffffu, mt, off));
            float m_old = s_m;
            float m_new = fmaxf(m_old, mt);
            float pe = expf(e - m_new);            // e=-inf -> 0
            float ps = pe;
#pragma unroll
            for (int off=16; off>0; off>>=1) ps += __shfl_xor_sync(0xffffffffu, ps, off);
            if (lane == 0){
                float sc = (m_old == -INFINITY) ? 0.f : expf(m_old - m_new);
                s_scale = sc;
                s_s = s_s*sc + ps;
                s_m = m_new;
            }
            spe[lane] = pe;
        }
        __syncthreads();
        float sc = s_scale;
        racc *= sc;
        const float* col = g_hfeat + (size_t)n0*256 + tid;
        for (int i = 0; i < nrows; i++)
            racc = fmaf(spe[i], col[(size_t)i*256], racc);
        __syncthreads();
    }
    int ci = b*8 + ch;
    if (tid == 0){ g_am[ci] = s_m; g_as[ci] = s_s; }
    g_ar[(size_t)ci*256 + tid] = racc;
}

// combine chunks -> q_star (both halves)
__global__ void attn_comb(const float* __restrict__ h2)
{
    int b = blockIdx.x, tid = threadIdx.x;
    __shared__ float sm[8], ss[8];
    if (tid < 8){ sm[tid] = g_am[b*8+tid]; ss[tid] = g_as[b*8+tid]; }
    __syncthreads();
    float mg = -INFINITY;
#pragma unroll
    for (int c=0;c<8;c++) mg = fmaxf(mg, sm[c]);
    if (!isfinite(mg)) mg = 0.f;
    float denom = 0.f, w[8];
#pragma unroll
    for (int c=0;c<8;c++){
        float wc = expf(sm[c] - mg);   // sm=-inf -> 0
        w[c] = wc;
        denom += ss[c]*wc;
    }
    float r = 0.f;
#pragma unroll
    for (int c=0;c<8;c++) r += g_ar[(size_t)(b*8+c)*256 + tid] * w[c];
    r /= (denom + 1e-16f);
    g_qstar[(size_t)b*512 + tid]       = h2[(size_t)b*256 + tid];
    g_qstar[(size_t)b*512 + 256 + tid] = r;
}

// out[b,e] = q_star[b,:] @ out_W[:,e] + out_b[e]
__global__ void out_gemm(const float* __restrict__ W, const float* __restrict__ bias,
                         float* __restrict__ out)
{
    int b = blockIdx.x, e = threadIdx.x;
    const float* qs = g_qstar + (size_t)b*(2*GH);
    float acc = bias[e];
    for (int k = 0; k < 2*GH; k++) acc = fmaf(qs[k], W[(size_t)k*GE + e], acc);
    out[(size_t)b*GE + e] = acc;
}

// ---------------- launch ----------------
extern "C" void kernel_launch(void* const* d_in, const int* in_sizes, int n_in,
                              void* d_out, int out_size)
{
    const float* x    = (const float*)d_in[0];
    const int*   bi   = (const int*)  d_in[1];
    const float* W1   = (const float*)d_in[2];
    const float* b1   = (const float*)d_in[3];
    const float* W2   = (const float*)d_in[4];
    const float* b2   = (const float*)d_in[5];
    const float* Wih[3] = {(const float*)d_in[6],  (const float*)d_in[10], (const float*)d_in[14]};
    const float* Whh[3] = {(const float*)d_in[7],  (const float*)d_in[11], (const float*)d_in[15]};
    const float* bih[3] = {(const float*)d_in[8],  (const float*)d_in[12], (const float*)d_in[16]};
    const float* bhh[3] = {(const float*)d_in[9],  (const float*)d_in[13], (const float*)d_in[17]};
    const float* outW = (const float*)d_in[18];
    const float* outb = (const float*)d_in[19];

    float *hfeat, *gates, *h, *c, *qstar;
    __nv_bfloat16 *t1h, *t1l, *wt1h, *wt1l, *wt2h, *wt2l, *wihh, *wihl, *whhh, *whhl;
    cudaGetSymbolAddress((void**)&hfeat, g_hfeat);
    cudaGetSymbolAddress((void**)&gates, g_gates);
    cudaGetSymbolAddress((void**)&h,     g_h);
    cudaGetSymbolAddress((void**)&c,     g_c);
    cudaGetSymbolAddress((void**)&qstar, g_qstar);
    cudaGetSymbolAddress((void**)&t1h,   g_t1h);
    cudaGetSymbolAddress((void**)&t1l,   g_t1l);
    cudaGetSymbolAddress((void**)&wt1h,  g_wt1h);
    cudaGetSymbolAddress((void**)&wt1l,  g_wt1l);
    cudaGetSymbolAddress((void**)&wt2h,  g_wt2h);
    cudaGetSymbolAddress((void**)&wt2l,  g_wt2l);
    cudaGetSymbolAddress((void**)&wihh,  g_wihh);
    cudaGetSymbolAddress((void**)&wihl,  g_wihl);
    cudaGetSymbolAddress((void**)&whhh,  g_whhh);
    cudaGetSymbolAddress((void**)&whhl,  g_whhl);

    cudaFuncSetAttribute(gemm_big<false,true,true>,  cudaFuncAttributeMaxDynamicSharedMemorySize, 2*FBUF);
    cudaFuncSetAttribute(gemm_big<true,false,false>, cudaFuncAttributeMaxDynamicSharedMemorySize, 2*FBUF);
    cudaFuncSetAttribute(lstm_gates_tc, cudaFuncAttributeMaxDynamicSharedMemorySize, 2*LBUF);

    // weight prep (cheap, once per call)
    wt_prep<<<dim3(8,8), dim3(32,8)>>>(W1, wt1h, wt1l);
    wt_prep<<<dim3(8,8), dim3(32,8)>>>(W2, wt2h, wt2l);
    const int ihOff[3] = {0, 1024*512, 1024*512 + 1024*256};
    const int ihSz[3]  = {1024*512, 1024*256, 1024*256};
    for (int l = 0; l < 3; l++){
        wsplit<<<(ihSz[l]+255)/256, 256>>>(Wih[l], wihh + ihOff[l], wihl + ihOff[l], ihSz[l]);
        wsplit<<<(1024*256+255)/256, 256>>>(Whh[l], whhh + l*1024*256, whhl + l*1024*256, 1024*256);
    }

    int nblk = (GN + 127) / 128;
    gemm_big<false,true,true><<<nblk, 256, 2*FBUF>>>(
        x, nullptr, nullptr, wt1h, wt1l, b1, nullptr, t1h, t1l, GN);
    gemm_big<true,false,false><<<nblk, 256, 2*FBUF>>>(
        nullptr, t1h, t1l, wt2h, wt2l, b2, hfeat, nullptr, nullptr, GN);
    init_state<<<(3*GB*GH + 255)/256, 256>>>();

    for (int step = 0; step < NSTEPS; step++){
        const float* lin = qstar; int Kx = 2*GH;
        for (int l = 0; l < 3; l++){
            lstm_gates_tc<<<8, 256, 2*LBUF>>>(
                lin, Kx, h + l*GB*GH,
                wihh + ihOff[l], wihl + ihOff[l],
                whhh + l*1024*256, whhl + l*1024*256, gates);
            lstm_cell3<<<GB, GH>>>(gates, bih[l], bhh[l], h + l*GB*GH, c + l*GB*GH);
            lin = h + l*GB*GH; Kx = GH;
        }
        attn_fused<<<dim3(GB, 8), 256>>>(h + 2*GB*GH, bi);
        attn_comb<<<GB, 256>>>(h + 2*GB*GH);
    }
    out_gemm<<<GB, GE>>>(outW, outb, (float*)d_out);
}

// round 10
// speedup vs baseline: 3.1495x; 1.2880x over previous
#include <cuda_runtime.h>
#include <cuda_bf16.h>
#include <math.h>
#include <stdint.h>

#define GN 100000
#define GD 256
#define GH 256
#define GB 128
#define GE 128
#define NSTEPS 5
#define GJ (4*GH)     // 1024 gate width

// ---------------- scratch (device globals; no allocations) ----------------
__device__ __nv_bfloat16 g_t1h[(size_t)GN*GH], g_t1l[(size_t)GN*GH];  // split ELU output
__device__ float g_hfeat[(size_t)GN*GH];  // node features (fp32)
__device__ float g_h[3*GB*GH];
__device__ float g_c[3*GB*GH];
__device__ float g_qstar[GB*2*GH];
__device__ float g_gpart[3*GB*GJ];        // LSTM gate partials (<=3 K-splits)
// FNN weight transposed hi/lo splits ([n][k] k-major)
__device__ __nv_bfloat16 g_wt1h[GD*GH], g_wt1l[GD*GH];
__device__ __nv_bfloat16 g_wt2h[GH*GH], g_wt2l[GH*GH];
// LSTM weight hi/lo splits ([j][k]); Wih packed l0@0 (1024x512), l1, l2
__device__ __nv_bfloat16 g_wihh[1024*1024], g_wihl[1024*1024];
__device__ __nv_bfloat16 g_whhh[3*1024*256], g_whhl[3*1024*256];
// attention chunk partials
__device__ float g_am[GB*8], g_as[GB*8], g_ar[(size_t)GB*8*256];

// ---------------- mma/ldmatrix/cp.async helpers (family-wide only) ----------------
__device__ __forceinline__ uint32_t smem_u32(const void* p){
    uint32_t a;
    asm("{ .reg .u64 t; cvta.to.shared.u64 t, %1; cvt.u32.u64 %0, t; }" : "=r"(a) : "l"(p));
    return a;
}
__device__ __forceinline__ void ldsm4(uint32_t r[4], uint32_t addr){
    asm volatile("ldmatrix.sync.aligned.m8n8.x4.shared.b16 {%0,%1,%2,%3}, [%4];"
        : "=r"(r[0]), "=r"(r[1]), "=r"(r[2]), "=r"(r[3]) : "r"(addr));
}
__device__ __forceinline__ void mma16816(float d[4], const uint32_t a[4], uint32_t b0, uint32_t b1){
    asm volatile("mma.sync.aligned.m16n8k16.row.col.f32.bf16.bf16.f32 "
        "{%0,%1,%2,%3},{%4,%5,%6,%7},{%8,%9},{%0,%1,%2,%3};"
        : "+f"(d[0]), "+f"(d[1]), "+f"(d[2]), "+f"(d[3])
        : "r"(a[0]), "r"(a[1]), "r"(a[2]), "r"(a[3]), "r"(b0), "r"(b1));
}
__device__ __forceinline__ void cpa16(uint32_t dst, const void* src){
    asm volatile("cp.async.cg.shared.global [%0], [%1], 16;" :: "r"(dst), "l"(src));
}
__device__ __forceinline__ void cpa_commit(){ asm volatile("cp.async.commit_group;"); }
__device__ __forceinline__ void cpa_wait0(){ asm volatile("cp.async.wait_group 0;" ::: "memory"); }

__device__ __forceinline__ uint32_t sw_off(int r, int kc){
    return (uint32_t)(r*64 + ((kc ^ ((r>>1)&3))*16));
}
__device__ __forceinline__ void split8(float4 a, float4 b, uint4& hi, uint4& lo){
    float v[8] = {a.x,a.y,a.z,a.w,b.x,b.y,b.z,b.w};
    unsigned short hs[8], ls[8];
#pragma unroll
    for (int i=0;i<8;i++){
        __nv_bfloat16 h = __float2bfloat16_rn(v[i]);
        hs[i] = __bfloat16_as_ushort(h);
        float r = v[i] - __bfloat162float(h);
        ls[i] = __bfloat16_as_ushort(__float2bfloat16_rn(r));
    }
    hi.x = hs[0] | ((uint32_t)hs[1]<<16); hi.y = hs[2] | ((uint32_t)hs[3]<<16);
    hi.z = hs[4] | ((uint32_t)hs[5]<<16); hi.w = hs[6] | ((uint32_t)hs[7]<<16);
    lo.x = ls[0] | ((uint32_t)ls[1]<<16); lo.y = ls[2] | ((uint32_t)ls[3]<<16);
    lo.z = ls[4] | ((uint32_t)ls[5]<<16); lo.w = ls[6] | ((uint32_t)ls[7]<<16);
}

// ---------------- weight prep ----------------
__global__ void wt_prep(const float* __restrict__ W,
                        __nv_bfloat16* __restrict__ Th, __nv_bfloat16* __restrict__ Tl)
{
    __shared__ float tile[32][33];
    int n0 = blockIdx.x*32, k0 = blockIdx.y*32;
    int tx = threadIdx.x, ty = threadIdx.y;   // block (32,8)
#pragma unroll
    for (int i=0;i<32;i+=8)
        tile[ty+i][tx] = W[(size_t)(k0+ty+i)*256 + n0+tx];
    __syncthreads();
#pragma unroll
    for (int i=0;i<32;i+=8){
        int n = n0 + ty + i, k = k0 + tx;
        float v = tile[tx][ty+i];
        __nv_bfloat16 h = __float2bfloat16_rn(v);
        Th[(size_t)n*256 + k] = h;
        Tl[(size_t)n*256 + k] = __float2bfloat16_rn(v - __bfloat162float(h));
    }
}
// batched elementwise split for the 6 LSTM weight matrices (one launch)
struct WsplitArgs {
    const float* src[6];
    __nv_bfloat16 *hi[6], *lo[6];
    int sz[6];
};
__global__ void wsplit6(WsplitArgs a)
{
    int y = blockIdx.y;
    int i = blockIdx.x*blockDim.x + threadIdx.x;
    if (i >= a.sz[y]) return;
    float v = a.src[y][i];
    __nv_bfloat16 h = __float2bfloat16_rn(v);
    a.hi[y][i] = h;
    a.lo[y][i] = __float2bfloat16_rn(v - __bfloat162float(h));
}

// ---------------- FNN GEMM: BM=128, BN=128, BK=32, cp.async staging ----------------
// buffer: Ah 8K | Al 8K | Bh 8K | Bl 8K = 32K; double buffered (64K dynamic)
#define FBUF 32768
template<bool ASPLIT, bool OSPLIT, bool ELU>
__global__ void __launch_bounds__(256, 1) gemm_f(
    const float* __restrict__ Af,
    const __nv_bfloat16* __restrict__ Ah_g, const __nv_bfloat16* __restrict__ Al_g,
    const __nv_bfloat16* __restrict__ Bh, const __nv_bfloat16* __restrict__ Bl,
    const float* __restrict__ bias,
    float* __restrict__ Cf, __nv_bfloat16* __restrict__ Ch, __nv_bfloat16* __restrict__ Cl,
    int M)
{
    extern __shared__ char smem[];
    const int tid = threadIdx.x, lane = tid & 31, wid = tid >> 5;
    const int row0 = blockIdx.y * 128;
    const int col0 = blockIdx.x * 128;
    const int mw = (wid >> 1) * 32;   // 4 m groups of 32
    const int nw = (wid & 1) * 64;    // 2 n groups of 64
    const uint32_t sbase = smem_u32(smem);

    float acc[2][8][4];
#pragma unroll
    for (int i=0;i<2;i++)
#pragma unroll
        for (int j=0;j<8;j++)
#pragma unroll
            for (int f=0;f<4;f++) acc[i][j][f]=0.f;

    float4 ra[4];
    const int sr  = tid >> 1;
    const int skh = (tid & 1) * 16;

    auto cpB = [&](int it, int buf){
        uint32_t base = sbase + buf*FBUF;
        int k0 = it*32;
#pragma unroll
        for (int t = 0; t < 2; t++){
            int idx = tid + t*256;          // 0..511
            int r = idx >> 2, kc = idx & 3;
            uint32_t d = base + 16384 + sw_off(r, kc);
            cpa16(d,        Bh + (size_t)(col0+r)*256 + k0 + kc*8);
            cpa16(d + 8192, Bl + (size_t)(col0+r)*256 + k0 + kc*8);
        }
    };
    auto cpA = [&](int it, int buf){
        uint32_t base = sbase + buf*FBUF;
        int k0 = it*32;
#pragma unroll
        for (int t = 0; t < 2; t++){
            int idx = tid + t*256;
            int r = idx >> 2, kc = idx & 3;
            uint32_t d = base + sw_off(r, kc);
            if (row0 + r < M){
                cpa16(d,        Ah_g + (size_t)(row0+r)*256 + k0 + kc*8);
                cpa16(d + 8192, Al_g + (size_t)(row0+r)*256 + k0 + kc*8);
            } else {
                uint4 z = make_uint4(0,0,0,0);
                *reinterpret_cast<uint4*>(smem + buf*FBUF + sw_off(r,kc)) = z;
                *reinterpret_cast<uint4*>(smem + buf*FBUF + 8192 + sw_off(r,kc)) = z;
            }
        }
    };
    auto ldA = [&](int it){
        int k0 = it*32;
        bool ok = (row0 + sr) < M;
        const float* ap = Af + (size_t)(row0+sr)*256 + k0 + skh;
#pragma unroll
        for (int i=0;i<4;i++)
            ra[i] = ok ? *reinterpret_cast<const float4*>(ap + i*4)
                       : make_float4(0.f,0.f,0.f,0.f);
    };
    auto stA = [&](int buf){
        char* base = smem + buf*FBUF;
        int c0 = (tid & 1) * 2;
        uint4 h0,l0,h1,l1;
        split8(ra[0], ra[1], h0, l0);
        split8(ra[2], ra[3], h1, l1);
        *reinterpret_cast<uint4*>(base +        sw_off(sr, c0  )) = h0;
        *reinterpret_cast<uint4*>(base +        sw_off(sr, c0+1)) = h1;
        *reinterpret_cast<uint4*>(base + 8192 + sw_off(sr, c0  )) = l0;
        *reinterpret_cast<uint4*>(base + 8192 + sw_off(sr, c0+1)) = l1;
    };
    auto compute = [&](int buf){
        uint32_t aB = sbase + buf*FBUF;
        const int lr = (lane & 7) + ((lane >> 3) & 1) * 8;
        const int lk = lane >> 4;
#pragma unroll
        for (int s = 0; s < 2; s++){
            int kc = s*2 + lk;
            uint32_t ah[2][4], al[2][4];
#pragma unroll
            for (int f = 0; f < 2; f++){
                uint32_t ad = aB + sw_off(mw + f*16 + lr, kc);
                ldsm4(ah[f], ad);
                ldsm4(al[f], ad + 8192);
            }
            uint32_t bh[4][4], bl[4][4];
#pragma unroll
            for (int g = 0; g < 4; g++){
                uint32_t ad = aB + 16384 + sw_off(nw + g*16 + lr, kc);
                ldsm4(bh[g], ad);
                ldsm4(bl[g], ad + 8192);
            }
#pragma unroll
            for (int f = 0; f < 2; f++)
#pragma unroll
                for (int g = 0; g < 4; g++)
#pragma unroll
                    for (int t = 0; t < 2; t++){
                        float* d = acc[f][g*2+t];
                        mma16816(d, al[f], bh[g][t], bh[g][2+t]);
                        mma16816(d, ah[f], bl[g][t], bl[g][2+t]);
                        mma16816(d, ah[f], bh[g][t], bh[g][2+t]);
                    }
        }
    };

    // prologue
    if (ASPLIT){ cpA(0,0); } else { ldA(0); }
    cpB(0,0); cpa_commit();
    if (!ASPLIT) stA(0);
    cpa_wait0(); __syncthreads();

#pragma unroll 1
    for (int it = 0; it < 8; it++){
        int buf = it & 1, nbuf = buf ^ 1;
        if (it + 1 < 8){
            if (ASPLIT){ cpA(it+1, nbuf); } else { ldA(it+1); }
            cpB(it+1, nbuf); cpa_commit();
        }
        compute(buf);
        __syncthreads();
        if (it + 1 < 8){
            if (!ASPLIT) stA(nbuf);
            cpa_wait0(); __syncthreads();
        }
    }

    // epilogue
#pragma unroll
    for (int f = 0; f < 2; f++){
        int r = row0 + mw + f*16 + (lane >> 2);
#pragma unroll
        for (int j = 0; j < 8; j++){
            int cb = col0 + nw + (j>>1)*16 + (j&1)*8 + (lane & 3)*2;
            float b0 = bias[cb], b1 = bias[cb+1];
            float v0 = acc[f][j][0] + b0, v1 = acc[f][j][1] + b1;
            float v2 = acc[f][j][2] + b0, v3 = acc[f][j][3] + b1;
            if (ELU){
                v0 = v0 > 0.f ? v0 : expm1f(v0);
                v1 = v1 > 0.f ? v1 : expm1f(v1);
                v2 = v2 > 0.f ? v2 : expm1f(v2);
                v3 = v3 > 0.f ? v3 : expm1f(v3);
            }
            if (OSPLIT){
                if (r < M){
                    __nv_bfloat16 h0=__float2bfloat16_rn(v0), h1=__float2bfloat16_rn(v1);
                    Ch[(size_t)r*256+cb]   = h0;  Ch[(size_t)r*256+cb+1] = h1;
                    Cl[(size_t)r*256+cb]   = __float2bfloat16_rn(v0-__bfloat162float(h0));
                    Cl[(size_t)r*256+cb+1] = __float2bfloat16_rn(v1-__bfloat162float(h1));
                }
                if (r + 8 < M){
                    __nv_bfloat16 h2=__float2bfloat16_rn(v2), h3=__float2bfloat16_rn(v3);
                    Ch[(size_t)(r+8)*256+cb]   = h2;  Ch[(size_t)(r+8)*256+cb+1] = h3;
                    Cl[(size_t)(r+8)*256+cb]   = __float2bfloat16_rn(v2-__bfloat162float(h2));
                    Cl[(size_t)(r+8)*256+cb+1] = __float2bfloat16_rn(v3-__bfloat162float(h3));
                }
            } else {
                if (r < M)     *reinterpret_cast<float2*>(&Cf[(size_t)r*256 + cb])     = make_float2(v0, v1);
                if (r + 8 < M) *reinterpret_cast<float2*>(&Cf[(size_t)(r+8)*256 + cb]) = make_float2(v2, v3);
            }
        }
    }
}

// ---------------- LSTM gates: tensor cores, j-split x K-split ----------------
// grid (8, ksplit): block = 128 j-cols x 8 K-chunks(32) partial GEMM over [xin|h].
#define LBUF 32768
__global__ void __launch_bounds__(256, 1) lstm_gates_tc(
    const float* __restrict__ A0, int K0,            // xin, row stride K0
    const float* __restrict__ A1,                     // h, row stride 256
    const __nv_bfloat16* __restrict__ B0h, const __nv_bfloat16* __restrict__ B0l,
    const __nv_bfloat16* __restrict__ B1h, const __nv_bfloat16* __restrict__ B1l,
    float* __restrict__ gpart)
{
    extern __shared__ char smem[];
    const int tid = threadIdx.x, lane = tid & 31, wid = tid >> 5;
    const int j0 = blockIdx.x * 128;
    const int part = blockIdx.y;
    const int kbase = part * 8;                       // global chunk offset
    const int mw = (wid >> 1) * 32;
    const int nw = (wid & 1) * 64;
    const uint32_t sbase = smem_u32(smem);
    const int nch0 = K0 >> 5;

    float acc[2][8][4];
#pragma unroll
    for (int i=0;i<2;i++)
#pragma unroll
        for (int j=0;j<8;j++)
#pragma unroll
            for (int f=0;f<4;f++) acc[i][j][f]=0.f;

    float4 ra[4];
    const int sr  = tid >> 1;
    const int skh = (tid & 1) * 16;

    auto ldA = [&](int c){
        int cg = kbase + c;
        const float* ap;
        if (cg < nch0) ap = A0 + (size_t)sr*K0 + cg*32 + skh;
        else           ap = A1 + (size_t)sr*256 + (cg-nch0)*32 + skh;
#pragma unroll
        for (int i=0;i<4;i++) ra[i] = *reinterpret_cast<const float4*>(ap + i*4);
    };
    auto stA = [&](int buf){
        char* base = smem + buf*LBUF;
        int c0 = (tid & 1) * 2;
        uint4 h0,l0,h1,l1;
        split8(ra[0], ra[1], h0, l0);
        split8(ra[2], ra[3], h1, l1);
        *reinterpret_cast<uint4*>(base +        sw_off(sr, c0  )) = h0;
        *reinterpret_cast<uint4*>(base +        sw_off(sr, c0+1)) = h1;
        *reinterpret_cast<uint4*>(base + 8192 + sw_off(sr, c0  )) = l0;
        *reinterpret_cast<uint4*>(base + 8192 + sw_off(sr, c0+1)) = l1;
    };
    auto cpB = [&](int c, int buf){
        uint32_t base = sbase + buf*LBUF;
        int cg = kbase + c;
        const __nv_bfloat16 *bh, *bl; int ld, k0;
        if (cg < nch0){ bh=B0h; bl=B0l; ld=K0; k0=cg*32; }
        else          { bh=B1h; bl=B1l; ld=256; k0=(cg-nch0)*32; }
#pragma unroll
        for (int t = 0; t < 2; t++){
            int idx = tid + t*256;
            int r = idx >> 2, kc = idx & 3;
            uint32_t d = base + 16384 + sw_off(r, kc);
            cpa16(d,        bh + (size_t)(j0+r)*ld + k0 + kc*8);
            cpa16(d + 8192, bl + (size_t)(j0+r)*ld + k0 + kc*8);
        }
    };
    auto compute = [&](int buf){
        uint32_t aB = sbase + buf*LBUF;
        const int lr = (lane & 7) + ((lane >> 3) & 1) * 8;
        const int lk = lane >> 4;
#pragma unroll
        for (int s = 0; s < 2; s++){
            int kc = s*2 + lk;
            uint32_t ah[2][4], al[2][4];
#pragma unroll
            for (int f = 0; f < 2; f++){
                uint32_t ad = aB + sw_off(mw + f*16 + lr, kc);
                ldsm4(ah[f], ad);
                ldsm4(al[f], ad + 8192);
            }
            uint32_t bh[4][4], bl[4][4];
#pragma unroll
            for (int g = 0; g < 4; g++){
                uint32_t ad = aB + 16384 + sw_off(nw + g*16 + lr, kc);
                ldsm4(bh[g], ad);
                ldsm4(bl[g], ad + 8192);
            }
#pragma unroll
            for (int f = 0; f < 2; f++)
#pragma unroll
                for (int g = 0; g < 4; g++)
#pragma unroll
                    for (int t = 0; t < 2; t++){
                        float* d = acc[f][g*2+t];
                        mma16816(d, al[f], bh[g][t], bh[g][2+t]);
                        mma16816(d, ah[f], bl[g][t], bl[g][2+t]);
                        mma16816(d, ah[f], bh[g][t], bh[g][2+t]);
                    }
        }
    };

    ldA(0); cpB(0, 0); cpa_commit(); stA(0);
    cpa_wait0(); __syncthreads();
#pragma unroll 1
    for (int it = 0; it < 8; it++){
        int buf = it & 1, nbuf = buf ^ 1;
        if (it + 1 < 8){ ldA(it+1); cpB(it+1, nbuf); cpa_commit(); }
        compute(buf);
        __syncthreads();
        if (it + 1 < 8){ stA(nbuf); cpa_wait0(); __syncthreads(); }
    }

    float* gp = gpart + (size_t)part*GB*GJ;
#pragma unroll
    for (int f = 0; f < 2; f++){
        int b = mw + f*16 + (lane >> 2);
#pragma unroll
        for (int j = 0; j < 8; j++){
            int cb = j0 + nw + (j>>1)*16 + (j&1)*8 + (lane & 3)*2;
            *reinterpret_cast<float2*>(&gp[(size_t)b*GJ + cb])
                = make_float2(acc[f][j][0], acc[f][j][1]);
            *reinterpret_cast<float2*>(&gp[(size_t)(b+8)*GJ + cb])
                = make_float2(acc[f][j][2], acc[f][j][3]);
        }
    }
}

// cell: reduce ksplit partials + biases + activation
__global__ void lstm_cell4(const float* __restrict__ gpart, int ksplit,
                           const float* __restrict__ bih, const float* __restrict__ bhh,
                           float* __restrict__ h, float* __restrict__ c)
{
    int idx = blockIdx.x * blockDim.x + threadIdx.x;  // GB*GH
    int b = idx >> 8, k = idx & 255;
    float gi = bih[k]        + bhh[k];
    float gf = bih[GH  + k]  + bhh[GH  + k];
    float gg = bih[2*GH + k] + bhh[2*GH + k];
    float go = bih[3*GH + k] + bhh[3*GH + k];
    for (int p = 0; p < ksplit; p++){
        const float* gp = gpart + (size_t)p*GB*GJ + (size_t)b*GJ;
        gi += gp[k];
        gf += gp[GH  + k];
        gg += gp[2*GH + k];
        go += gp[3*GH + k];
    }
    float si = 1.f/(1.f+expf(-gi));
    float sf = 1.f/(1.f+expf(-gf));
    float so = 1.f/(1.f+expf(-go));
    float cn = sf*c[idx] + si*tanhf(gg);
    c[idx] = cn;
    h[idx] = so * tanhf(cn);
}

__global__ void init_state(){
    int idx = blockIdx.x*blockDim.x + threadIdx.x;
    if (idx < 3*GB*GH){ g_h[idx]=0.f; g_c[idx]=0.f; }
    if (idx < GB*2*GH) g_qstar[idx]=0.f;
}

// ---------------- fused single-pass attention ----------------
__global__ void __launch_bounds__(256) attn_fused(const float* __restrict__ q,
                                                  const int* __restrict__ bi)
{
    const int b = blockIdx.x, ch = blockIdx.y;
    const int tid = threadIdx.x, lane = tid & 31, wid = tid >> 5;
    __shared__ float sq[256];
    __shared__ float se[32], spe[32];
    __shared__ float s_m, s_s, s_scale;

    int lo = 0, hi = GN;
    while (lo < hi){ int mid=(lo+hi)>>1; if (bi[mid] <  b) lo=mid+1; else hi=mid; }
    int start = lo; hi = GN;
    while (lo < hi){ int mid=(lo+hi)>>1; if (bi[mid] <= b) lo=mid+1; else hi=mid; }
    int end = lo;
    int len = end - start;
    int per = (len + 7) >> 3;
    int s = start + ch*per;
    int t = min(end, s + per);

    sq[tid] = q[(size_t)b*256 + tid];
    if (tid == 0){ s_m = -INFINITY; s_s = 0.f; s_scale = 1.f; }
    float racc = 0.f;
    __syncthreads();

    for (int n0 = s; n0 < t; n0 += 32){
        int nrows = min(32, t - n0);
#pragma unroll
        for (int i = 0; i < 4; i++){
            int rr = wid*4 + i;
            float sd = 0.f;
            if (rr < nrows){
                const float4* hp = reinterpret_cast<const float4*>(g_hfeat + (size_t)(n0+rr)*256);
                const float4* qp = reinterpret_cast<const float4*>(sq);
                float4 a = hp[lane*2],   w = qp[lane*2];
                sd += a.x*w.x + a.y*w.y + a.z*w.z + a.w*w.w;
                a = hp[lane*2+1]; w = qp[lane*2+1];
                sd += a.x*w.x + a.y*w.y + a.z*w.z + a.w*w.w;
            }
#pragma unroll
            for (int off=16; off>0; off>>=1) sd += __shfl_xor_sync(0xffffffffu, sd, off);
            if (lane == 0) se[rr] = (rr < nrows) ? sd : -INFINITY;
        }
        __syncthreads();
        if (wid == 0){
            float e = se[lane];
            float mt = e;
#pragma unroll
            for (int off=16; off>0; off>>=1) mt = fmaxf(mt, __shfl_xor_sync(0xffffffffu, mt, off));
            float m_old = s_m;
            float m_new = fmaxf(m_old, mt);
            float pe = expf(e - m_new);
            float ps = pe;
#pragma unroll
            for (int off=16; off>0; off>>=1) ps += __shfl_xor_sync(0xffffffffu, ps, off);
            if (lane == 0){
                float sc = (m_old == -INFINITY) ? 0.f : expf(m_old - m_new);
                s_scale = sc;
                s_s = s_s*sc + ps;
                s_m = m_new;
            }
            spe[lane] = pe;
        }
        __syncthreads();
        float sc = s_scale;
        racc *= sc;
        const float* col = g_hfeat + (size_t)n0*256 + tid;
        for (int i = 0; i < nrows; i++)
            racc = fmaf(spe[i], col[(size_t)i*256], racc);
        __syncthreads();
    }
    int ci = b*8 + ch;
    if (tid == 0){ g_am[ci] = s_m; g_as[ci] = s_s; }
    g_ar[(size_t)ci*256 + tid] = racc;
}

__global__ void attn_comb(const float* __restrict__ h2)
{
    int b = blockIdx.x, tid = threadIdx.x;
    __shared__ float sm[8], ss[8];
    if (tid < 8){ sm[tid] = g_am[b*8+tid]; ss[tid] = g_as[b*8+tid]; }
    __syncthreads();
    float mg = -INFINITY;
#pragma unroll
    for (int c=0;c<8;c++) mg = fmaxf(mg, sm[c]);
    if (!isfinite(mg)) mg = 0.f;
    float denom = 0.f, w[8];
#pragma unroll
    for (int c=0;c<8;c++){
        float wc = expf(sm[c] - mg);
        w[c] = wc;
        denom += ss[c]*wc;
    }
    float r = 0.f;
#pragma unroll
    for (int c=0;c<8;c++) r += g_ar[(size_t)(b*8+c)*256 + tid] * w[c];
    r /= (denom + 1e-16f);
    g_qstar[(size_t)b*512 + tid]       = h2[(size_t)b*256 + tid];
    g_qstar[(size_t)b*512 + 256 + tid] = r;
}

__global__ void out_gemm(const float* __restrict__ W, const float* __restrict__ bias,
                         float* __restrict__ out)
{
    int b = blockIdx.x, e = threadIdx.x;
    const float* qs = g_qstar + (size_t)b*(2*GH);
    float acc = bias[e];
    for (int k = 0; k < 2*GH; k++) acc = fmaf(qs[k], W[(size_t)k*GE + e], acc);
    out[(size_t)b*GE + e] = acc;
}

// ---------------- launch ----------------
extern "C" void kernel_launch(void* const* d_in, const int* in_sizes, int n_in,
                              void* d_out, int out_size)
{
    const float* x    = (const float*)d_in[0];
    const int*   bi   = (const int*)  d_in[1];
    const float* W1   = (const float*)d_in[2];
    const float* b1   = (const float*)d_in[3];
    const float* W2   = (const float*)d_in[4];
    const float* b2   = (const float*)d_in[5];
    const float* Wih[3] = {(const float*)d_in[6],  (const float*)d_in[10], (const float*)d_in[14]};
    const float* Whh[3] = {(const float*)d_in[7],  (const float*)d_in[11], (const float*)d_in[15]};
    const float* bih[3] = {(const float*)d_in[8],  (const float*)d_in[12], (const float*)d_in[16]};
    const float* bhh[3] = {(const float*)d_in[9],  (const float*)d_in[13], (const float*)d_in[17]};
    const float* outW = (const float*)d_in[18];
    const float* outb = (const float*)d_in[19];

    float *hfeat, *gpart, *h, *c, *qstar;
    __nv_bfloat16 *t1h, *t1l, *wt1h, *wt1l, *wt2h, *wt2l, *wihh, *wihl, *whhh, *whhl;
    cudaGetSymbolAddress((void**)&hfeat, g_hfeat);
    cudaGetSymbolAddress((void**)&gpart, g_gpart);
    cudaGetSymbolAddress((void**)&h,     g_h);
    cudaGetSymbolAddress((void**)&c,     g_c);
    cudaGetSymbolAddress((void**)&qstar, g_qstar);
    cudaGetSymbolAddress((void**)&t1h,   g_t1h);
    cudaGetSymbolAddress((void**)&t1l,   g_t1l);
    cudaGetSymbolAddress((void**)&wt1h,  g_wt1h);
    cudaGetSymbolAddress((void**)&wt1l,  g_wt1l);
    cudaGetSymbolAddress((void**)&wt2h,  g_wt2h);
    cudaGetSymbolAddress((void**)&wt2l,  g_wt2l);
    cudaGetSymbolAddress((void**)&wihh,  g_wihh);
    cudaGetSymbolAddress((void**)&wihl,  g_wihl);
    cudaGetSymbolAddress((void**)&whhh,  g_whhh);
    cudaGetSymbolAddress((void**)&whhl,  g_whhl);

    cudaFuncSetAttribute(gemm_f<false,true,true>,  cudaFuncAttributeMaxDynamicSharedMemorySize, 2*FBUF);
    cudaFuncSetAttribute(gemm_f<true,false,false>, cudaFuncAttributeMaxDynamicSharedMemorySize, 2*FBUF);
    cudaFuncSetAttribute(lstm_gates_tc, cudaFuncAttributeMaxDynamicSharedMemorySize, 2*LBUF);

    // weight prep
    wt_prep<<<dim3(8,8), dim3(32,8)>>>(W1, wt1h, wt1l);
    wt_prep<<<dim3(8,8), dim3(32,8)>>>(W2, wt2h, wt2l);
    const int ihOff[3] = {0, 1024*512, 1024*512 + 1024*256};
    const int ihSz[3]  = {1024*512, 1024*256, 1024*256};
    {
        WsplitArgs wa;
        for (int l = 0; l < 3; l++){
            wa.src[l] = Wih[l]; wa.hi[l] = wihh + ihOff[l]; wa.lo[l] = wihl + ihOff[l]; wa.sz[l] = ihSz[l];
            wa.src[3+l] = Whh[l]; wa.hi[3+l] = whhh + l*1024*256; wa.lo[3+l] = whhl + l*1024*256; wa.sz[3+l] = 1024*256;
        }
        wsplit6<<<dim3(2048, 6), 256>>>(wa);
    }

    dim3 gg(2, (GN + 127) / 128);
    gemm_f<false,true,true><<<gg, 256, 2*FBUF>>>(
        x, nullptr, nullptr, wt1h, wt1l, b1, nullptr, t1h, t1l, GN);
    gemm_f<true,false,false><<<gg, 256, 2*FBUF>>>(
        nullptr, t1h, t1l, wt2h, wt2l, b2, hfeat, nullptr, nullptr, GN);
    init_state<<<(3*GB*GH + 255)/256, 256>>>();

    for (int step = 0; step < NSTEPS; step++){
        const float* lin = qstar; int Kx = 2*GH;
        for (int l = 0; l < 3; l++){
            int ksplit = (Kx + GH) / 256;   // 3 for layer 0, 2 for layers 1,2
            lstm_gates_tc<<<dim3(8, ksplit), 256, 2*LBUF>>>(
                lin, Kx, h + l*GB*GH,
                wihh + ihOff[l], wihl + ihOff[l],
                whhh + l*1024*256, whhl + l*1024*256, gpart);
            lstm_cell4<<<GB, GH>>>(gpart, ksplit, bih[l], bhh[l], h + l*GB*GH, c + l*GB*GH);
            lin = h + l*GB*GH; Kx = GH;
        }
        attn_fused<<<dim3(GB, 8), 256>>>(h + 2*GB*GH, bi);
        attn_comb<<<GB, 256>>>(h + 2*GB*GH);
    }
    out_gemm<<<GB, GE>>>(outW, outb, (float*)d_out);
}

// round 12
// speedup vs baseline: 3.1723x; 1.0072x over previous
#include <cuda_runtime.h>
#include <cuda_bf16.h>
#include <math.h>
#include <stdint.h>

#define GN 100000
#define GD 256
#define GH 256
#define GB 128
#define GE 128
#define NSTEPS 5
#define GJ (4*GH)     // 1024 gate width

// ---------------- scratch (device globals; no allocations) ----------------
__device__ __nv_bfloat16 g_xh[(size_t)GN*GD], g_xl[(size_t)GN*GD];    // split input x
__device__ __nv_bfloat16 g_t1h[(size_t)GN*GH], g_t1l[(size_t)GN*GH];  // split ELU output
__device__ float g_hfeat[(size_t)GN*GH];  // node features (fp32)
__device__ float g_h[3*GB*GH];
__device__ float g_c[3*GB*GH];
__device__ float g_qstar[GB*2*GH];
__device__ float g_gpart[3*GB*GJ];        // LSTM gate partials (<=3 K-splits)
// FNN weight transposed hi/lo splits ([n][k] k-major)
__device__ __nv_bfloat16 g_wt1h[GD*GH], g_wt1l[GD*GH];
__device__ __nv_bfloat16 g_wt2h[GH*GH], g_wt2l[GH*GH];
// LSTM weight hi/lo splits ([j][k]); Wih packed l0@0 (1024x512), l1, l2
__device__ __nv_bfloat16 g_wihh[1024*1024], g_wihl[1024*1024];
__device__ __nv_bfloat16 g_whhh[3*1024*256], g_whhl[3*1024*256];
// attention chunk partials
__device__ float g_am[GB*8], g_as[GB*8], g_ar[(size_t)GB*8*256];

// ---------------- mma/ldmatrix/cp.async helpers (family-wide only) ----------------
__device__ __forceinline__ uint32_t smem_u32(const void* p){
    uint32_t a;
    asm("{ .reg .u64 t; cvta.to.shared.u64 t, %1; cvt.u32.u64 %0, t; }" : "=r"(a) : "l"(p));
    return a;
}
__device__ __forceinline__ void ldsm4(uint32_t r[4], uint32_t addr){
    asm volatile("ldmatrix.sync.aligned.m8n8.x4.shared.b16 {%0,%1,%2,%3}, [%4];"
        : "=r"(r[0]), "=r"(r[1]), "=r"(r[2]), "=r"(r[3]) : "r"(addr));
}
__device__ __forceinline__ void mma16816(float d[4], const uint32_t a[4], uint32_t b0, uint32_t b1){
    asm volatile("mma.sync.aligned.m16n8k16.row.col.f32.bf16.bf16.f32 "
        "{%0,%1,%2,%3},{%4,%5,%6,%7},{%8,%9},{%0,%1,%2,%3};"
        : "+f"(d[0]), "+f"(d[1]), "+f"(d[2]), "+f"(d[3])
        : "r"(a[0]), "r"(a[1]), "r"(a[2]), "r"(a[3]), "r"(b0), "r"(b1));
}
__device__ __forceinline__ void cpa16(uint32_t dst, const void* src){
    asm volatile("cp.async.cg.shared.global [%0], [%1], 16;" :: "r"(dst), "l"(src));
}
__device__ __forceinline__ void cpa_commit(){ asm volatile("cp.async.commit_group;"); }
__device__ __forceinline__ void cpa_wait0(){ asm volatile("cp.async.wait_group 0;" ::: "memory"); }

__device__ __forceinline__ uint32_t sw_off(int r, int kc){
    return (uint32_t)(r*64 + ((kc ^ ((r>>1)&3))*16));
}
__device__ __forceinline__ void split8(float4 a, float4 b, uint4& hi, uint4& lo){
    float v[8] = {a.x,a.y,a.z,a.w,b.x,b.y,b.z,b.w};
    unsigned short hs[8], ls[8];
#pragma unroll
    for (int i=0;i<8;i++){
        __nv_bfloat16 h = __float2bfloat16_rn(v[i]);
        hs[i] = __bfloat16_as_ushort(h);
        float r = v[i] - __bfloat162float(h);
        ls[i] = __bfloat16_as_ushort(__float2bfloat16_rn(r));
    }
    hi.x = hs[0] | ((uint32_t)hs[1]<<16); hi.y = hs[2] | ((uint32_t)hs[3]<<16);
    hi.z = hs[4] | ((uint32_t)hs[5]<<16); hi.w = hs[6] | ((uint32_t)hs[7]<<16);
    lo.x = ls[0] | ((uint32_t)ls[1]<<16); lo.y = ls[2] | ((uint32_t)ls[3]<<16);
    lo.z = ls[4] | ((uint32_t)ls[5]<<16); lo.w = ls[6] | ((uint32_t)ls[7]<<16);
}

// ---------------- weight/input prep ----------------
__global__ void wt_prep(const float* __restrict__ W,
                        __nv_bfloat16* __restrict__ Th, __nv_bfloat16* __restrict__ Tl)
{
    __shared__ float tile[32][33];
    int n0 = blockIdx.x*32, k0 = blockIdx.y*32;
    int tx = threadIdx.x, ty = threadIdx.y;   // block (32,8)
#pragma unroll
    for (int i=0;i<32;i+=8)
        tile[ty+i][tx] = W[(size_t)(k0+ty+i)*256 + n0+tx];
    __syncthreads();
#pragma unroll
    for (int i=0;i<32;i+=8){
        int n = n0 + ty + i, k = k0 + tx;
        float v = tile[tx][ty+i];
        __nv_bfloat16 h = __float2bfloat16_rn(v);
        Th[(size_t)n*256 + k] = h;
        Tl[(size_t)n*256 + k] = __float2bfloat16_rn(v - __bfloat162float(h));
    }
}
struct WsplitArgs {
    const float* src[6];
    __nv_bfloat16 *hi[6], *lo[6];
    int sz[6];
};
__global__ void wsplit6(WsplitArgs a)
{
    int y = blockIdx.y;
    int i = blockIdx.x*blockDim.x + threadIdx.x;
    if (i >= a.sz[y]) return;
    float v = a.src[y][i];
    __nv_bfloat16 h = __float2bfloat16_rn(v);
    a.hi[y][i] = h;
    a.lo[y][i] = __float2bfloat16_rn(v - __bfloat162float(h));
}
// split x: 8 floats per thread
__global__ void xsplit(const float* __restrict__ src,
                       __nv_bfloat16* __restrict__ hi, __nv_bfloat16* __restrict__ lo)
{
    size_t i = (size_t)(blockIdx.x)*blockDim.x + threadIdx.x;   // chunk of 8
    if (i >= ((size_t)GN*GD)/8) return;
    const float4* s = reinterpret_cast<const float4*>(src) + i*2;
    uint4 h, l;
    split8(s[0], s[1], h, l);
    reinterpret_cast<uint4*>(hi)[i] = h;
    reinterpret_cast<uint4*>(lo)[i] = l;
}

// ---------------- FNN GEMM: BM=128, BN=128, BK=32, pure cp.async, 1 sync/iter ----------------
// buffer: Ah 8K | Al 8K | Bh 8K | Bl 8K = 32K; double buffered (64K dynamic)
#define FBUF 32768
template<bool OSPLIT, bool ELU>
__global__ void __launch_bounds__(256, 1) gemm_a(
    const __nv_bfloat16* __restrict__ Ah_g, const __nv_bfloat16* __restrict__ Al_g,
    const __nv_bfloat16* __restrict__ Bh, const __nv_bfloat16* __restrict__ Bl,
    const float* __restrict__ bias,
    float* __restrict__ Cf, __nv_bfloat16* __restrict__ Ch, __nv_bfloat16* __restrict__ Cl,
    int M)
{
    extern __shared__ char smem[];
    const int tid = threadIdx.x, lane = tid & 31, wid = tid >> 5;
    const int row0 = blockIdx.y * 128;
    const int col0 = blockIdx.x * 128;
    const int mw = (wid >> 1) * 32;   // 4 m groups of 32
    const int nw = (wid & 1) * 64;    // 2 n groups of 64
    const uint32_t sbase = smem_u32(smem);

    float acc[2][8][4];
#pragma unroll
    for (int i=0;i<2;i++)
#pragma unroll
        for (int j=0;j<8;j++)
#pragma unroll
            for (int f=0;f<4;f++) acc[i][j][f]=0.f;

    auto cpAB = [&](int it, int buf){
        uint32_t base = sbase + buf*FBUF;
        int k0 = it*32;
#pragma unroll
        for (int t = 0; t < 2; t++){
            int idx = tid + t*256;          // 0..511
            int r = idx >> 2, kc = idx & 3;
            uint32_t dA = base + sw_off(r, kc);
            if (row0 + r < M){
                cpa16(dA,        Ah_g + (size_t)(row0+r)*256 + k0 + kc*8);
                cpa16(dA + 8192, Al_g + (size_t)(row0+r)*256 + k0 + kc*8);
            } else {
                uint4 z = make_uint4(0,0,0,0);
                *reinterpret_cast<uint4*>(smem + buf*FBUF + sw_off(r,kc)) = z;
                *reinterpret_cast<uint4*>(smem + buf*FBUF + 8192 + sw_off(r,kc)) = z;
            }
            uint32_t dB = base + 16384 + sw_off(r, kc);
            cpa16(dB,        Bh + (size_t)(col0+r)*256 + k0 + kc*8);
            cpa16(dB + 8192, Bl + (size_t)(col0+r)*256 + k0 + kc*8);
        }
    };
    auto compute = [&](int buf){
        uint32_t aB = sbase + buf*FBUF;
        const int lr = (lane & 7) + ((lane >> 3) & 1) * 8;
        const int lk = lane >> 4;
#pragma unroll
        for (int s = 0; s < 2; s++){
            int kc = s*2 + lk;
            uint32_t ah[2][4], al[2][4];
#pragma unroll
            for (int f = 0; f < 2; f++){
                uint32_t ad = aB + sw_off(mw + f*16 + lr, kc);
                ldsm4(ah[f], ad);
                ldsm4(al[f], ad + 8192);
            }
            uint32_t bh[4][4], bl[4][4];
#pragma unroll
            for (int g = 0; g < 4; g++){
                uint32_t ad = aB + 16384 + sw_off(nw + g*16 + lr, kc);
                ldsm4(bh[g], ad);
                ldsm4(bl[g], ad + 8192);
            }
#pragma unroll
            for (int f = 0; f < 2; f++)
#pragma unroll
                for (int g = 0; g < 4; g++)
#pragma unroll
                    for (int t = 0; t < 2; t++){
                        float* d = acc[f][g*2+t];
                        mma16816(d, al[f], bh[g][t], bh[g][2+t]);
                        mma16816(d, ah[f], bl[g][t], bl[g][2+t]);
                        mma16816(d, ah[f], bh[g][t], bh[g][2+t]);
                    }
        }
    };

    // prologue
    cpAB(0, 0); cpa_commit();
    cpa_wait0(); __syncthreads();

#pragma unroll 1
    for (int it = 0; it < 8; it++){
        int buf = it & 1, nbuf = buf ^ 1;
        if (it + 1 < 8){ cpAB(it+1, nbuf); cpa_commit(); }
        compute(buf);
        if (it + 1 < 8){ cpa_wait0(); __syncthreads(); }
    }

    // epilogue
#pragma unroll
    for (int f = 0; f < 2; f++){
        int r = row0 + mw + f*16 + (lane >> 2);
#pragma unroll
        for (int j = 0; j < 8; j++){
            int cb = col0 + nw + (j>>1)*16 + (j&1)*8 + (lane & 3)*2;
            float b0 = bias[cb], b1 = bias[cb+1];
            float v0 = acc[f][j][0] + b0, v1 = acc[f][j][1] + b1;
            float v2 = acc[f][j][2] + b0, v3 = acc[f][j][3] + b1;
            if (ELU){
                v0 = v0 > 0.f ? v0 : expm1f(v0);
                v1 = v1 > 0.f ? v1 : expm1f(v1);
                v2 = v2 > 0.f ? v2 : expm1f(v2);
                v3 = v3 > 0.f ? v3 : expm1f(v3);
            }
            if (OSPLIT){
                if (r < M){
                    __nv_bfloat16 h0=__float2bfloat16_rn(v0), h1=__float2bfloat16_rn(v1);
                    uint32_t ph = __bfloat16_as_ushort(h0) | ((uint32_t)__bfloat16_as_ushort(h1)<<16);
                    uint32_t pl = __bfloat16_as_ushort(__float2bfloat16_rn(v0-__bfloat162float(h0)))
                               | ((uint32_t)__bfloat16_as_ushort(__float2bfloat16_rn(v1-__bfloat162float(h1)))<<16);
                    *reinterpret_cast<uint32_t*>(&Ch[(size_t)r*256+cb]) = ph;
                    *reinterpret_cast<uint32_t*>(&Cl[(size_t)r*256+cb]) = pl;
                }
                if (r + 8 < M){
                    __nv_bfloat16 h2=__float2bfloat16_rn(v2), h3=__float2bfloat16_rn(v3);
                    uint32_t ph = __bfloat16_as_ushort(h2) | ((uint32_t)__bfloat16_as_ushort(h3)<<16);
                    uint32_t pl = __bfloat16_as_ushort(__float2bfloat16_rn(v2-__bfloat162float(h2)))
                               | ((uint32_t)__bfloat16_as_ushort(__float2bfloat16_rn(v3-__bfloat162float(h3)))<<16);
                    *reinterpret_cast<uint32_t*>(&Ch[(size_t)(r+8)*256+cb]) = ph;
                    *reinterpret_cast<uint32_t*>(&Cl[(size_t)(r+8)*256+cb]) = pl;
                }
            } else {
                if (r < M)     *reinterpret_cast<float2*>(&Cf[(size_t)r*256 + cb])     = make_float2(v0, v1);
                if (r + 8 < M) *reinterpret_cast<float2*>(&Cf[(size_t)(r+8)*256 + cb]) = make_float2(v2, v3);
            }
        }
    }
}

// ---------------- LSTM gates: tensor cores, j-split x K-split, 1 sync/iter ----------------
#define LBUF 32768
__global__ void __launch_bounds__(256, 1) lstm_gates_tc(
    const float* __restrict__ A0, int K0,            // xin, row stride K0
    const float* __restrict__ A1,                     // h, row stride 256
    const __nv_bfloat16* __restrict__ B0h, const __nv_bfloat16* __restrict__ B0l,
    const __nv_bfloat16* __restrict__ B1h, const __nv_bfloat16* __restrict__ B1l,
    float* __restrict__ gpart)
{
    extern __shared__ char smem[];
    const int tid = threadIdx.x, lane = tid & 31, wid = tid >> 5;
    const int j0 = blockIdx.x * 128;
    const int part = blockIdx.y;
    const int kbase = part * 8;
    const int mw = (wid >> 1) * 32;
    const int nw = (wid & 1) * 64;
    const uint32_t sbase = smem_u32(smem);
    const int nch0 = K0 >> 5;

    float acc[2][8][4];
#pragma unroll
    for (int i=0;i<2;i++)
#pragma unroll
        for (int j=0;j<8;j++)
#pragma unroll
            for (int f=0;f<4;f++) acc[i][j][f]=0.f;

    float4 ra[4];
    const int sr  = tid >> 1;
    const int skh = (tid & 1) * 16;

    auto ldA = [&](int c){
        int cg = kbase + c;
        const float* ap;
        if (cg < nch0) ap = A0 + (size_t)sr*K0 + cg*32 + skh;
        else           ap = A1 + (size_t)sr*256 + (cg-nch0)*32 + skh;
#pragma unroll
        for (int i=0;i<4;i++) ra[i] = *reinterpret_cast<const float4*>(ap + i*4);
    };
    auto stA = [&](int buf){
        char* base = smem + buf*LBUF;
        int c0 = (tid & 1) * 2;
        uint4 h0,l0,h1,l1;
        split8(ra[0], ra[1], h0, l0);
        split8(ra[2], ra[3], h1, l1);
        *reinterpret_cast<uint4*>(base +        sw_off(sr, c0  )) = h0;
        *reinterpret_cast<uint4*>(base +        sw_off(sr, c0+1)) = h1;
        *reinterpret_cast<uint4*>(base + 8192 + sw_off(sr, c0  )) = l0;
        *reinterpret_cast<uint4*>(base + 8192 + sw_off(sr, c0+1)) = l1;
    };
    auto cpB = [&](int c, int buf){
        uint32_t base = sbase + buf*LBUF;
        int cg = kbase + c;
        const __nv_bfloat16 *bh, *bl; int ld, k0;
        if (cg < nch0){ bh=B0h; bl=B0l; ld=K0; k0=cg*32; }
        else          { bh=B1h; bl=B1l; ld=256; k0=(cg-nch0)*32; }
#pragma unroll
        for (int t = 0; t < 2; t++){
            int idx = tid + t*256;
            int r = idx >> 2, kc = idx & 3;
            uint32_t d = base + 16384 + sw_off(r, kc);
            cpa16(d,        bh + (size_t)(j0+r)*ld + k0 + kc*8);
            cpa16(d + 8192, bl + (size_t)(j0+r)*ld + k0 + kc*8);
        }
    };
    auto compute = [&](int buf){
        uint32_t aB = sbase + buf*LBUF;
        const int lr = (lane & 7) + ((lane >> 3) & 1) * 8;
        const int lk = lane >> 4;
#pragma unroll
        for (int s = 0; s < 2; s++){
            int kc = s*2 + lk;
            uint32_t ah[2][4], al[2][4];
#pragma unroll
            for (int f = 0; f < 2; f++){
                uint32_t ad = aB + sw_off(mw + f*16 + lr, kc);
                ldsm4(ah[f], ad);
                ldsm4(al[f], ad + 8192);
            }
            uint32_t bh[4][4], bl[4][4];
#pragma unroll
            for (int g = 0; g < 4; g++){
                uint32_t ad = aB + 16384 + sw_off(nw + g*16 + lr, kc);
                ldsm4(bh[g], ad);
                ldsm4(bl[g], ad + 8192);
            }
#pragma unroll
            for (int f = 0; f < 2; f++)
#pragma unroll
                for (int g = 0; g < 4; g++)
#pragma unroll
                    for (int t = 0; t < 2; t++){
                        float* d = acc[f][g*2+t];
                        mma16816(d, al[f], bh[g][t], bh[g][2+t]);
                        mma16816(d, ah[f], bl[g][t], bl[g][2+t]);
                        mma16816(d, ah[f], bh[g][t], bh[g][2+t]);
                    }
        }
    };

    ldA(0); cpB(0, 0); cpa_commit(); stA(0);
    cpa_wait0(); __syncthreads();
#pragma unroll 1
    for (int it = 0; it < 8; it++){
        int buf = it & 1, nbuf = buf ^ 1;
        if (it + 1 < 8){ ldA(it+1); stA(nbuf); cpB(it+1, nbuf); cpa_commit(); }
        compute(buf);
        if (it + 1 < 8){ cpa_wait0(); __syncthreads(); }
    }

    float* gp = gpart + (size_t)part*GB*GJ;
#pragma unroll
    for (int f = 0; f < 2; f++){
        int b = mw + f*16 + (lane >> 2);
#pragma unroll
        for (int j = 0; j < 8; j++){
            int cb = j0 + nw + (j>>1)*16 + (j&1)*8 + (lane & 3)*2;
            *reinterpret_cast<float2*>(&gp[(size_t)b*GJ + cb])
                = make_float2(acc[f][j][0], acc[f][j][1]);
            *reinterpret_cast<float2*>(&gp[(size_t)(b+8)*GJ + cb])
                = make_float2(acc[f][j][2], acc[f][j][3]);
        }
    }
}

// cell: reduce ksplit partials + biases + activation
__global__ void lstm_cell4(const float* __restrict__ gpart, int ksplit,
                           const float* __restrict__ bih, const float* __restrict__ bhh,
                           float* __restrict__ h, float* __restrict__ c)
{
    int idx = blockIdx.x * blockDim.x + threadIdx.x;  // GB*GH
    int b = idx >> 8, k = idx & 255;
    float gi = bih[k]        + bhh[k];
    float gf = bih[GH  + k]  + bhh[GH  + k];
    float gg = bih[2*GH + k] + bhh[2*GH + k];
    float go = bih[3*GH + k] + bhh[3*GH + k];
    for (int p = 0; p < ksplit; p++){
        const float* gp = gpart + (size_t)p*GB*GJ + (size_t)b*GJ;
        gi += gp[k];
        gf += gp[GH  + k];
        gg += gp[2*GH + k];
        go += gp[3*GH + k];
    }
    float si = 1.f/(1.f+expf(-gi));
    float sf = 1.f/(1.f+expf(-gf));
    float so = 1.f/(1.f+expf(-go));
    float cn = sf*c[idx] + si*tanhf(gg);
    c[idx] = cn;
    h[idx] = so * tanhf(cn);
}

__global__ void init_state(){
    int idx = blockIdx.x*blockDim.x + threadIdx.x;
    if (idx < 3*GB*GH){ g_h[idx]=0.f; g_c[idx]=0.f; }
    if (idx < GB*2*GH) g_qstar[idx]=0.f;
}

// ---------------- fused single-pass attention ----------------
__global__ void __launch_bounds__(256) attn_fused(const float* __restrict__ q,
                                                  const int* __restrict__ bi)
{
    const int b = blockIdx.x, ch = blockIdx.y;
    const int tid = threadIdx.x, lane = tid & 31, wid = tid >> 5;
    __shared__ float sq[256];
    __shared__ float se[32], spe[32];
    __shared__ float s_m, s_s, s_scale;

    int lo = 0, hi = GN;
    while (lo < hi){ int mid=(lo+hi)>>1; if (bi[mid] <  b) lo=mid+1; else hi=mid; }
    int start = lo; hi = GN;
    while (lo < hi){ int mid=(lo+hi)>>1; if (bi[mid] <= b) lo=mid+1; else hi=mid; }
    int end = lo;
    int len = end - start;
    int per = (len + 7) >> 3;
    int s = start + ch*per;
    int t = min(end, s + per);

    sq[tid] = q[(size_t)b*256 + tid];
    if (tid == 0){ s_m = -INFINITY; s_s = 0.f; s_scale = 1.f; }
    float racc = 0.f;
    __syncthreads();

    for (int n0 = s; n0 < t; n0 += 32){
        int nrows = min(32, t - n0);
#pragma unroll
        for (int i = 0; i < 4; i++){
            int rr = wid*4 + i;
            float sd = 0.f;
            if (rr < nrows){
                const float4* hp = reinterpret_cast<const float4*>(g_hfeat + (size_t)(n0+rr)*256);
                const float4* qp = reinterpret_cast<const float4*>(sq);
                float4 a = hp[lane*2],   w = qp[lane*2];
                sd += a.x*w.x + a.y*w.y + a.z*w.z + a.w*w.w;
                a = hp[lane*2+1]; w = qp[lane*2+1];
                sd += a.x*w.x + a.y*w.y + a.z*w.z + a.w*w.w;
            }
#pragma unroll
            for (int off=16; off>0; off>>=1) sd += __shfl_xor_sync(0xffffffffu, sd, off);
            if (lane == 0) se[rr] = (rr < nrows) ? sd : -INFINITY;
        }
        __syncthreads();
        if (wid == 0){
            float e = se[lane];
            float mt = e;
#pragma unroll
            for (int off=16; off>0; off>>=1) mt = fmaxf(mt, __shfl_xor_sync(0xffffffffu, mt, off));
            float m_old = s_m;
            float m_new = fmaxf(m_old, mt);
            float pe = expf(e - m_new);
            float ps = pe;
#pragma unroll
            for (int off=16; off>0; off>>=1) ps += __shfl_xor_sync(0xffffffffu, ps, off);
            if (lane == 0){
                float sc = (m_old == -INFINITY) ? 0.f : expf(m_old - m_new);
                s_scale = sc;
                s_s = s_s*sc + ps;
                s_m = m_new;
            }
            spe[lane] = pe;
        }
        __syncthreads();
        float sc = s_scale;
        racc *= sc;
        const float* col = g_hfeat + (size_t)n0*256 + tid;
        for (int i = 0; i < nrows; i++)
            racc = fmaf(spe[i], col[(size_t)i*256], racc);
        __syncthreads();
    }
    int ci = b*8 + ch;
    if (tid == 0){ g_am[ci] = s_m; g_as[ci] = s_s; }
    g_ar[(size_t)ci*256 + tid] = racc;
}

__global__ void attn_comb(const float* __restrict__ h2)
{
    int b = blockIdx.x, tid = threadIdx.x;
    __shared__ float sm[8], ss[8];
    if (tid < 8){ sm[tid] = g_am[b*8+tid]; ss[tid] = g_as[b*8+tid]; }
    __syncthreads();
    float mg = -INFINITY;
#pragma unroll
    for (int c=0;c<8;c++) mg = fmaxf(mg, sm[c]);
    if (!isfinite(mg)) mg = 0.f;
    float denom = 0.f, w[8];
#pragma unroll
    for (int c=0;c<8;c++){
        float wc = expf(sm[c] - mg);
        w[c] = wc;
        denom += ss[c]*wc;
    }
    float r = 0.f;
#pragma unroll
    for (int c=0;c<8;c++) r += g_ar[(size_t)(b*8+c)*256 + tid] * w[c];
    r /= (denom + 1e-16f);
    g_qstar[(size_t)b*512 + tid]       = h2[(size_t)b*256 + tid];
    g_qstar[(size_t)b*512 + 256 + tid] = r;
}

__global__ void out_gemm(const float* __restrict__ W, const float* __restrict__ bias,
                         float* __restrict__ out)
{
    int b = blockIdx.x, e = threadIdx.x;
    const float* qs = g_qstar + (size_t)b*(2*GH);
    float acc = bias[e];
    for (int k = 0; k < 2*GH; k++) acc = fmaf(qs[k], W[(size_t)k*GE + e], acc);
    out[(size_t)b*GE + e] = acc;
}

// ---------------- launch ----------------
extern "C" void kernel_launch(void* const* d_in, const int* in_sizes, int n_in,
                              void* d_out, int out_size)
{
    const float* x    = (const float*)d_in[0];
    const int*   bi   = (const int*)  d_in[1];
    const float* W1   = (const float*)d_in[2];
    const float* b1   = (const float*)d_in[3];
    const float* W2   = (const float*)d_in[4];
    const float* b2   = (const float*)d_in[5];
    const float* Wih[3] = {(const float*)d_in[6],  (const float*)d_in[10], (const float*)d_in[14]};
    const float* Whh[3] = {(const float*)d_in[7],  (const float*)d_in[11], (const float*)d_in[15]};
    const float* bih[3] = {(const float*)d_in[8],  (const float*)d_in[12], (const float*)d_in[16]};
    const float* bhh[3] = {(const float*)d_in[9],  (const float*)d_in[13], (const float*)d_in[17]};
    const float* outW = (const float*)d_in[18];
    const float* outb = (const float*)d_in[19];

    float *hfeat, *gpart, *h, *c, *qstar;
    __nv_bfloat16 *xh, *xl, *t1h, *t1l, *wt1h, *wt1l, *wt2h, *wt2l, *wihh, *wihl, *whhh, *whhl;
    cudaGetSymbolAddress((void**)&hfeat, g_hfeat);
    cudaGetSymbolAddress((void**)&gpart, g_gpart);
    cudaGetSymbolAddress((void**)&h,     g_h);
    cudaGetSymbolAddress((void**)&c,     g_c);
    cudaGetSymbolAddress((void**)&qstar, g_qstar);
    cudaGetSymbolAddress((void**)&xh,    g_xh);
    cudaGetSymbolAddress((void**)&xl,    g_xl);
    cudaGetSymbolAddress((void**)&t1h,   g_t1h);
    cudaGetSymbolAddress((void**)&t1l,   g_t1l);
    cudaGetSymbolAddress((void**)&wt1h,  g_wt1h);
    cudaGetSymbolAddress((void**)&wt1l,  g_wt1l);
    cudaGetSymbolAddress((void**)&wt2h,  g_wt2h);
    cudaGetSymbolAddress((void**)&wt2l,  g_wt2l);
    cudaGetSymbolAddress((void**)&wihh,  g_wihh);
    cudaGetSymbolAddress((void**)&wihl,  g_wihl);
    cudaGetSymbolAddress((void**)&whhh,  g_whhh);
    cudaGetSymbolAddress((void**)&whhl,  g_whhl);

    cudaFuncSetAttribute(gemm_a<true,true>,   cudaFuncAttributeMaxDynamicSharedMemorySize, 2*FBUF);
    cudaFuncSetAttribute(gemm_a<false,false>, cudaFuncAttributeMaxDynamicSharedMemorySize, 2*FBUF);
    cudaFuncSetAttribute(lstm_gates_tc, cudaFuncAttributeMaxDynamicSharedMemorySize, 2*LBUF);

    // prep: weights + input split
    wt_prep<<<dim3(8,8), dim3(32,8)>>>(W1, wt1h, wt1l);
    wt_prep<<<dim3(8,8), dim3(32,8)>>>(W2, wt2h, wt2l);
    xsplit<<<(int)(((size_t)GN*GD/8 + 255)/256), 256>>>(x, xh, xl);
    const int ihOff[3] = {0, 1024*512, 1024*512 + 1024*256};
    const int ihSz[3]  = {1024*512, 1024*256, 1024*256};
    {
        WsplitArgs wa;
        for (int l = 0; l < 3; l++){
            wa.src[l] = Wih[l]; wa.hi[l] = wihh + ihOff[l]; wa.lo[l] = wihl + ihOff[l]; wa.sz[l] = ihSz[l];
            wa.src[3+l] = Whh[l]; wa.hi[3+l] = whhh + l*1024*256; wa.lo[3+l] = whhl + l*1024*256; wa.sz[3+l] = 1024*256;
        }
        wsplit6<<<dim3(2048, 6), 256>>>(wa);
    }

    dim3 gg(2, (GN + 127) / 128);
    gemm_a<true,true><<<gg, 256, 2*FBUF>>>(
        xh, xl, wt1h, wt1l, b1, nullptr, t1h, t1l, GN);
    gemm_a<false,false><<<gg, 256, 2*FBUF>>>(
        t1h, t1l, wt2h, wt2l, b2, hfeat, nullptr, nullptr, GN);
    init_state<<<(3*GB*GH + 255)/256, 256>>>();

    for (int step = 0; step < NSTEPS; step++){
        const float* lin = qstar; int Kx = 2*GH;
        for (int l = 0; l < 3; l++){
            int ksplit = (Kx + GH) / 256;   // 3 for layer 0, 2 for layers 1,2
            lstm_gates_tc<<<dim3(8, ksplit), 256, 2*LBUF>>>(
                lin, Kx, h + l*GB*GH,
                wihh + ihOff[l], wihl + ihOff[l],
                whhh + l*1024*256, whhl + l*1024*256, gpart);
            lstm_cell4<<<GB, GH>>>(gpart, ksplit, bih[l], bhh[l], h + l*GB*GH, c + l*GB*GH);
            lin = h + l*GB*GH; Kx = GH;
        }
        attn_fused<<<dim3(GB, 8), 256>>>(h + 2*GB*GH, bi);
        attn_comb<<<GB, 256>>>(h + 2*GB*GH);
    }
    out_gemm<<<GB, GE>>>(outW, outb, (float*)d_out);
}

// round 13
// speedup vs baseline: 3.4673x; 1.0930x over previous
#include <cuda_runtime.h>
#include <cuda_bf16.h>
#include <math.h>
#include <stdint.h>

#define GN 100000
#define GD 256
#define GH 256
#define GB 128
#define GE 128
#define NSTEPS 5
#define GJ (4*GH)     // 1024 gate width

// ---------------- scratch (device globals; no allocations) ----------------
__device__ __nv_bfloat16 g_xh[(size_t)GN*GD], g_xl[(size_t)GN*GD];    // split input x
__device__ __nv_bfloat16 g_t1h[(size_t)GN*GH], g_t1l[(size_t)GN*GH];  // split ELU output
__device__ float g_hfeat[(size_t)GN*GH];  // node features (fp32)
__device__ float g_h[3*GB*GH];
__device__ float g_c[3*GB*GH];
__device__ float g_qstar[GB*2*GH];
__device__ float g_gpart[3*GB*GJ];        // LSTM gate partials (<=3 K-splits)
// FNN weight transposed hi/lo splits ([n][k] k-major)
__device__ __nv_bfloat16 g_wt1h[GD*GH], g_wt1l[GD*GH];
__device__ __nv_bfloat16 g_wt2h[GH*GH], g_wt2l[GH*GH];
// LSTM weight hi/lo splits ([j][k]); Wih packed l0@0 (1024x512), l1, l2
__device__ __nv_bfloat16 g_wihh[1024*1024], g_wihl[1024*1024];
__device__ __nv_bfloat16 g_whhh[3*1024*256], g_whhl[3*1024*256];
// attention chunk partials
__device__ float g_am[GB*8], g_as[GB*8], g_ar[(size_t)GB*8*256];

// ---------------- mma/ldmatrix/cp.async helpers (family-wide only) ----------------
__device__ __forceinline__ uint32_t smem_u32(const void* p){
    uint32_t a;
    asm("{ .reg .u64 t; cvta.to.shared.u64 t, %1; cvt.u32.u64 %0, t; }" : "=r"(a) : "l"(p));
    return a;
}
__device__ __forceinline__ void ldsm4(uint32_t r[4], uint32_t addr){
    asm volatile("ldmatrix.sync.aligned.m8n8.x4.shared.b16 {%0,%1,%2,%3}, [%4];"
        : "=r"(r[0]), "=r"(r[1]), "=r"(r[2]), "=r"(r[3]) : "r"(addr));
}
__device__ __forceinline__ void mma16816(float d[4], const uint32_t a[4], uint32_t b0, uint32_t b1){
    asm volatile("mma.sync.aligned.m16n8k16.row.col.f32.bf16.bf16.f32 "
        "{%0,%1,%2,%3},{%4,%5,%6,%7},{%8,%9},{%0,%1,%2,%3};"
        : "+f"(d[0]), "+f"(d[1]), "+f"(d[2]), "+f"(d[3])
        : "r"(a[0]), "r"(a[1]), "r"(a[2]), "r"(a[3]), "r"(b0), "r"(b1));
}
__device__ __forceinline__ void cpa16(uint32_t dst, const void* src){
    asm volatile("cp.async.cg.shared.global [%0], [%1], 16;" :: "r"(dst), "l"(src));
}
__device__ __forceinline__ void cpa_commit(){ asm volatile("cp.async.commit_group;"); }
__device__ __forceinline__ void cpa_wait0(){ asm volatile("cp.async.wait_group 0;" ::: "memory"); }

__device__ __forceinline__ uint32_t sw_off(int r, int kc){
    return (uint32_t)(r*64 + ((kc ^ ((r>>1)&3))*16));
}
__device__ __forceinline__ void split8(float4 a, float4 b, uint4& hi, uint4& lo){
    float v[8] = {a.x,a.y,a.z,a.w,b.x,b.y,b.z,b.w};
    unsigned short hs[8], ls[8];
#pragma unroll
    for (int i=0;i<8;i++){
        __nv_bfloat16 h = __float2bfloat16_rn(v[i]);
        hs[i] = __bfloat16_as_ushort(h);
        float r = v[i] - __bfloat162float(h);
        ls[i] = __bfloat16_as_ushort(__float2bfloat16_rn(r));
    }
    hi.x = hs[0] | ((uint32_t)hs[1]<<16); hi.y = hs[2] | ((uint32_t)hs[3]<<16);
    hi.z = hs[4] | ((uint32_t)hs[5]<<16); hi.w = hs[6] | ((uint32_t)hs[7]<<16);
    lo.x = ls[0] | ((uint32_t)ls[1]<<16); lo.y = ls[2] | ((uint32_t)ls[3]<<16);
    lo.z = ls[4] | ((uint32_t)ls[5]<<16); lo.w = ls[6] | ((uint32_t)ls[7]<<16);
}

// ---------------- weight/input prep ----------------
__global__ void wt_prep(const float* __restrict__ W,
                        __nv_bfloat16* __restrict__ Th, __nv_bfloat16* __restrict__ Tl)
{
    __shared__ float tile[32][33];
    int n0 = blockIdx.x*32, k0 = blockIdx.y*32;
    int tx = threadIdx.x, ty = threadIdx.y;   // block (32,8)
#pragma unroll
    for (int i=0;i<32;i+=8)
        tile[ty+i][tx] = W[(size_t)(k0+ty+i)*256 + n0+tx];
    __syncthreads();
#pragma unroll
    for (int i=0;i<32;i+=8){
        int n = n0 + ty + i, k = k0 + tx;
        float v = tile[tx][ty+i];
        __nv_bfloat16 h = __float2bfloat16_rn(v);
        Th[(size_t)n*256 + k] = h;
        Tl[(size_t)n*256 + k] = __float2bfloat16_rn(v - __bfloat162float(h));
    }
}
struct WsplitArgs {
    const float* src[6];
    __nv_bfloat16 *hi[6], *lo[6];
    int sz[6];
};
__global__ void wsplit6(WsplitArgs a)
{
    int y = blockIdx.y;
    int i = blockIdx.x*blockDim.x + threadIdx.x;
    if (i >= a.sz[y]) return;
    float v = a.src[y][i];
    __nv_bfloat16 h = __float2bfloat16_rn(v);
    a.hi[y][i] = h;
    a.lo[y][i] = __float2bfloat16_rn(v - __bfloat162float(h));
}
__global__ void xsplit(const float* __restrict__ src,
                       __nv_bfloat16* __restrict__ hi, __nv_bfloat16* __restrict__ lo)
{
    size_t i = (size_t)(blockIdx.x)*blockDim.x + threadIdx.x;   // chunk of 8
    if (i >= ((size_t)GN*GD)/8) return;
    const float4* s = reinterpret_cast<const float4*>(src) + i*2;
    uint4 h, l;
    split8(s[0], s[1], h, l);
    reinterpret_cast<uint4*>(hi)[i] = h;
    reinterpret_cast<uint4*>(lo)[i] = l;
}

// ---------------- FNN GEMM: BM=128, BN=64, BK=32, 2 CTAs/SM ----------------
// buffer: Ah 8K | Al 8K | Bh 4K | Bl 4K = 24K; double buffered (48K dynamic)
#define FBUF 24576
template<bool OSPLIT, bool ELU>
__global__ void __launch_bounds__(256, 2) gemm_a(
    const __nv_bfloat16* __restrict__ Ah_g, const __nv_bfloat16* __restrict__ Al_g,
    const __nv_bfloat16* __restrict__ Bh, const __nv_bfloat16* __restrict__ Bl,
    const float* __restrict__ bias,
    float* __restrict__ Cf, __nv_bfloat16* __restrict__ Ch, __nv_bfloat16* __restrict__ Cl,
    int M)
{
    extern __shared__ char smem[];
    const int tid = threadIdx.x, lane = tid & 31, wid = tid >> 5;
    const int row0 = blockIdx.y * 128;
    const int col0 = blockIdx.x * 64;
    const int mw = (wid >> 1) * 32;   // 4 m groups of 32
    const int nw = (wid & 1) * 32;    // 2 n groups of 32
    const uint32_t sbase = smem_u32(smem);

    float acc[2][4][4];
#pragma unroll
    for (int i=0;i<2;i++)
#pragma unroll
        for (int j=0;j<4;j++)
#pragma unroll
            for (int f=0;f<4;f++) acc[i][j][f]=0.f;

    auto cpAB = [&](int it, int buf){
        uint32_t base = sbase + buf*FBUF;
        int k0 = it*32;
#pragma unroll
        for (int t = 0; t < 2; t++){
            int idx = tid + t*256;          // 0..511: A rows
            int r = idx >> 2, kc = idx & 3;
            uint32_t dA = base + sw_off(r, kc);
            if (row0 + r < M){
                cpa16(dA,        Ah_g + (size_t)(row0+r)*256 + k0 + kc*8);
                cpa16(dA + 8192, Al_g + (size_t)(row0+r)*256 + k0 + kc*8);
            } else {
                uint4 z = make_uint4(0,0,0,0);
                *reinterpret_cast<uint4*>(smem + buf*FBUF + sw_off(r,kc)) = z;
                *reinterpret_cast<uint4*>(smem + buf*FBUF + 8192 + sw_off(r,kc)) = z;
            }
        }
        {
            int r = tid >> 2, kc = tid & 3;     // 64 B rows
            uint32_t dB = base + 16384 + sw_off(r, kc);
            cpa16(dB,        Bh + (size_t)(col0+r)*256 + k0 + kc*8);
            cpa16(dB + 4096, Bl + (size_t)(col0+r)*256 + k0 + kc*8);
        }
    };
    auto compute = [&](int buf){
        uint32_t aB = sbase + buf*FBUF;
        const int lr = (lane & 7) + ((lane >> 3) & 1) * 8;
        const int lk = lane >> 4;
#pragma unroll
        for (int s = 0; s < 2; s++){
            int kc = s*2 + lk;
            uint32_t ah[2][4], al[2][4];
#pragma unroll
            for (int f = 0; f < 2; f++){
                uint32_t ad = aB + sw_off(mw + f*16 + lr, kc);
                ldsm4(ah[f], ad);
                ldsm4(al[f], ad + 8192);
            }
            uint32_t bh[2][4], bl[2][4];
#pragma unroll
            for (int g = 0; g < 2; g++){
                uint32_t ad = aB + 16384 + sw_off(nw + g*16 + lr, kc);
                ldsm4(bh[g], ad);
                ldsm4(bl[g], ad + 4096);
            }
#pragma unroll
            for (int f = 0; f < 2; f++)
#pragma unroll
                for (int g = 0; g < 2; g++)
#pragma unroll
                    for (int t = 0; t < 2; t++){
                        float* d = acc[f][g*2+t];
                        mma16816(d, al[f], bh[g][t], bh[g][2+t]);
                        mma16816(d, ah[f], bl[g][t], bl[g][2+t]);
                        mma16816(d, ah[f], bh[g][t], bh[g][2+t]);
                    }
        }
    };

    cpAB(0, 0); cpa_commit();
    cpa_wait0(); __syncthreads();

#pragma unroll 1
    for (int it = 0; it < 8; it++){
        int buf = it & 1, nbuf = buf ^ 1;
        if (it + 1 < 8){ cpAB(it+1, nbuf); cpa_commit(); }
        compute(buf);
        if (it + 1 < 8){ cpa_wait0(); __syncthreads(); }
    }

    // epilogue
#pragma unroll
    for (int f = 0; f < 2; f++){
        int r = row0 + mw + f*16 + (lane >> 2);
#pragma unroll
        for (int j = 0; j < 4; j++){
            int cb = col0 + nw + (j>>1)*16 + (j&1)*8 + (lane & 3)*2;
            float b0 = bias[cb], b1 = bias[cb+1];
            float v0 = acc[f][j][0] + b0, v1 = acc[f][j][1] + b1;
            float v2 = acc[f][j][2] + b0, v3 = acc[f][j][3] + b1;
            if (ELU){
                v0 = v0 > 0.f ? v0 : expm1f(v0);
                v1 = v1 > 0.f ? v1 : expm1f(v1);
                v2 = v2 > 0.f ? v2 : expm1f(v2);
                v3 = v3 > 0.f ? v3 : expm1f(v3);
            }
            if (OSPLIT){
                if (r < M){
                    __nv_bfloat16 h0=__float2bfloat16_rn(v0), h1=__float2bfloat16_rn(v1);
                    uint32_t ph = __bfloat16_as_ushort(h0) | ((uint32_t)__bfloat16_as_ushort(h1)<<16);
                    uint32_t pl = __bfloat16_as_ushort(__float2bfloat16_rn(v0-__bfloat162float(h0)))
                               | ((uint32_t)__bfloat16_as_ushort(__float2bfloat16_rn(v1-__bfloat162float(h1)))<<16);
                    *reinterpret_cast<uint32_t*>(&Ch[(size_t)r*256+cb]) = ph;
                    *reinterpret_cast<uint32_t*>(&Cl[(size_t)r*256+cb]) = pl;
                }
                if (r + 8 < M){
                    __nv_bfloat16 h2=__float2bfloat16_rn(v2), h3=__float2bfloat16_rn(v3);
                    uint32_t ph = __bfloat16_as_ushort(h2) | ((uint32_t)__bfloat16_as_ushort(h3)<<16);
                    uint32_t pl = __bfloat16_as_ushort(__float2bfloat16_rn(v2-__bfloat162float(h2)))
                               | ((uint32_t)__bfloat16_as_ushort(__float2bfloat16_rn(v3-__bfloat162float(h3)))<<16);
                    *reinterpret_cast<uint32_t*>(&Ch[(size_t)(r+8)*256+cb]) = ph;
                    *reinterpret_cast<uint32_t*>(&Cl[(size_t)(r+8)*256+cb]) = pl;
                }
            } else {
                if (r < M)     *reinterpret_cast<float2*>(&Cf[(size_t)r*256 + cb])     = make_float2(v0, v1);
                if (r + 8 < M) *reinterpret_cast<float2*>(&Cf[(size_t)(r+8)*256 + cb]) = make_float2(v2, v3);
            }
        }
    }
}

// ---------------- LSTM gates: tensor cores, j-split x K-split, 1 sync/iter ----------------
#define LBUF 32768
__global__ void __launch_bounds__(256, 1) lstm_gates_tc(
    const float* __restrict__ A0, int K0,            // xin, row stride K0
    const float* __restrict__ A1,                     // h, row stride 256
    const __nv_bfloat16* __restrict__ B0h, const __nv_bfloat16* __restrict__ B0l,
    const __nv_bfloat16* __restrict__ B1h, const __nv_bfloat16* __restrict__ B1l,
    float* __restrict__ gpart)
{
    extern __shared__ char smem[];
    const int tid = threadIdx.x, lane = tid & 31, wid = tid >> 5;
    const int j0 = blockIdx.x * 128;
    const int part = blockIdx.y;
    const int kbase = part * 8;
    const int mw = (wid >> 1) * 32;
    const int nw = (wid & 1) * 64;
    const uint32_t sbase = smem_u32(smem);
    const int nch0 = K0 >> 5;

    float acc[2][8][4];
#pragma unroll
    for (int i=0;i<2;i++)
#pragma unroll
        for (int j=0;j<8;j++)
#pragma unroll
            for (int f=0;f<4;f++) acc[i][j][f]=0.f;

    float4 ra[4];
    const int sr  = tid >> 1;
    const int skh = (tid & 1) * 16;

    auto ldA = [&](int c){
        int cg = kbase + c;
        const float* ap;
        if (cg < nch0) ap = A0 + (size_t)sr*K0 + cg*32 + skh;
        else           ap = A1 + (size_t)sr*256 + (cg-nch0)*32 + skh;
#pragma unroll
        for (int i=0;i<4;i++) ra[i] = *reinterpret_cast<const float4*>(ap + i*4);
    };
    auto stA = [&](int buf){
        char* base = smem + buf*LBUF;
        int c0 = (tid & 1) * 2;
        uint4 h0,l0,h1,l1;
        split8(ra[0], ra[1], h0, l0);
        split8(ra[2], ra[3], h1, l1);
        *reinterpret_cast<uint4*>(base +        sw_off(sr, c0  )) = h0;
        *reinterpret_cast<uint4*>(base +        sw_off(sr, c0+1)) = h1;
        *reinterpret_cast<uint4*>(base + 8192 + sw_off(sr, c0  )) = l0;
        *reinterpret_cast<uint4*>(base + 8192 + sw_off(sr, c0+1)) = l1;
    };
    auto cpB = [&](int c, int buf){
        uint32_t base = sbase + buf*LBUF;
        int cg = kbase + c;
        const __nv_bfloat16 *bh, *bl; int ld, k0;
        if (cg < nch0){ bh=B0h; bl=B0l; ld=K0; k0=cg*32; }
        else          { bh=B1h; bl=B1l; ld=256; k0=(cg-nch0)*32; }
#pragma unroll
        for (int t = 0; t < 2; t++){
            int idx = tid + t*256;
            int r = idx >> 2, kc = idx & 3;
            uint32_t d = base + 16384 + sw_off(r, kc);
            cpa16(d,        bh + (size_t)(j0+r)*ld + k0 + kc*8);
            cpa16(d + 8192, bl + (size_t)(j0+r)*ld + k0 + kc*8);
        }
    };
    auto compute = [&](int buf){
        uint32_t aB = sbase + buf*LBUF;
        const int lr = (lane & 7) + ((lane >> 3) & 1) * 8;
        const int lk = lane >> 4;
#pragma unroll
        for (int s = 0; s < 2; s++){
            int kc = s*2 + lk;
            uint32_t ah[2][4], al[2][4];
#pragma unroll
            for (int f = 0; f < 2; f++){
                uint32_t ad = aB + sw_off(mw + f*16 + lr, kc);
                ldsm4(ah[f], ad);
                ldsm4(al[f], ad + 8192);
            }
            uint32_t bh[4][4], bl[4][4];
#pragma unroll
            for (int g = 0; g < 4; g++){
                uint32_t ad = aB + 16384 + sw_off(nw + g*16 + lr, kc);
                ldsm4(bh[g], ad);
                ldsm4(bl[g], ad + 8192);
            }
#pragma unroll
            for (int f = 0; f < 2; f++)
#pragma unroll
                for (int g = 0; g < 4; g++)
#pragma unroll
                    for (int t = 0; t < 2; t++){
                        float* d = acc[f][g*2+t];
                        mma16816(d, al[f], bh[g][t], bh[g][2+t]);
                        mma16816(d, ah[f], bl[g][t], bl[g][2+t]);
                        mma16816(d, ah[f], bh[g][t], bh[g][2+t]);
                    }
        }
    };

    ldA(0); cpB(0, 0); cpa_commit(); stA(0);
    cpa_wait0(); __syncthreads();
#pragma unroll 1
    for (int it = 0; it < 8; it++){
        int buf = it & 1, nbuf = buf ^ 1;
        if (it + 1 < 8){ ldA(it+1); stA(nbuf); cpB(it+1, nbuf); cpa_commit(); }
        compute(buf);
        if (it + 1 < 8){ cpa_wait0(); __syncthreads(); }
    }

    float* gp = gpart + (size_t)part*GB*GJ;
#pragma unroll
    for (int f = 0; f < 2; f++){
        int b = mw + f*16 + (lane >> 2);
#pragma unroll
        for (int j = 0; j < 8; j++){
            int cb = j0 + nw + (j>>1)*16 + (j&1)*8 + (lane & 3)*2;
            *reinterpret_cast<float2*>(&gp[(size_t)b*GJ + cb])
                = make_float2(acc[f][j][0], acc[f][j][1]);
            *reinterpret_cast<float2*>(&gp[(size_t)(b+8)*GJ + cb])
                = make_float2(acc[f][j][2], acc[f][j][3]);
        }
    }
}

// cell: reduce ksplit partials + biases + activation
__global__ void lstm_cell4(const float* __restrict__ gpart, int ksplit,
                           const float* __restrict__ bih, const float* __restrict__ bhh,
                           float* __restrict__ h, float* __restrict__ c)
{
    int idx = blockIdx.x * blockDim.x + threadIdx.x;  // GB*GH
    int b = idx >> 8, k = idx & 255;
    float gi = bih[k]        + bhh[k];
    float gf = bih[GH  + k]  + bhh[GH  + k];
    float gg = bih[2*GH + k] + bhh[2*GH + k];
    float go = bih[3*GH + k] + bhh[3*GH + k];
    for (int p = 0; p < ksplit; p++){
        const float* gp = gpart + (size_t)p*GB*GJ + (size_t)b*GJ;
        gi += gp[k];
        gf += gp[GH  + k];
        gg += gp[2*GH + k];
        go += gp[3*GH + k];
    }
    float si = 1.f/(1.f+expf(-gi));
    float sf = 1.f/(1.f+expf(-gf));
    float so = 1.f/(1.f+expf(-go));
    float cn = sf*c[idx] + si*tanhf(gg);
    c[idx] = cn;
    h[idx] = so * tanhf(cn);
}

__global__ void init_state(){
    int idx = blockIdx.x*blockDim.x + threadIdx.x;
    if (idx < 3*GB*GH){ g_h[idx]=0.f; g_c[idx]=0.f; }
    if (idx < GB*2*GH) g_qstar[idx]=0.f;
}

// ---------------- fused single-pass attention ----------------
__global__ void __launch_bounds__(256) attn_fused(const float* __restrict__ q,
                                                  const int* __restrict__ bi)
{
    const int b = blockIdx.x, ch = blockIdx.y;
    const int tid = threadIdx.x, lane = tid & 31, wid = tid >> 5;
    __shared__ float sq[256];
    __shared__ float se[32], spe[32];
    __shared__ float s_m, s_s, s_scale;

    int lo = 0, hi = GN;
    while (lo < hi){ int mid=(lo+hi)>>1; if (bi[mid] <  b) lo=mid+1; else hi=mid; }
    int start = lo; hi = GN;
    while (lo < hi){ int mid=(lo+hi)>>1; if (bi[mid] <= b) lo=mid+1; else hi=mid; }
    int end = lo;
    int len = end - start;
    int per = (len + 7) >> 3;
    int s = start + ch*per;
    int t = min(end, s + per);

    sq[tid] = q[(size_t)b*256 + tid];
    if (tid == 0){ s_m = -INFINITY; s_s = 0.f; s_scale = 1.f; }
    float racc = 0.f;
    __syncthreads();

    for (int n0 = s; n0 < t; n0 += 32){
        int nrows = min(32, t - n0);
#pragma unroll
        for (int i = 0; i < 4; i++){
            int rr = wid*4 + i;
            float sd = 0.f;
            if (rr < nrows){
                const float4* hp = reinterpret_cast<const float4*>(g_hfeat + (size_t)(n0+rr)*256);
                const float4* qp = reinterpret_cast<const float4*>(sq);
                float4 a = hp[lane*2],   w = qp[lane*2];
                sd += a.x*w.x + a.y*w.y + a.z*w.z + a.w*w.w;
                a = hp[lane*2+1]; w = qp[lane*2+1];
                sd += a.x*w.x + a.y*w.y + a.z*w.z + a.w*w.w;
            }
#pragma unroll
            for (int off=16; off>0; off>>=1) sd += __shfl_xor_sync(0xffffffffu, sd, off);
            if (lane == 0) se[rr] = (rr < nrows) ? sd : -INFINITY;
        }
        __syncthreads();
        if (wid == 0){
            float e = se[lane];
            float mt = e;
#pragma unroll
            for (int off=16; off>0; off>>=1) mt = fmaxf(mt, __shfl_xor_sync(0xffffffffu, mt, off));
            float m_old = s_m;
            float m_new = fmaxf(m_old, mt);
            float pe = expf(e - m_new);
            float ps = pe;
#pragma unroll
            for (int off=16; off>0; off>>=1) ps += __shfl_xor_sync(0xffffffffu, ps, off);
            if (lane == 0){
                float sc = (m_old == -INFINITY) ? 0.f : expf(m_old - m_new);
                s_scale = sc;
                s_s = s_s*sc + ps;
                s_m = m_new;
            }
            spe[lane] = pe;
        }
        __syncthreads();
        float sc = s_scale;
        racc *= sc;
        const float* col = g_hfeat + (size_t)n0*256 + tid;
        for (int i = 0; i < nrows; i++)
            racc = fmaf(spe[i], col[(size_t)i*256], racc);
        __syncthreads();
    }
    int ci = b*8 + ch;
    if (tid == 0){ g_am[ci] = s_m; g_as[ci] = s_s; }
    g_ar[(size_t)ci*256 + tid] = racc;
}

__global__ void attn_comb(const float* __restrict__ h2)
{
    int b = blockIdx.x, tid = threadIdx.x;
    __shared__ float sm[8], ss[8];
    if (tid < 8){ sm[tid] = g_am[b*8+tid]; ss[tid] = g_as[b*8+tid]; }
    __syncthreads();
    float mg = -INFINITY;
#pragma unroll
    for (int c=0;c<8;c++) mg = fmaxf(mg, sm[c]);
    if (!isfinite(mg)) mg = 0.f;
    float denom = 0.f, w[8];
#pragma unroll
    for (int c=0;c<8;c++){
        float wc = expf(sm[c] - mg);
        w[c] = wc;
        denom += ss[c]*wc;
    }
    float r = 0.f;
#pragma unroll
    for (int c=0;c<8;c++) r += g_ar[(size_t)(b*8+c)*256 + tid] * w[c];
    r /= (denom + 1e-16f);
    g_qstar[(size_t)b*512 + tid]       = h2[(size_t)b*256 + tid];
    g_qstar[(size_t)b*512 + 256 + tid] = r;
}

__global__ void out_gemm(const float* __restrict__ W, const float* __restrict__ bias,
                         float* __restrict__ out)
{
    int b = blockIdx.x, e = threadIdx.x;
    const float* qs = g_qstar + (size_t)b*(2*GH);
    float acc = bias[e];
    for (int k = 0; k < 2*GH; k++) acc = fmaf(qs[k], W[(size_t)k*GE + e], acc);
    out[(size_t)b*GE + e] = acc;
}

// ---------------- launch ----------------
extern "C" void kernel_launch(void* const* d_in, const int* in_sizes, int n_in,
                              void* d_out, int out_size)
{
    const float* x    = (const float*)d_in[0];
    const int*   bi   = (const int*)  d_in[1];
    const float* W1   = (const float*)d_in[2];
    const float* b1   = (const float*)d_in[3];
    const float* W2   = (const float*)d_in[4];
    const float* b2   = (const float*)d_in[5];
    const float* Wih[3] = {(const float*)d_in[6],  (const float*)d_in[10], (const float*)d_in[14]};
    const float* Whh[3] = {(const float*)d_in[7],  (const float*)d_in[11], (const float*)d_in[15]};
    const float* bih[3] = {(const float*)d_in[8],  (const float*)d_in[12], (const float*)d_in[16]};
    const float* bhh[3] = {(const float*)d_in[9],  (const float*)d_in[13], (const float*)d_in[17]};
    const float* outW = (const float*)d_in[18];
    const float* outb = (const float*)d_in[19];

    float *hfeat, *gpart, *h, *c, *qstar;
    __nv_bfloat16 *xh, *xl, *t1h, *t1l, *wt1h, *wt1l, *wt2h, *wt2l, *wihh, *wihl, *whhh, *whhl;
    cudaGetSymbolAddress((void**)&hfeat, g_hfeat);
    cudaGetSymbolAddress((void**)&gpart, g_gpart);
    cudaGetSymbolAddress((void**)&h,     g_h);
    cudaGetSymbolAddress((void**)&c,     g_c);
    cudaGetSymbolAddress((void**)&qstar, g_qstar);
    cudaGetSymbolAddress((void**)&xh,    g_xh);
    cudaGetSymbolAddress((void**)&xl,    g_xl);
    cudaGetSymbolAddress((void**)&t1h,   g_t1h);
    cudaGetSymbolAddress((void**)&t1l,   g_t1l);
    cudaGetSymbolAddress((void**)&wt1h,  g_wt1h);
    cudaGetSymbolAddress((void**)&wt1l,  g_wt1l);
    cudaGetSymbolAddress((void**)&wt2h,  g_wt2h);
    cudaGetSymbolAddress((void**)&wt2l,  g_wt2l);
    cudaGetSymbolAddress((void**)&wihh,  g_wihh);
    cudaGetSymbolAddress((void**)&wihl,  g_wihl);
    cudaGetSymbolAddress((void**)&whhh,  g_whhh);
    cudaGetSymbolAddress((void**)&whhl,  g_whhl);

    cudaFuncSetAttribute(gemm_a<true,true>,   cudaFuncAttributeMaxDynamicSharedMemorySize, 2*FBUF);
    cudaFuncSetAttribute(gemm_a<false,false>, cudaFuncAttributeMaxDynamicSharedMemorySize, 2*FBUF);
    cudaFuncSetAttribute(lstm_gates_tc, cudaFuncAttributeMaxDynamicSharedMemorySize, 2*LBUF);

    // prep: weights + input split
    wt_prep<<<dim3(8,8), dim3(32,8)>>>(W1, wt1h, wt1l);
    wt_prep<<<dim3(8,8), dim3(32,8)>>>(W2, wt2h, wt2l);
    xsplit<<<(int)(((size_t)GN*GD/8 + 255)/256), 256>>>(x, xh, xl);
    const int ihOff[3] = {0, 1024*512, 1024*512 + 1024*256};
    const int ihSz[3]  = {1024*512, 1024*256, 1024*256};
    {
        WsplitArgs wa;
        for (int l = 0; l < 3; l++){
            wa.src[l] = Wih[l]; wa.hi[l] = wihh + ihOff[l]; wa.lo[l] = wihl + ihOff[l]; wa.sz[l] = ihSz[l];
            wa.src[3+l] = Whh[l]; wa.hi[3+l] = whhh + l*1024*256; wa.lo[3+l] = whhl + l*1024*256; wa.sz[3+l] = 1024*256;
        }
        wsplit6<<<dim3(2048, 6), 256>>>(wa);
    }

    dim3 gg(4, (GN + 127) / 128);
    gemm_a<true,true><<<gg, 256, 2*FBUF>>>(
        xh, xl, wt1h, wt1l, b1, nullptr, t1h, t1l, GN);
    gemm_a<false,false><<<gg, 256, 2*FBUF>>>(
        t1h, t1l, wt2h, wt2l, b2, hfeat, nullptr, nullptr, GN);
    init_state<<<(3*GB*GH + 255)/256, 256>>>();

    for (int step = 0; step < NSTEPS; step++){
        const float* lin = qstar; int Kx = 2*GH;
        for (int l = 0; l < 3; l++){
            int ksplit = (Kx + GH) / 256;   // 3 for layer 0, 2 for layers 1,2
            lstm_gates_tc<<<dim3(8, ksplit), 256, 2*LBUF>>>(
                lin, Kx, h + l*GB*GH,
                wihh + ihOff[l], wihl + ihOff[l],
                whhh + l*1024*256, whhl + l*1024*256, gpart);
            lstm_cell4<<<GB, GH>>>(gpart, ksplit, bih[l], bhh[l], h + l*GB*GH, c + l*GB*GH);
            lin = h + l*GB*GH; Kx = GH;
        }
        attn_fused<<<dim3(GB, 8), 256>>>(h + 2*GB*GH, bi);
        attn_comb<<<GB, 256>>>(h + 2*GB*GH);
    }
    out_gemm<<<GB, GE>>>(outW, outb, (float*)d_out);
}

// round 15
// speedup vs baseline: 4.1376x; 1.1933x over previous
#include <cuda_runtime.h>
#include <cuda_bf16.h>
#include <math.h>
#include <stdint.h>

#define GN 100000
#define GD 256
#define GH 256
#define GB 128
#define GE 128
#define NSTEPS 5
#define GJ (4*GH)     // 1024 gate width
#define NCHMAX 24     // max K chunks of 32 (layer0: 768/32)

// ---------------- scratch (device globals; no allocations) ----------------
__device__ __nv_bfloat16 g_xh[(size_t)GN*GD], g_xl[(size_t)GN*GD];    // split input x
__device__ __nv_bfloat16 g_t1h[(size_t)GN*GH], g_t1l[(size_t)GN*GH];  // split ELU output
__device__ float g_hfeat[(size_t)GN*GH];  // node features (fp32)
__device__ float g_h[3*GB*GH];
__device__ float g_c[3*GB*GH];
__device__ float g_qstar[GB*2*GH];
__device__ float g_gpart[(size_t)NCHMAX*GB*GJ];   // LSTM gate partials
// FNN weight transposed hi/lo splits ([n][k] k-major)
__device__ __nv_bfloat16 g_wt1h[GD*GH], g_wt1l[GD*GH];
__device__ __nv_bfloat16 g_wt2h[GH*GH], g_wt2l[GH*GH];
// LSTM weight hi/lo splits ([j][k]); Wih packed l0@0 (1024x512), l1, l2
__device__ __nv_bfloat16 g_wihh[1024*1024], g_wihl[1024*1024];
__device__ __nv_bfloat16 g_whhh[3*1024*256], g_whhl[3*1024*256];
// attention chunk partials
__device__ float g_am[GB*8], g_as[GB*8], g_ar[(size_t)GB*8*256];

// ---------------- mma/ldmatrix/cp.async helpers (family-wide only) ----------------
__device__ __forceinline__ uint32_t smem_u32(const void* p){
    uint32_t a;
    asm("{ .reg .u64 t; cvta.to.shared.u64 t, %1; cvt.u32.u64 %0, t; }" : "=r"(a) : "l"(p));
    return a;
}
__device__ __forceinline__ void ldsm4(uint32_t r[4], uint32_t addr){
    asm volatile("ldmatrix.sync.aligned.m8n8.x4.shared.b16 {%0,%1,%2,%3}, [%4];"
        : "=r"(r[0]), "=r"(r[1]), "=r"(r[2]), "=r"(r[3]) : "r"(addr));
}
__device__ __forceinline__ void mma16816(float d[4], const uint32_t a[4], uint32_t b0, uint32_t b1){
    asm volatile("mma.sync.aligned.m16n8k16.row.col.f32.bf16.bf16.f32 "
        "{%0,%1,%2,%3},{%4,%5,%6,%7},{%8,%9},{%0,%1,%2,%3};"
        : "+f"(d[0]), "+f"(d[1]), "+f"(d[2]), "+f"(d[3])
        : "r"(a[0]), "r"(a[1]), "r"(a[2]), "r"(a[3]), "r"(b0), "r"(b1));
}
__device__ __forceinline__ void cpa16(uint32_t dst, const void* src){
    asm volatile("cp.async.cg.shared.global [%0], [%1], 16;" :: "r"(dst), "l"(src));
}
__device__ __forceinline__ void cpa_commit(){ asm volatile("cp.async.commit_group;"); }
__device__ __forceinline__ void cpa_wait0(){ asm volatile("cp.async.wait_group 0;" ::: "memory"); }
__device__ __forceinline__ void cpa_wait1(){ asm volatile("cp.async.wait_group 1;" ::: "memory"); }

__device__ __forceinline__ uint32_t sw_off(int r, int kc){
    return (uint32_t)(r*64 + ((kc ^ ((r>>1)&3))*16));
}
__device__ __forceinline__ void split8(float4 a, float4 b, uint4& hi, uint4& lo){
    float v[8] = {a.x,a.y,a.z,a.w,b.x,b.y,b.z,b.w};
    unsigned short hs[8], ls[8];
#pragma unroll
    for (int i=0;i<8;i++){
        __nv_bfloat16 h = __float2bfloat16_rn(v[i]);
        hs[i] = __bfloat16_as_ushort(h);
        float r = v[i] - __bfloat162float(h);
        ls[i] = __bfloat16_as_ushort(__float2bfloat16_rn(r));
    }
    hi.x = hs[0] | ((uint32_t)hs[1]<<16); hi.y = hs[2] | ((uint32_t)hs[3]<<16);
    hi.z = hs[4] | ((uint32_t)hs[5]<<16); hi.w = hs[6] | ((uint32_t)hs[7]<<16);
    lo.x = ls[0] | ((uint32_t)ls[1]<<16); lo.y = ls[2] | ((uint32_t)ls[3]<<16);
    lo.z = ls[4] | ((uint32_t)ls[5]<<16); lo.w = ls[6] | ((uint32_t)ls[7]<<16);
}

// ---------------- weight/input prep ----------------
__global__ void wt_prep(const float* __restrict__ W,
                        __nv_bfloat16* __restrict__ Th, __nv_bfloat16* __restrict__ Tl)
{
    __shared__ float tile[32][33];
    int n0 = blockIdx.x*32, k0 = blockIdx.y*32;
    int tx = threadIdx.x, ty = threadIdx.y;   // block (32,8)
#pragma unroll
    for (int i=0;i<32;i+=8)
        tile[ty+i][tx] = W[(size_t)(k0+ty+i)*256 + n0+tx];
    __syncthreads();
#pragma unroll
    for (int i=0;i<32;i+=8){
        int n = n0 + ty + i, k = k0 + tx;
        float v = tile[tx][ty+i];
        __nv_bfloat16 h = __float2bfloat16_rn(v);
        Th[(size_t)n*256 + k] = h;
        Tl[(size_t)n*256 + k] = __float2bfloat16_rn(v - __bfloat162float(h));
    }
}
struct WsplitArgs {
    const float* src[6];
    __nv_bfloat16 *hi[6], *lo[6];
    int sz[6];
};
__global__ void wsplit6(WsplitArgs a)
{
    int y = blockIdx.y;
    int i = blockIdx.x*blockDim.x + threadIdx.x;
    if (i >= a.sz[y]) return;
    float v = a.src[y][i];
    __nv_bfloat16 h = __float2bfloat16_rn(v);
    a.hi[y][i] = h;
    a.lo[y][i] = __float2bfloat16_rn(v - __bfloat162float(h));
}
__global__ void xsplit(const float* __restrict__ src,
                       __nv_bfloat16* __restrict__ hi, __nv_bfloat16* __restrict__ lo)
{
    size_t i = (size_t)(blockIdx.x)*blockDim.x + threadIdx.x;   // chunk of 8
    if (i >= ((size_t)GN*GD)/8) return;
    const float4* s = reinterpret_cast<const float4*>(src) + i*2;
    uint4 h, l;
    split8(s[0], s[1], h, l);
    reinterpret_cast<uint4*>(hi)[i] = h;
    reinterpret_cast<uint4*>(lo)[i] = l;
}

// ---------------- FNN GEMM: BM=128, BN=64, BK=32, 3-stage pipeline, 2 CTAs/SM ----------------
// stage buffer: Ah 8K | Al 8K | Bh 4K | Bl 4K = 24K; 3 stages = 72K dynamic
#define FBUF 24576
template<bool OSPLIT, bool ELU>
__global__ void __launch_bounds__(256, 2) gemm_a(
    const __nv_bfloat16* __restrict__ Ah_g, const __nv_bfloat16* __restrict__ Al_g,
    const __nv_bfloat16* __restrict__ Bh, const __nv_bfloat16* __restrict__ Bl,
    const float* __restrict__ bias,
    float* __restrict__ Cf, __nv_bfloat16* __restrict__ Ch, __nv_bfloat16* __restrict__ Cl,
    int M)
{
    extern __shared__ char smem[];
    const int tid = threadIdx.x, lane = tid & 31, wid = tid >> 5;
    const int row0 = blockIdx.y * 128;
    const int col0 = blockIdx.x * 64;
    const int mw = (wid >> 1) * 32;   // 4 m groups of 32
    const int nw = (wid & 1) * 32;    // 2 n groups of 32
    const uint32_t sbase = smem_u32(smem);

    float acc[2][4][4];
#pragma unroll
    for (int i=0;i<2;i++)
#pragma unroll
        for (int j=0;j<4;j++)
#pragma unroll
            for (int f=0;f<4;f++) acc[i][j][f]=0.f;

    auto cpAB = [&](int it, int buf){
        uint32_t base = sbase + buf*FBUF;
        int k0 = it*32;
#pragma unroll
        for (int t = 0; t < 2; t++){
            int idx = tid + t*256;          // 0..511: A rows
            int r = idx >> 2, kc = idx & 3;
            uint32_t dA = base + sw_off(r, kc);
            if (row0 + r < M){
                cpa16(dA,        Ah_g + (size_t)(row0+r)*256 + k0 + kc*8);
                cpa16(dA + 8192, Al_g + (size_t)(row0+r)*256 + k0 + kc*8);
            } else {
                uint4 z = make_uint4(0,0,0,0);
                *reinterpret_cast<uint4*>(smem + buf*FBUF + sw_off(r,kc)) = z;
                *reinterpret_cast<uint4*>(smem + buf*FBUF + 8192 + sw_off(r,kc)) = z;
            }
        }
        {
            int r = tid >> 2, kc = tid & 3;     // 64 B rows
            uint32_t dB = base + 16384 + sw_off(r, kc);
            cpa16(dB,        Bh + (size_t)(col0+r)*256 + k0 + kc*8);
            cpa16(dB + 4096, Bl + (size_t)(col0+r)*256 + k0 + kc*8);
        }
    };
    auto compute = [&](int buf){
        uint32_t aB = sbase + buf*FBUF;
        const int lr = (lane & 7) + ((lane >> 3) & 1) * 8;
        const int lk = lane >> 4;
#pragma unroll
        for (int s = 0; s < 2; s++){
            int kc = s*2 + lk;
            uint32_t ah[2][4], al[2][4];
#pragma unroll
            for (int f = 0; f < 2; f++){
                uint32_t ad = aB + sw_off(mw + f*16 + lr, kc);
                ldsm4(ah[f], ad);
                ldsm4(al[f], ad + 8192);
            }
            uint32_t bh[2][4], bl[2][4];
#pragma unroll
            for (int g = 0; g < 2; g++){
                uint32_t ad = aB + 16384 + sw_off(nw + g*16 + lr, kc);
                ldsm4(bh[g], ad);
                ldsm4(bl[g], ad + 4096);
            }
#pragma unroll
            for (int f = 0; f < 2; f++)
#pragma unroll
                for (int g = 0; g < 2; g++)
#pragma unroll
                    for (int t = 0; t < 2; t++){
                        float* d = acc[f][g*2+t];
                        mma16816(d, al[f], bh[g][t], bh[g][2+t]);
                        mma16816(d, ah[f], bl[g][t], bl[g][2+t]);
                        mma16816(d, ah[f], bh[g][t], bh[g][2+t]);
                    }
        }
    };

    // 3-stage prologue: stages 0 and 1 in flight
    cpAB(0, 0); cpa_commit();
    cpAB(1, 1); cpa_commit();
    cpa_wait1();           // stage 0 ready
    __syncthreads();

#pragma unroll 1
    for (int it = 0; it < 8; it++){
        int buf = it % 3;
        if (it + 2 < 8){ cpAB(it+2, (it+2) % 3); cpa_commit(); }
        compute(buf);
        if (it + 1 < 8){
            if (it + 2 < 8) cpa_wait1(); else cpa_wait0();
            __syncthreads();
        }
    }

    // epilogue
#pragma unroll
    for (int f = 0; f < 2; f++){
        int r = row0 + mw + f*16 + (lane >> 2);
#pragma unroll
        for (int j = 0; j < 4; j++){
            int cb = col0 + nw + (j>>1)*16 + (j&1)*8 + (lane & 3)*2;
            float b0 = bias[cb], b1 = bias[cb+1];
            float v0 = acc[f][j][0] + b0, v1 = acc[f][j][1] + b1;
            float v2 = acc[f][j][2] + b0, v3 = acc[f][j][3] + b1;
            if (ELU){
                v0 = v0 > 0.f ? v0 : expm1f(v0);
                v1 = v1 > 0.f ? v1 : expm1f(v1);
                v2 = v2 > 0.f ? v2 : expm1f(v2);
                v3 = v3 > 0.f ? v3 : expm1f(v3);
            }
            if (OSPLIT){
                if (r < M){
                    __nv_bfloat16 h0=__float2bfloat16_rn(v0), h1=__float2bfloat16_rn(v1);
                    uint32_t ph = __bfloat16_as_ushort(h0) | ((uint32_t)__bfloat16_as_ushort(h1)<<16);
                    uint32_t pl = __bfloat16_as_ushort(__float2bfloat16_rn(v0-__bfloat162float(h0)))
                               | ((uint32_t)__bfloat16_as_ushort(__float2bfloat16_rn(v1-__bfloat162float(h1)))<<16);
                    *reinterpret_cast<uint32_t*>(&Ch[(size_t)r*256+cb]) = ph;
                    *reinterpret_cast<uint32_t*>(&Cl[(size_t)r*256+cb]) = pl;
                }
                if (r + 8 < M){
                    __nv_bfloat16 h2=__float2bfloat16_rn(v2), h3=__float2bfloat16_rn(v3);
                    uint32_t ph = __bfloat16_as_ushort(h2) | ((uint32_t)__bfloat16_as_ushort(h3)<<16);
                    uint32_t pl = __bfloat16_as_ushort(__float2bfloat16_rn(v2-__bfloat162float(h2)))
                               | ((uint32_t)__bfloat16_as_ushort(__float2bfloat16_rn(v3-__bfloat162float(h3)))<<16);
                    *reinterpret_cast<uint32_t*>(&Ch[(size_t)(r+8)*256+cb]) = ph;
                    *reinterpret_cast<uint32_t*>(&Cl[(size_t)(r+8)*256+cb]) = pl;
                }
            } else {
                if (r < M)     *reinterpret_cast<float2*>(&Cf[(size_t)r*256 + cb])     = make_float2(v0, v1);
                if (r + 8 < M) *reinterpret_cast<float2*>(&Cf[(size_t)(r+8)*256 + cb]) = make_float2(v2, v3);
            }
        }
    }
}

// ---------------- LSTM gates: one K-chunk per CTA (no loop, minimal latency) ----------------
// grid (8 j-blocks, nch chunks); smem 32K single stage.
#define LBUF 32768
__global__ void __launch_bounds__(256, 1) lstm_gates_tc(
    const float* __restrict__ A0, int K0,            // xin, row stride K0
    const float* __restrict__ A1,                     // h, row stride 256
    const __nv_bfloat16* __restrict__ B0h, const __nv_bfloat16* __restrict__ B0l,
    const __nv_bfloat16* __restrict__ B1h, const __nv_bfloat16* __restrict__ B1l,
    float* __restrict__ gpart)
{
    extern __shared__ char smem[];
    const int tid = threadIdx.x, lane = tid & 31, wid = tid >> 5;
    const int j0 = blockIdx.x * 128;
    const int cg = blockIdx.y;                        // global K chunk (32-wide)
    const int mw = (wid >> 1) * 32;
    const int nw = (wid & 1) * 64;
    const uint32_t sbase = smem_u32(smem);
    const int nch0 = K0 >> 5;

    float acc[2][8][4];
#pragma unroll
    for (int i=0;i<2;i++)
#pragma unroll
        for (int j=0;j<8;j++)
#pragma unroll
            for (int f=0;f<4;f++) acc[i][j][f]=0.f;

    // B chunk via cp.async
    {
        const __nv_bfloat16 *bh, *bl; int ld, k0;
        if (cg < nch0){ bh=B0h; bl=B0l; ld=K0; k0=cg*32; }
        else          { bh=B1h; bl=B1l; ld=256; k0=(cg-nch0)*32; }
#pragma unroll
        for (int t = 0; t < 2; t++){
            int idx = tid + t*256;
            int r = idx >> 2, kc = idx & 3;
            uint32_t d = sbase + 16384 + sw_off(r, kc);
            cpa16(d,        bh + (size_t)(j0+r)*ld + k0 + kc*8);
            cpa16(d + 8192, bl + (size_t)(j0+r)*ld + k0 + kc*8);
        }
        cpa_commit();
    }
    // A chunk: load fp32, split, store
    {
        const int sr  = tid >> 1;
        const int skh = (tid & 1) * 16;
        const float* ap;
        if (cg < nch0) ap = A0 + (size_t)sr*K0 + cg*32 + skh;
        else           ap = A1 + (size_t)sr*256 + (cg-nch0)*32 + skh;
        float4 ra[4];
#pragma unroll
        for (int i=0;i<4;i++) ra[i] = *reinterpret_cast<const float4*>(ap + i*4);
        int c0 = (tid & 1) * 2;
        uint4 h0,l0,h1,l1;
        split8(ra[0], ra[1], h0, l0);
        split8(ra[2], ra[3], h1, l1);
        *reinterpret_cast<uint4*>(smem +        sw_off(sr, c0  )) = h0;
        *reinterpret_cast<uint4*>(smem +        sw_off(sr, c0+1)) = h1;
        *reinterpret_cast<uint4*>(smem + 8192 + sw_off(sr, c0  )) = l0;
        *reinterpret_cast<uint4*>(smem + 8192 + sw_off(sr, c0+1)) = l1;
    }
    cpa_wait0();
    __syncthreads();

    // compute (one 32-k tile)
    {
        const int lr = (lane & 7) + ((lane >> 3) & 1) * 8;
        const int lk = lane >> 4;
#pragma unroll
        for (int s = 0; s < 2; s++){
            int kc = s*2 + lk;
            uint32_t ah[2][4], al[2][4];
#pragma unroll
            for (int f = 0; f < 2; f++){
                uint32_t ad = sbase + sw_off(mw + f*16 + lr, kc);
                ldsm4(ah[f], ad);
                ldsm4(al[f], ad + 8192);
            }
            uint32_t bh[4][4], bl[4][4];
#pragma unroll
            for (int g = 0; g < 4; g++){
                uint32_t ad = sbase + 16384 + sw_off(nw + g*16 + lr, kc);
                ldsm4(bh[g], ad);
                ldsm4(bl[g], ad + 8192);
            }
#pragma unroll
            for (int f = 0; f < 2; f++)
#pragma unroll
                for (int g = 0; g < 4; g++)
#pragma unroll
                    for (int t = 0; t < 2; t++){
                        float* d = acc[f][g*2+t];
                        mma16816(d, al[f], bh[g][t], bh[g][2+t]);
                        mma16816(d, ah[f], bl[g][t], bl[g][2+t]);
                        mma16816(d, ah[f], bh[g][t], bh[g][2+t]);
                    }
        }
    }

    float* gp = gpart + (size_t)cg*GB*GJ;
#pragma unroll
    for (int f = 0; f < 2; f++){
        int b = mw + f*16 + (lane >> 2);
#pragma unroll
        for (int j = 0; j < 8; j++){
            int cb = j0 + nw + (j>>1)*16 + (j&1)*8 + (lane & 3)*2;
            *reinterpret_cast<float2*>(&gp[(size_t)b*GJ + cb])
                = make_float2(acc[f][j][0], acc[f][j][1]);
            *reinterpret_cast<float2*>(&gp[(size_t)(b+8)*GJ + cb])
                = make_float2(acc[f][j][2], acc[f][j][3]);
        }
    }
}

// cell: reduce nch partials + biases + activation
__global__ void lstm_cell4(const float* __restrict__ gpart, int nch,
                           const float* __restrict__ bih, const float* __restrict__ bhh,
                           float* __restrict__ h, float* __restrict__ c)
{
    int idx = blockIdx.x * blockDim.x + threadIdx.x;  // GB*GH
    int b = idx >> 8, k = idx & 255;
    float gi = bih[k]        + bhh[k];
    float gf = bih[GH  + k]  + bhh[GH  + k];
    float gg = bih[2*GH + k] + bhh[2*GH + k];
    float go = bih[3*GH + k] + bhh[3*GH + k];
    for (int p = 0; p < nch; p++){
        const float* gp = gpart + (size_t)p*GB*GJ + (size_t)b*GJ;
        gi += gp[k];
        gf += gp[GH  + k];
        gg += gp[2*GH + k];
        go += gp[3*GH + k];
    }
    float si = 1.f/(1.f+expf(-gi));
    float sf = 1.f/(1.f+expf(-gf));
    float so = 1.f/(1.f+expf(-go));
    float cn = sf*c[idx] + si*tanhf(gg);
    c[idx] = cn;
    h[idx] = so * tanhf(cn);
}

__global__ void init_state(){
    int idx = blockIdx.x*blockDim.x + threadIdx.x;
    if (idx < 3*GB*GH){ g_h[idx]=0.f; g_c[idx]=0.f; }
    if (idx < GB*2*GH) g_qstar[idx]=0.f;
}

// ---------------- fused single-pass attention ----------------
__global__ void __launch_bounds__(256) attn_fused(const float* __restrict__ q,
                                                  const int* __restrict__ bi)
{
    const int b = blockIdx.x, ch = blockIdx.y;
    const int tid = threadIdx.x, lane = tid & 31, wid = tid >> 5;
    __shared__ float sq[256];
    __shared__ float se[32], spe[32];
    __shared__ float s_m, s_s, s_scale;

    int lo = 0, hi = GN;
    while (lo < hi){ int mid=(lo+hi)>>1; if (bi[mid] <  b) lo=mid+1; else hi=mid; }
    int start = lo; hi = GN;
    while (lo < hi){ int mid=(lo+hi)>>1; if (bi[mid] <= b) lo=mid+1; else hi=mid; }
    int end = lo;
    int len = end - start;
    int per = (len + 7) >> 3;
    int s = start + ch*per;
    int t = min(end, s + per);

    sq[tid] = q[(size_t)b*256 + tid];
    if (tid == 0){ s_m = -INFINITY; s_s = 0.f; s_scale = 1.f; }
    float racc = 0.f;
    __syncthreads();

    for (int n0 = s; n0 < t; n0 += 32){
        int nrows = min(32, t - n0);
#pragma unroll
        for (int i = 0; i < 4; i++){
            int rr = wid*4 + i;
            float sd = 0.f;
            if (rr < nrows){
                const float4* hp = reinterpret_cast<const float4*>(g_hfeat + (size_t)(n0+rr)*256);
                const float4* qp = reinterpret_cast<const float4*>(sq);
                float4 a = hp[lane*2],   w = qp[lane*2];
                sd += a.x*w.x + a.y*w.y + a.z*w.z + a.w*w.w;
                a = hp[lane*2+1]; w = qp[lane*2+1];
                sd += a.x*w.x + a.y*w.y + a.z*w.z + a.w*w.w;
            }
#pragma unroll
            for (int off=16; off>0; off>>=1) sd += __shfl_xor_sync(0xffffffffu, sd, off);
            if (lane == 0) se[rr] = (rr < nrows) ? sd : -INFINITY;
        }
        __syncthreads();
        if (wid == 0){
            float e = se[lane];
            float mt = e;
#pragma unroll
            for (int off=16; off>0; off>>=1) mt = fmaxf(mt, __shfl_xor_sync(0xffffffffu, mt, off));
            float m_old = s_m;
            float m_new = fmaxf(m_old, mt);
            float pe = expf(e - m_new);
            float ps = pe;
#pragma unroll
            for (int off=16; off>0; off>>=1) ps += __shfl_xor_sync(0xffffffffu, ps, off);
            if (lane == 0){
                float sc = (m_old == -INFINITY) ? 0.f : expf(m_old - m_new);
                s_scale = sc;
                s_s = s_s*sc + ps;
                s_m = m_new;
            }
            spe[lane] = pe;
        }
        __syncthreads();
        float sc = s_scale;
        racc *= sc;
        const float* col = g_hfeat + (size_t)n0*256 + tid;
        for (int i = 0; i < nrows; i++)
            racc = fmaf(spe[i], col[(size_t)i*256], racc);
        __syncthreads();
    }
    int ci = b*8 + ch;
    if (tid == 0){ g_am[ci] = s_m; g_as[ci] = s_s; }
    g_ar[(size_t)ci*256 + tid] = racc;
}

__global__ void attn_comb(const float* __restrict__ h2)
{
    int b = blockIdx.x, tid = threadIdx.x;
    __shared__ float sm[8], ss[8];
    if (tid < 8){ sm[tid] = g_am[b*8+tid]; ss[tid] = g_as[b*8+tid]; }
    __syncthreads();
    float mg = -INFINITY;
#pragma unroll
    for (int c=0;c<8;c++) mg = fmaxf(mg, sm[c]);
    if (!isfinite(mg)) mg = 0.f;
    float denom = 0.f, w[8];
#pragma unroll
    for (int c=0;c<8;c++){
        float wc = expf(sm[c] - mg);
        w[c] = wc;
        denom += ss[c]*wc;
    }
    float r = 0.f;
#pragma unroll
    for (int c=0;c<8;c++) r += g_ar[(size_t)(b*8+c)*256 + tid] * w[c];
    r /= (denom + 1e-16f);
    g_qstar[(size_t)b*512 + tid]       = h2[(size_t)b*256 + tid];
    g_qstar[(size_t)b*512 + 256 + tid] = r;
}

__global__ void out_gemm(const float* __restrict__ W, const float* __restrict__ bias,
                         float* __restrict__ out)
{
    int b = blockIdx.x, e = threadIdx.x;
    const float* qs = g_qstar + (size_t)b*(2*GH);
    float acc = bias[e];
    for (int k = 0; k < 2*GH; k++) acc = fmaf(qs[k], W[(size_t)k*GE + e], acc);
    out[(size_t)b*GE + e] = acc;
}

// ---------------- launch ----------------
extern "C" void kernel_launch(void* const* d_in, const int* in_sizes, int n_in,
                              void* d_out, int out_size)
{
    const float* x    = (const float*)d_in[0];
    const int*   bi   = (const int*)  d_in[1];
    const float* W1   = (const float*)d_in[2];
    const float* b1   = (const float*)d_in[3];
    const float* W2   = (const float*)d_in[4];
    const float* b2   = (const float*)d_in[5];
    const float* Wih[3] = {(const float*)d_in[6],  (const float*)d_in[10], (const float*)d_in[14]};
    const float* Whh[3] = {(const float*)d_in[7],  (const float*)d_in[11], (const float*)d_in[15]};
    const float* bih[3] = {(const float*)d_in[8],  (const float*)d_in[12], (const float*)d_in[16]};
    const float* bhh[3] = {(const float*)d_in[9],  (const float*)d_in[13], (const float*)d_in[17]};
    const float* outW = (const float*)d_in[18];
    const float* outb = (const float*)d_in[19];

    float *hfeat, *gpart, *h, *c, *qstar;
    __nv_bfloat16 *xh, *xl, *t1h, *t1l, *wt1h, *wt1l, *wt2h, *wt2l, *wihh, *wihl, *whhh, *whhl;
    cudaGetSymbolAddress((void**)&hfeat, g_hfeat);
    cudaGetSymbolAddress((void**)&gpart, g_gpart);
    cudaGetSymbolAddress((void**)&h,     g_h);
    cudaGetSymbolAddress((void**)&c,     g_c);
    cudaGetSymbolAddress((void**)&qstar, g_qstar);
    cudaGetSymbolAddress((void**)&xh,    g_xh);
    cudaGetSymbolAddress((void**)&xl,    g_xl);
    cudaGetSymbolAddress((void**)&t1h,   g_t1h);
    cudaGetSymbolAddress((void**)&t1l,   g_t1l);
    cudaGetSymbolAddress((void**)&wt1h,  g_wt1h);
    cudaGetSymbolAddress((void**)&wt1l,  g_wt1l);
    cudaGetSymbolAddress((void**)&wt2h,  g_wt2h);
    cudaGetSymbolAddress((void**)&wt2l,  g_wt2l);
    cudaGetSymbolAddress((void**)&wihh,  g_wihh);
    cudaGetSymbolAddress((void**)&wihl,  g_wihl);
    cudaGetSymbolAddress((void**)&whhh,  g_whhh);
    cudaGetSymbolAddress((void**)&whhl,  g_whhl);

    cudaFuncSetAttribute(gemm_a<true,true>,   cudaFuncAttributeMaxDynamicSharedMemorySize, 3*FBUF);
    cudaFuncSetAttribute(gemm_a<false,false>, cudaFuncAttributeMaxDynamicSharedMemorySize, 3*FBUF);
    cudaFuncSetAttribute(lstm_gates_tc, cudaFuncAttributeMaxDynamicSharedMemorySize, LBUF);

    // prep: weights + input split
    wt_prep<<<dim3(8,8), dim3(32,8)>>>(W1, wt1h, wt1l);
    wt_prep<<<dim3(8,8), dim3(32,8)>>>(W2, wt2h, wt2l);
    xsplit<<<(int)(((size_t)GN*GD/8 + 255)/256), 256>>>(x, xh, xl);
    const int ihOff[3] = {0, 1024*512, 1024*512 + 1024*256};
    const int ihSz[3]  = {1024*512, 1024*256, 1024*256};
    {
        WsplitArgs wa;
        for (int l = 0; l < 3; l++){
            wa.src[l] = Wih[l]; wa.hi[l] = wihh + ihOff[l]; wa.lo[l] = wihl + ihOff[l]; wa.sz[l] = ihSz[l];
            wa.src[3+l] = Whh[l]; wa.hi[3+l] = whhh + l*1024*256; wa.lo[3+l] = whhl + l*1024*256; wa.sz[3+l] = 1024*256;
        }
        wsplit6<<<dim3(2048, 6), 256>>>(wa);
    }

    dim3 gg(4, (GN + 127) / 128);
    gemm_a<true,true><<<gg, 256, 3*FBUF>>>(
        xh, xl, wt1h, wt1l, b1, nullptr, t1h, t1l, GN);
    gemm_a<false,false><<<gg, 256, 3*FBUF>>>(
        t1h, t1l, wt2h, wt2l, b2, hfeat, nullptr, nullptr, GN);
    init_state<<<(3*GB*GH + 255)/256, 256>>>();

    for (int step = 0; step < NSTEPS; step++){
        const float* lin = qstar; int Kx = 2*GH;
        for (int l = 0; l < 3; l++){
            int nch = (Kx + GH) / 32;   // 24 for layer 0, 16 for layers 1,2
            lstm_gates_tc<<<dim3(8, nch), 256, LBUF>>>(
                lin, Kx, h + l*GB*GH,
                wihh + ihOff[l], wihl + ihOff[l],
                whhh + l*1024*256, whhl + l*1024*256, gpart);
            lstm_cell4<<<GB, GH>>>(gpart, nch, bih[l], bhh[l], h + l*GB*GH, c + l*GB*GH);
            lin = h + l*GB*GH; Kx = GH;
        }
        attn_fused<<<dim3(GB, 8), 256>>>(h + 2*GB*GH, bi);
        attn_comb<<<GB, 256>>>(h + 2*GB*GH);
    }
    out_gemm<<<GB, GE>>>(outW, outb, (float*)d_out);
}

// round 16
// speedup vs baseline: 4.1563x; 1.0045x over previous
#include <cuda_runtime.h>
#include <cuda_bf16.h>
#include <math.h>
#include <stdint.h>

#define GN 100000
#define GD 256
#define GH 256
#define GB 128
#define GE 128
#define NSTEPS 5
#define GJ (4*GH)     // 1024 gate width
#define NCH64MAX 12   // max 64-wide K chunks (layer0: 768/64)

// ---------------- scratch (device globals; no allocations) ----------------
__device__ __nv_bfloat16 g_xh[(size_t)GN*GD], g_xl[(size_t)GN*GD];    // split input x
__device__ __nv_bfloat16 g_t1h[(size_t)GN*GH], g_t1l[(size_t)GN*GH];  // split ELU output
__device__ float g_hfeat[(size_t)GN*GH];  // node features (fp32)
__device__ float g_h[3*GB*GH];
__device__ float g_c[3*GB*GH];
__device__ float g_qstar[GB*2*GH];
__device__ float g_gpart[(size_t)NCH64MAX*GB*GJ];   // LSTM gate partials
__device__ unsigned g_cnt[16];                       // per (step,layer) arrival counters
// FNN weight transposed hi/lo splits ([n][k] k-major)
__device__ __nv_bfloat16 g_wt1h[GD*GH], g_wt1l[GD*GH];
__device__ __nv_bfloat16 g_wt2h[GH*GH], g_wt2l[GH*GH];
// LSTM weight hi/lo splits ([j][k]); Wih packed l0@0 (1024x512), l1, l2
__device__ __nv_bfloat16 g_wihh[1024*1024], g_wihl[1024*1024];
__device__ __nv_bfloat16 g_whhh[3*1024*256], g_whhl[3*1024*256];
// attention chunk partials
__device__ float g_am[GB*8], g_as[GB*8], g_ar[(size_t)GB*8*256];

// ---------------- mma/ldmatrix/cp.async helpers (family-wide only) ----------------
__device__ __forceinline__ uint32_t smem_u32(const void* p){
    uint32_t a;
    asm("{ .reg .u64 t; cvta.to.shared.u64 t, %1; cvt.u32.u64 %0, t; }" : "=r"(a) : "l"(p));
    return a;
}
__device__ __forceinline__ void ldsm4(uint32_t r[4], uint32_t addr){
    asm volatile("ldmatrix.sync.aligned.m8n8.x4.shared.b16 {%0,%1,%2,%3}, [%4];"
        : "=r"(r[0]), "=r"(r[1]), "=r"(r[2]), "=r"(r[3]) : "r"(addr));
}
__device__ __forceinline__ void mma16816(float d[4], const uint32_t a[4], uint32_t b0, uint32_t b1){
    asm volatile("mma.sync.aligned.m16n8k16.row.col.f32.bf16.bf16.f32 "
        "{%0,%1,%2,%3},{%4,%5,%6,%7},{%8,%9},{%0,%1,%2,%3};"
        : "+f"(d[0]), "+f"(d[1]), "+f"(d[2]), "+f"(d[3])
        : "r"(a[0]), "r"(a[1]), "r"(a[2]), "r"(a[3]), "r"(b0), "r"(b1));
}
__device__ __forceinline__ void cpa16(uint32_t dst, const void* src){
    asm volatile("cp.async.cg.shared.global [%0], [%1], 16;" :: "r"(dst), "l"(src));
}
__device__ __forceinline__ void cpa_commit(){ asm volatile("cp.async.commit_group;"); }
__device__ __forceinline__ void cpa_wait0(){ asm volatile("cp.async.wait_group 0;" ::: "memory"); }
__device__ __forceinline__ void cpa_wait1(){ asm volatile("cp.async.wait_group 1;" ::: "memory"); }

__device__ __forceinline__ uint32_t sw_off(int r, int kc){
    return (uint32_t)(r*64 + ((kc ^ ((r>>1)&3))*16));
}
__device__ __forceinline__ void split8(float4 a, float4 b, uint4& hi, uint4& lo){
    float v[8] = {a.x,a.y,a.z,a.w,b.x,b.y,b.z,b.w};
    unsigned short hs[8], ls[8];
#pragma unroll
    for (int i=0;i<8;i++){
        __nv_bfloat16 h = __float2bfloat16_rn(v[i]);
        hs[i] = __bfloat16_as_ushort(h);
        float r = v[i] - __bfloat162float(h);
        ls[i] = __bfloat16_as_ushort(__float2bfloat16_rn(r));
    }
    hi.x = hs[0] | ((uint32_t)hs[1]<<16); hi.y = hs[2] | ((uint32_t)hs[3]<<16);
    hi.z = hs[4] | ((uint32_t)hs[5]<<16); hi.w = hs[6] | ((uint32_t)hs[7]<<16);
    lo.x = ls[0] | ((uint32_t)ls[1]<<16); lo.y = ls[2] | ((uint32_t)ls[3]<<16);
    lo.z = ls[4] | ((uint32_t)ls[5]<<16); lo.w = ls[6] | ((uint32_t)ls[7]<<16);
}

// ---------------- weight/input prep ----------------
__global__ void wt_prep(const float* __restrict__ W,
                        __nv_bfloat16* __restrict__ Th, __nv_bfloat16* __restrict__ Tl)
{
    __shared__ float tile[32][33];
    int n0 = blockIdx.x*32, k0 = blockIdx.y*32;
    int tx = threadIdx.x, ty = threadIdx.y;   // block (32,8)
#pragma unroll
    for (int i=0;i<32;i+=8)
        tile[ty+i][tx] = W[(size_t)(k0+ty+i)*256 + n0+tx];
    __syncthreads();
#pragma unroll
    for (int i=0;i<32;i+=8){
        int n = n0 + ty + i, k = k0 + tx;
        float v = tile[tx][ty+i];
        __nv_bfloat16 h = __float2bfloat16_rn(v);
        Th[(size_t)n*256 + k] = h;
        Tl[(size_t)n*256 + k] = __float2bfloat16_rn(v - __bfloat162float(h));
    }
}
struct WsplitArgs {
    const float* src[6];
    __nv_bfloat16 *hi[6], *lo[6];
    int sz[6];
};
__global__ void wsplit6(WsplitArgs a)
{
    int y = blockIdx.y;
    int i = blockIdx.x*blockDim.x + threadIdx.x;
    if (i >= a.sz[y]) return;
    float v = a.src[y][i];
    __nv_bfloat16 h = __float2bfloat16_rn(v);
    a.hi[y][i] = h;
    a.lo[y][i] = __float2bfloat16_rn(v - __bfloat162float(h));
}
__global__ void xsplit(const float* __restrict__ src,
                       __nv_bfloat16* __restrict__ hi, __nv_bfloat16* __restrict__ lo)
{
    size_t i = (size_t)(blockIdx.x)*blockDim.x + threadIdx.x;   // chunk of 8
    if (i >= ((size_t)GN*GD)/8) return;
    const float4* s = reinterpret_cast<const float4*>(src) + i*2;
    uint4 h, l;
    split8(s[0], s[1], h, l);
    reinterpret_cast<uint4*>(hi)[i] = h;
    reinterpret_cast<uint4*>(lo)[i] = l;
}

// ---------------- FNN GEMM: BM=128, BN=64, BK=32, 3-stage pipeline, 2 CTAs/SM ----------------
// stage buffer: Ah 8K | Al 8K | Bh 4K | Bl 4K = 24K; 3 stages = 72K dynamic
#define FBUF 24576
template<bool OSPLIT, bool ELU>
__global__ void __launch_bounds__(256, 2) gemm_a(
    const __nv_bfloat16* __restrict__ Ah_g, const __nv_bfloat16* __restrict__ Al_g,
    const __nv_bfloat16* __restrict__ Bh, const __nv_bfloat16* __restrict__ Bl,
    const float* __restrict__ bias,
    float* __restrict__ Cf, __nv_bfloat16* __restrict__ Ch, __nv_bfloat16* __restrict__ Cl,
    int M)
{
    extern __shared__ char smem[];
    const int tid = threadIdx.x, lane = tid & 31, wid = tid >> 5;
    const int row0 = blockIdx.y * 128;
    const int col0 = blockIdx.x * 64;
    const int mw = (wid >> 1) * 32;   // 4 m groups of 32
    const int nw = (wid & 1) * 32;    // 2 n groups of 32
    const uint32_t sbase = smem_u32(smem);

    float acc[2][4][4];
#pragma unroll
    for (int i=0;i<2;i++)
#pragma unroll
        for (int j=0;j<4;j++)
#pragma unroll
            for (int f=0;f<4;f++) acc[i][j][f]=0.f;

    auto cpAB = [&](int it, int buf){
        uint32_t base = sbase + buf*FBUF;
        int k0 = it*32;
#pragma unroll
        for (int t = 0; t < 2; t++){
            int idx = tid + t*256;          // 0..511: A rows
            int r = idx >> 2, kc = idx & 3;
            uint32_t dA = base + sw_off(r, kc);
            if (row0 + r < M){
                cpa16(dA,        Ah_g + (size_t)(row0+r)*256 + k0 + kc*8);
                cpa16(dA + 8192, Al_g + (size_t)(row0+r)*256 + k0 + kc*8);
            } else {
                uint4 z = make_uint4(0,0,0,0);
                *reinterpret_cast<uint4*>(smem + buf*FBUF + sw_off(r,kc)) = z;
                *reinterpret_cast<uint4*>(smem + buf*FBUF + 8192 + sw_off(r,kc)) = z;
            }
        }
        {
            int r = tid >> 2, kc = tid & 3;     // 64 B rows
            uint32_t dB = base + 16384 + sw_off(r, kc);
            cpa16(dB,        Bh + (size_t)(col0+r)*256 + k0 + kc*8);
            cpa16(dB + 4096, Bl + (size_t)(col0+r)*256 + k0 + kc*8);
        }
    };
    auto compute = [&](int buf){
        uint32_t aB = sbase + buf*FBUF;
        const int lr = (lane & 7) + ((lane >> 3) & 1) * 8;
        const int lk = lane >> 4;
#pragma unroll
        for (int s = 0; s < 2; s++){
            int kc = s*2 + lk;
            uint32_t ah[2][4], al[2][4];
#pragma unroll
            for (int f = 0; f < 2; f++){
                uint32_t ad = aB + sw_off(mw + f*16 + lr, kc);
                ldsm4(ah[f], ad);
                ldsm4(al[f], ad + 8192);
            }
            uint32_t bh[2][4], bl[2][4];
#pragma unroll
            for (int g = 0; g < 2; g++){
                uint32_t ad = aB + 16384 + sw_off(nw + g*16 + lr, kc);
                ldsm4(bh[g], ad);
                ldsm4(bl[g], ad + 4096);
            }
#pragma unroll
            for (int f = 0; f < 2; f++)
#pragma unroll
                for (int g = 0; g < 2; g++)
#pragma unroll
                    for (int t = 0; t < 2; t++){
                        float* d = acc[f][g*2+t];
                        mma16816(d, al[f], bh[g][t], bh[g][2+t]);
                        mma16816(d, ah[f], bl[g][t], bl[g][2+t]);
                        mma16816(d, ah[f], bh[g][t], bh[g][2+t]);
                    }
        }
    };

    // 3-stage prologue
    cpAB(0, 0); cpa_commit();
    cpAB(1, 1); cpa_commit();
    cpa_wait1();
    __syncthreads();

#pragma unroll 1
    for (int it = 0; it < 8; it++){
        int buf = it % 3;
        if (it + 2 < 8){ cpAB(it+2, (it+2) % 3); cpa_commit(); }
        compute(buf);
        if (it + 1 < 8){
            if (it + 2 < 8) cpa_wait1(); else cpa_wait0();
            __syncthreads();
        }
    }

    // epilogue
#pragma unroll
    for (int f = 0; f < 2; f++){
        int r = row0 + mw + f*16 + (lane >> 2);
#pragma unroll
        for (int j = 0; j < 4; j++){
            int cb = col0 + nw + (j>>1)*16 + (j&1)*8 + (lane & 3)*2;
            float b0 = bias[cb], b1 = bias[cb+1];
            float v0 = acc[f][j][0] + b0, v1 = acc[f][j][1] + b1;
            float v2 = acc[f][j][2] + b0, v3 = acc[f][j][3] + b1;
            if (ELU){
                v0 = v0 > 0.f ? v0 : expm1f(v0);
                v1 = v1 > 0.f ? v1 : expm1f(v1);
                v2 = v2 > 0.f ? v2 : expm1f(v2);
                v3 = v3 > 0.f ? v3 : expm1f(v3);
            }
            if (OSPLIT){
                if (r < M){
                    __nv_bfloat16 h0=__float2bfloat16_rn(v0), h1=__float2bfloat16_rn(v1);
                    uint32_t ph = __bfloat16_as_ushort(h0) | ((uint32_t)__bfloat16_as_ushort(h1)<<16);
                    uint32_t pl = __bfloat16_as_ushort(__float2bfloat16_rn(v0-__bfloat162float(h0)))
                               | ((uint32_t)__bfloat16_as_ushort(__float2bfloat16_rn(v1-__bfloat162float(h1)))<<16);
                    *reinterpret_cast<uint32_t*>(&Ch[(size_t)r*256+cb]) = ph;
                    *reinterpret_cast<uint32_t*>(&Cl[(size_t)r*256+cb]) = pl;
                }
                if (r + 8 < M){
                    __nv_bfloat16 h2=__float2bfloat16_rn(v2), h3=__float2bfloat16_rn(v3);
                    uint32_t ph = __bfloat16_as_ushort(h2) | ((uint32_t)__bfloat16_as_ushort(h3)<<16);
                    uint32_t pl = __bfloat16_as_ushort(__float2bfloat16_rn(v2-__bfloat162float(h2)))
                               | ((uint32_t)__bfloat16_as_ushort(__float2bfloat16_rn(v3-__bfloat162float(h3)))<<16);
                    *reinterpret_cast<uint32_t*>(&Ch[(size_t)(r+8)*256+cb]) = ph;
                    *reinterpret_cast<uint32_t*>(&Cl[(size_t)(r+8)*256+cb]) = pl;
                }
            } else {
                if (r < M)     *reinterpret_cast<float2*>(&Cf[(size_t)r*256 + cb])     = make_float2(v0, v1);
                if (r + 8 < M) *reinterpret_cast<float2*>(&Cf[(size_t)(r+8)*256 + cb]) = make_float2(v2, v3);
            }
        }
    }
}

// ---------------- fused LSTM layer: gates (64-wide K chunk per CTA) + spin + cell ----------------
// grid (8 j-blocks, nch64); <=96 CTAs -> all wave-1 resident at any occupancy (spin-safe).
// smem: 2 x 32K buffers (one per 32-sub-chunk).
#define LBUF 32768
__global__ void lstm_fused(
    const float* __restrict__ A0, int K0,            // xin, row stride K0
    const float* __restrict__ A1,                     // h, row stride 256
    const __nv_bfloat16* __restrict__ B0h, const __nv_bfloat16* __restrict__ B0l,
    const __nv_bfloat16* __restrict__ B1h, const __nv_bfloat16* __restrict__ B1l,
    float* __restrict__ gpart, int slot, int nch64,
    const float* __restrict__ bih, const float* __restrict__ bhh,
    float* __restrict__ h, float* __restrict__ c)
{
    extern __shared__ char smem[];
    const int tid = threadIdx.x, lane = tid & 31, wid = tid >> 5;
    const int j0 = blockIdx.x * 128;
    const int cg64 = blockIdx.y;
    const int mw = (wid >> 1) * 32;
    const int nw = (wid & 1) * 64;
    const uint32_t sbase = smem_u32(smem);
    const int nch0 = K0 >> 5;        // 32-chunk count in A0

    float acc[2][8][4];
#pragma unroll
    for (int i=0;i<2;i++)
#pragma unroll
        for (int j=0;j<8;j++)
#pragma unroll
            for (int f=0;f<4;f++) acc[i][j][f]=0.f;

    auto cpB = [&](int cs, int buf){
        uint32_t base = sbase + buf*LBUF;
        const __nv_bfloat16 *bh, *bl; int ld, k0;
        if (cs < nch0){ bh=B0h; bl=B0l; ld=K0; k0=cs*32; }
        else          { bh=B1h; bl=B1l; ld=256; k0=(cs-nch0)*32; }
#pragma unroll
        for (int t = 0; t < 2; t++){
            int idx = tid + t*256;
            int r = idx >> 2, kc = idx & 3;
            uint32_t d = base + 16384 + sw_off(r, kc);
            cpa16(d,        bh + (size_t)(j0+r)*ld + k0 + kc*8);
            cpa16(d + 8192, bl + (size_t)(j0+r)*ld + k0 + kc*8);
        }
        cpa_commit();
    };
    auto ldstA = [&](int cs, int buf){
        char* base = smem + buf*LBUF;
        const int sr  = tid >> 1;
        const int skh = (tid & 1) * 16;
        const float* ap;
        if (cs < nch0) ap = A0 + (size_t)sr*K0 + cs*32 + skh;
        else           ap = A1 + (size_t)sr*256 + (cs-nch0)*32 + skh;
        float4 ra[4];
#pragma unroll
        for (int i=0;i<4;i++) ra[i] = *reinterpret_cast<const float4*>(ap + i*4);
        int c0 = (tid & 1) * 2;
        uint4 h0,l0,h1,l1;
        split8(ra[0], ra[1], h0, l0);
        split8(ra[2], ra[3], h1, l1);
        *reinterpret_cast<uint4*>(base +        sw_off(sr, c0  )) = h0;
        *reinterpret_cast<uint4*>(base +        sw_off(sr, c0+1)) = h1;
        *reinterpret_cast<uint4*>(base + 8192 + sw_off(sr, c0  )) = l0;
        *reinterpret_cast<uint4*>(base + 8192 + sw_off(sr, c0+1)) = l1;
    };
    auto compute = [&](int buf){
        uint32_t aB = sbase + buf*LBUF;
        const int lr = (lane & 7) + ((lane >> 3) & 1) * 8;
        const int lk = lane >> 4;
#pragma unroll
        for (int s = 0; s < 2; s++){
            int kc = s*2 + lk;
            uint32_t ah[2][4], al[2][4];
#pragma unroll
            for (int f = 0; f < 2; f++){
                uint32_t ad = aB + sw_off(mw + f*16 + lr, kc);
                ldsm4(ah[f], ad);
                ldsm4(al[f], ad + 8192);
            }
            uint32_t bh[4][4], bl[4][4];
#pragma unroll
            for (int g = 0; g < 4; g++){
                uint32_t ad = aB + 16384 + sw_off(nw + g*16 + lr, kc);
                ldsm4(bh[g], ad);
                ldsm4(bl[g], ad + 8192);
            }
#pragma unroll
            for (int f = 0; f < 2; f++)
#pragma unroll
                for (int g = 0; g < 4; g++)
#pragma unroll
                    for (int t = 0; t < 2; t++){
                        float* d = acc[f][g*2+t];
                        mma16816(d, al[f], bh[g][t], bh[g][2+t]);
                        mma16816(d, ah[f], bl[g][t], bl[g][2+t]);
                        mma16816(d, ah[f], bh[g][t], bh[g][2+t]);
                    }
        }
    };

    // load both sub-chunks, single sync, two computes
    cpB(cg64*2, 0);
    ldstA(cg64*2, 0);
    cpB(cg64*2 + 1, 1);
    ldstA(cg64*2 + 1, 1);
    cpa_wait0();
    __syncthreads();
    compute(0);
    compute(1);

    // write partial slice
    {
        float* gp = gpart + (size_t)cg64*GB*GJ;
#pragma unroll
        for (int f = 0; f < 2; f++){
            int b = mw + f*16 + (lane >> 2);
#pragma unroll
            for (int j = 0; j < 8; j++){
                int cb = j0 + nw + (j>>1)*16 + (j&1)*8 + (lane & 3)*2;
                *reinterpret_cast<float2*>(&gp[(size_t)b*GJ + cb])
                    = make_float2(acc[f][j][0], acc[f][j][1]);
                *reinterpret_cast<float2*>(&gp[(size_t)(b+8)*GJ + cb])
                    = make_float2(acc[f][j][2], acc[f][j][3]);
            }
        }
    }

    // signal
    __threadfence();
    __syncthreads();
    if (tid == 0) atomicAdd(&g_cnt[slot], 1u);

    // cell: first 32 CTAs
    int cid = blockIdx.y * gridDim.x + blockIdx.x;
    if (cid >= 32) return;
    if (tid == 0){
        volatile unsigned* vc = (volatile unsigned*)g_cnt;
        unsigned tot = gridDim.x * gridDim.y;
        while (vc[slot] < tot) __nanosleep(64);
    }
    __syncthreads();
    __threadfence();

    int e0 = (cid*256 + tid) * 4;     // 4 consecutive elems, same b
    int b = e0 >> 8, k = e0 & 255;
    float4 gi = *reinterpret_cast<const float4*>(&bih[k]);
    float4 tb = *reinterpret_cast<const float4*>(&bhh[k]);
    gi.x += tb.x; gi.y += tb.y; gi.z += tb.z; gi.w += tb.w;
    float4 gf = *reinterpret_cast<const float4*>(&bih[GH + k]);
    tb = *reinterpret_cast<const float4*>(&bhh[GH + k]);
    gf.x += tb.x; gf.y += tb.y; gf.z += tb.z; gf.w += tb.w;
    float4 gg = *reinterpret_cast<const float4*>(&bih[2*GH + k]);
    tb = *reinterpret_cast<const float4*>(&bhh[2*GH + k]);
    gg.x += tb.x; gg.y += tb.y; gg.z += tb.z; gg.w += tb.w;
    float4 go = *reinterpret_cast<const float4*>(&bih[3*GH + k]);
    tb = *reinterpret_cast<const float4*>(&bhh[3*GH + k]);
    go.x += tb.x; go.y += tb.y; go.z += tb.z; go.w += tb.w;
    for (int p = 0; p < nch64; p++){
        const float* gp = gpart + (size_t)p*GB*GJ + (size_t)b*GJ;
        float4 v;
        v = *reinterpret_cast<const float4*>(&gp[k]);        gi.x+=v.x; gi.y+=v.y; gi.z+=v.z; gi.w+=v.w;
        v = *reinterpret_cast<const float4*>(&gp[GH + k]);   gf.x+=v.x; gf.y+=v.y; gf.z+=v.z; gf.w+=v.w;
        v = *reinterpret_cast<const float4*>(&gp[2*GH + k]); gg.x+=v.x; gg.y+=v.y; gg.z+=v.z; gg.w+=v.w;
        v = *reinterpret_cast<const float4*>(&gp[3*GH + k]); go.x+=v.x; go.y+=v.y; go.z+=v.z; go.w+=v.w;
    }
    float4 cold = *reinterpret_cast<const float4*>(&c[e0]);
    float4 cn, hn;
    {
        float si, sf, so;
        si = 1.f/(1.f+expf(-gi.x)); sf = 1.f/(1.f+expf(-gf.x)); so = 1.f/(1.f+expf(-go.x));
        cn.x = sf*cold.x + si*tanhf(gg.x); hn.x = so*tanhf(cn.x);
        si = 1.f/(1.f+expf(-gi.y)); sf = 1.f/(1.f+expf(-gf.y)); so = 1.f/(1.f+expf(-go.y));
        cn.y = sf*cold.y + si*tanhf(gg.y); hn.y = so*tanhf(cn.y);
        si = 1.f/(1.f+expf(-gi.z)); sf = 1.f/(1.f+expf(-gf.z)); so = 1.f/(1.f+expf(-go.z));
        cn.z = sf*cold.z + si*tanhf(gg.z); hn.z = so*tanhf(cn.z);
        si = 1.f/(1.f+expf(-gi.w)); sf = 1.f/(1.f+expf(-gf.w)); so = 1.f/(1.f+expf(-go.w));
        cn.w = sf*cold.w + si*tanhf(gg.w); hn.w = so*tanhf(cn.w);
    }
    *reinterpret_cast<float4*>(&c[e0]) = cn;
    *reinterpret_cast<float4*>(&h[e0]) = hn;
}

__global__ void init_state(){
    int idx = blockIdx.x*blockDim.x + threadIdx.x;
    if (idx < 3*GB*GH){ g_h[idx]=0.f; g_c[idx]=0.f; }
    if (idx < GB*2*GH) g_qstar[idx]=0.f;
    if (idx < 16) g_cnt[idx] = 0u;
}

// ---------------- fused single-pass attention (64-row blocks) ----------------
__global__ void __launch_bounds__(256) attn_fused(const float* __restrict__ q,
                                                  const int* __restrict__ bi)
{
    const int b = blockIdx.x, ch = blockIdx.y;
    const int tid = threadIdx.x, lane = tid & 31, wid = tid >> 5;
    __shared__ float sq[256];
    __shared__ float se[64], spe[64];
    __shared__ float s_m, s_s, s_scale;

    int lo = 0, hi = GN;
    while (lo < hi){ int mid=(lo+hi)>>1; if (bi[mid] <  b) lo=mid+1; else hi=mid; }
    int start = lo; hi = GN;
    while (lo < hi){ int mid=(lo+hi)>>1; if (bi[mid] <= b) lo=mid+1; else hi=mid; }
    int end = lo;
    int len = end - start;
    int per = (len + 7) >> 3;
    int s = start + ch*per;
    int t = min(end, s + per);

    sq[tid] = q[(size_t)b*256 + tid];
    if (tid == 0){ s_m = -INFINITY; s_s = 0.f; s_scale = 1.f; }
    float racc = 0.f;
    __syncthreads();

    for (int n0 = s; n0 < t; n0 += 64){
        int nrows = min(64, t - n0);
        // phase A: 8 warps x 8 rows
#pragma unroll
        for (int i = 0; i < 8; i++){
            int rr = wid*8 + i;
            float sd = 0.f;
            if (rr < nrows){
                const float4* hp = reinterpret_cast<const float4*>(g_hfeat + (size_t)(n0+rr)*256);
                const float4* qp = reinterpret_cast<const float4*>(sq);
                float4 a = hp[lane*2],   w = qp[lane*2];
                sd += a.x*w.x + a.y*w.y + a.z*w.z + a.w*w.w;
                a = hp[lane*2+1]; w = qp[lane*2+1];
                sd += a.x*w.x + a.y*w.y + a.z*w.z + a.w*w.w;
            }
#pragma unroll
            for (int off=16; off>0; off>>=1) sd += __shfl_xor_sync(0xffffffffu, sd, off);
            if (lane == 0) se[rr] = (rr < nrows) ? sd : -INFINITY;
        }
        __syncthreads();
        // phase B: warp 0 handles 64 entries (2 per lane)
        if (wid == 0){
            float e0 = se[lane], e1 = se[lane + 32];
            float mt = fmaxf(e0, e1);
#pragma unroll
            for (int off=16; off>0; off>>=1) mt = fmaxf(mt, __shfl_xor_sync(0xffffffffu, mt, off));
            float m_old = s_m;
            float m_new = fmaxf(m_old, mt);
            float pe0 = expf(e0 - m_new);
            float pe1 = expf(e1 - m_new);
            float ps = pe0 + pe1;
#pragma unroll
            for (int off=16; off>0; off>>=1) ps += __shfl_xor_sync(0xffffffffu, ps, off);
            if (lane == 0){
                float sc = (m_old == -INFINITY) ? 0.f : expf(m_old - m_new);
                s_scale = sc;
                s_s = s_s*sc + ps;
                s_m = m_new;
            }
            spe[lane] = pe0;
            spe[lane + 32] = pe1;
        }
        __syncthreads();
        float sc = s_scale;
        racc *= sc;
        const float* col = g_hfeat + (size_t)n0*256 + tid;
        for (int i = 0; i < nrows; i++)
            racc = fmaf(spe[i], col[(size_t)i*256], racc);
        __syncthreads();
    }
    int ci = b*8 + ch;
    if (tid == 0){ g_am[ci] = s_m; g_as[ci] = s_s; }
    g_ar[(size_t)ci*256 + tid] = racc;
}

__global__ void attn_comb(const float* __restrict__ h2)
{
    int b = blockIdx.x, tid = threadIdx.x;
    __shared__ float sm[8], ss[8];
    if (tid < 8){ sm[tid] = g_am[b*8+tid]; ss[tid] = g_as[b*8+tid]; }
    __syncthreads();
    float mg = -INFINITY;
#pragma unroll
    for (int c=0;c<8;c++) mg = fmaxf(mg, sm[c]);
    if (!isfinite(mg)) mg = 0.f;
    float denom = 0.f, w[8];
#pragma unroll
    for (int c=0;c<8;c++){
        float wc = expf(sm[c] - mg);
        w[c] = wc;
        denom += ss[c]*wc;
    }
    float r = 0.f;
#pragma unroll
    for (int c=0;c<8;c++) r += g_ar[(size_t)(b*8+c)*256 + tid] * w[c];
    r /= (denom + 1e-16f);
    g_qstar[(size_t)b*512 + tid]       = h2[(size_t)b*256 + tid];
    g_qstar[(size_t)b*512 + 256 + tid] = r;
}

__global__ void out_gemm(const float* __restrict__ W, const float* __restrict__ bias,
                         float* __restrict__ out)
{
    int b = blockIdx.x, e = threadIdx.x;
    const float* qs = g_qstar + (size_t)b*(2*GH);
    float acc = bias[e];
    for (int k = 0; k < 2*GH; k++) acc = fmaf(qs[k], W[(size_t)k*GE + e], acc);
    out[(size_t)b*GE + e] = acc;
}

// ---------------- launch ----------------
extern "C" void kernel_launch(void* const* d_in, const int* in_sizes, int n_in,
                              void* d_out, int out_size)
{
    const float* x    = (const float*)d_in[0];
    const int*   bi   = (const int*)  d_in[1];
    const float* W1   = (const float*)d_in[2];
    const float* b1   = (const float*)d_in[3];
    const float* W2   = (const float*)d_in[4];
    const float* b2   = (const float*)d_in[5];
    const float* Wih[3] = {(const float*)d_in[6],  (const float*)d_in[10], (const float*)d_in[14]};
    const float* Whh[3] = {(const float*)d_in[7],  (const float*)d_in[11], (const float*)d_in[15]};
    const float* bih[3] = {(const float*)d_in[8],  (const float*)d_in[12], (const float*)d_in[16]};
    const float* bhh[3] = {(const float*)d_in[9],  (const float*)d_in[13], (const float*)d_in[17]};
    const float* outW = (const float*)d_in[18];
    const float* outb = (const float*)d_in[19];

    float *hfeat, *gpart, *h, *c, *qstar;
    __nv_bfloat16 *xh, *xl, *t1h, *t1l, *wt1h, *wt1l, *wt2h, *wt2l, *wihh, *wihl, *whhh, *whhl;
    cudaGetSymbolAddress((void**)&hfeat, g_hfeat);
    cudaGetSymbolAddress((void**)&gpart, g_gpart);
    cudaGetSymbolAddress((void**)&h,     g_h);
    cudaGetSymbolAddress((void**)&c,     g_c);
    cudaGetSymbolAddress((void**)&qstar, g_qstar);
    cudaGetSymbolAddress((void**)&xh,    g_xh);
    cudaGetSymbolAddress((void**)&xl,    g_xl);
    cudaGetSymbolAddress((void**)&t1h,   g_t1h);
    cudaGetSymbolAddress((void**)&t1l,   g_t1l);
    cudaGetSymbolAddress((void**)&wt1h,  g_wt1h);
    cudaGetSymbolAddress((void**)&wt1l,  g_wt1l);
    cudaGetSymbolAddress((void**)&wt2h,  g_wt2h);
    cudaGetSymbolAddress((void**)&wt2l,  g_wt2l);
    cudaGetSymbolAddress((void**)&wihh,  g_wihh);
    cudaGetSymbolAddress((void**)&wihl,  g_wihl);
    cudaGetSymbolAddress((void**)&whhh,  g_whhh);
    cudaGetSymbolAddress((void**)&whhl,  g_whhl);

    cudaFuncSetAttribute(gemm_a<true,true>,   cudaFuncAttributeMaxDynamicSharedMemorySize, 3*FBUF);
    cudaFuncSetAttribute(gemm_a<false,false>, cudaFuncAttributeMaxDynamicSharedMemorySize, 3*FBUF);
    cudaFuncSetAttribute(lstm_fused, cudaFuncAttributeMaxDynamicSharedMemorySize, 2*LBUF);

    // prep: weights + input split
    wt_prep<<<dim3(8,8), dim3(32,8)>>>(W1, wt1h, wt1l);
    wt_prep<<<dim3(8,8), dim3(32,8)>>>(W2, wt2h, wt2l);
    xsplit<<<(int)(((size_t)GN*GD/8 + 255)/256), 256>>>(x, xh, xl);
    const int ihOff[3] = {0, 1024*512, 1024*512 + 1024*256};
    const int ihSz[3]  = {1024*512, 1024*256, 1024*256};
    {
        WsplitArgs wa;
        for (int l = 0; l < 3; l++){
            wa.src[l] = Wih[l]; wa.hi[l] = wihh + ihOff[l]; wa.lo[l] = wihl + ihOff[l]; wa.sz[l] = ihSz[l];
            wa.src[3+l] = Whh[l]; wa.hi[3+l] = whhh + l*1024*256; wa.lo[3+l] = whhl + l*1024*256; wa.sz[3+l] = 1024*256;
        }
        wsplit6<<<dim3(2048, 6), 256>>>(wa);
    }

    dim3 gg(4, (GN + 127) / 128);
    gemm_a<true,true><<<gg, 256, 3*FBUF>>>(
        xh, xl, wt1h, wt1l, b1, nullptr, t1h, t1l, GN);
    gemm_a<false,false><<<gg, 256, 3*FBUF>>>(
        t1h, t1l, wt2h, wt2l, b2, hfeat, nullptr, nullptr, GN);
    init_state<<<(3*GB*GH + 255)/256, 256>>>();

    for (int step = 0; step < NSTEPS; step++){
        const float* lin = qstar; int Kx = 2*GH;
        for (int l = 0; l < 3; l++){
            int nch64 = (Kx + GH) / 64;   // 12 for layer 0, 8 for layers 1,2
            lstm_fused<<<dim3(8, nch64), 256, 2*LBUF>>>(
                lin, Kx, h + l*GB*GH,
                wihh + ihOff[l], wihl + ihOff[l],
                whhh + l*1024*256, whhl + l*1024*256,
                gpart, step*3 + l, nch64,
                bih[l], bhh[l], h + l*GB*GH, c + l*GB*GH);
            lin = h + l*GB*GH; Kx = GH;
        }
        attn_fused<<<dim3(GB, 8), 256>>>(h + 2*GB*GH, bi);
        attn_comb<<<GB, 256>>>(h + 2*GB*GH);
    }
    out_gemm<<<GB, GE>>>(outW, outb, (float*)d_out);
}